// round 14
// baseline (speedup 1.0000x reference)
#include <cuda_runtime.h>
#include <cuda_bf16.h>
#include <math.h>
#include <stdint.h>

// ---------------- problem constants ----------------
#define BATCH   2
#define SEQ     2048
#define DMODEL  768
#define NHEADS  12
#define HDIM    64
#define DFF     3072
#define MROWS   (BATCH * SEQ)        // 4096
#define LN_EPS  1e-5f
#define QSTRIDE 2304                 // fused qkv row stride

#if defined(__CUDA_ARCH__) && (defined(__CUDA_ARCH_FEAT_SM103_ALL) || defined(__CUDA_ARCH_FEAT_SM100_ALL) || defined(__CUDA_ARCH_FEAT_SM101_ALL))
#define HAS_TCGEN05 1
#else
#define HAS_TCGEN05 0
#endif

// ---------------- inline PTX helpers (sm_103a) ----------------
__device__ __forceinline__ uint32_t smem_u32(const void* p) {
    uint32_t a;
    asm("{ .reg .u64 t; cvta.to.shared.u64 t, %1; cvt.u32.u64 %0, t; }" : "=r"(a) : "l"(p));
    return a;
}

#if HAS_TCGEN05
__device__ __forceinline__ uint32_t elect_one() {
    uint32_t pred;
    asm volatile("{\n\t.reg .pred p;\n\telect.sync _|p, 0xFFFFFFFF;\n\tselp.b32 %0, 1, 0, p;\n\t}" : "=r"(pred));
    return pred;
}
#define MBARRIER_INIT(addr, cnt) \
    asm volatile("mbarrier.init.shared.b64 [%0], %1;" :: "r"((uint32_t)(addr)), "r"((uint32_t)(cnt)) : "memory")
#define MBARRIER_WAIT_PARITY(addr, par) do { \
    uint32_t _m = (uint32_t)(addr), _p = (uint32_t)(par), _d; \
    asm volatile("{\n\t.reg .pred p;\n\tmbarrier.try_wait.parity.acquire.cta.shared::cta.b64 p, [%1], %2;\n\tselp.b32 %0, 1, 0, p;\n\t}" \
        : "=r"(_d) : "r"(_m), "r"(_p) : "memory"); \
    if (!_d) { \
        asm volatile("{\n\t.reg .pred P1;\n\tWL_%=:\n\tmbarrier.try_wait.parity.acquire.cta.shared::cta.b64 P1, [%0], %1, 0x989680;\n\t@P1 bra.uni WD_%=;\n\tbra.uni WL_%=;\n\tWD_%=:\n\t}" \
            :: "r"(_m), "r"(_p) : "memory"); \
    } \
} while (0)
#define TCGEN05_ALLOC(saddr, ncols) \
    asm volatile("tcgen05.alloc.cta_group::1.sync.aligned.shared::cta.b32 [%0], %1;" :: "r"((uint32_t)(saddr)), "r"((uint32_t)(ncols)) : "memory")
#define TCGEN05_DEALLOC(tmem, ncols) \
    asm volatile("tcgen05.dealloc.cta_group::1.sync.aligned.b32 %0, %1;" :: "r"(tmem), "r"((uint32_t)(ncols)))
#define TCGEN05_RELINQUISH() \
    asm volatile("tcgen05.relinquish_alloc_permit.cta_group::1.sync.aligned;")
#define TCGEN05_COMMIT(mbar) \
    asm volatile("tcgen05.commit.cta_group::1.mbarrier::arrive::one.shared::cluster.b64 [%0];" :: "r"((uint32_t)(mbar)) : "memory")
#define TCGEN05_WAIT_LD() asm volatile("tcgen05.wait::ld.sync.aligned;" ::: "memory")
#define TCGEN05_FENCE_AFTER() asm volatile("tcgen05.fence::after_thread_sync;" ::: "memory")
#define FENCE_PROXY_ASYNC_SHARED_CTA() asm volatile("fence.proxy.async.shared::cta;" ::: "memory")
#define TCGEN05_LD_X32(r, tmem_addr) \
    asm volatile( \
        "tcgen05.ld.sync.aligned.32x32b.x32.b32 " \
        "{%0, %1, %2, %3, %4, %5, %6, %7, " \
        " %8, %9, %10, %11, %12, %13, %14, %15, " \
        " %16, %17, %18, %19, %20, %21, %22, %23, " \
        " %24, %25, %26, %27, %28, %29, %30, %31}, [%32];" \
        : "=r"((r)[0]),  "=r"((r)[1]),  "=r"((r)[2]),  "=r"((r)[3]), \
          "=r"((r)[4]),  "=r"((r)[5]),  "=r"((r)[6]),  "=r"((r)[7]), \
          "=r"((r)[8]),  "=r"((r)[9]),  "=r"((r)[10]), "=r"((r)[11]), \
          "=r"((r)[12]), "=r"((r)[13]), "=r"((r)[14]), "=r"((r)[15]), \
          "=r"((r)[16]), "=r"((r)[17]), "=r"((r)[18]), "=r"((r)[19]), \
          "=r"((r)[20]), "=r"((r)[21]), "=r"((r)[22]), "=r"((r)[23]), \
          "=r"((r)[24]), "=r"((r)[25]), "=r"((r)[26]), "=r"((r)[27]), \
          "=r"((r)[28]), "=r"((r)[29]), "=r"((r)[30]), "=r"((r)[31]) \
        : "r"(tmem_addr))

// K-major SW128 descriptor (LBO=1, SBO=64)
static __device__ __forceinline__ uint64_t make_desc_sw128(uint32_t addr) {
    const uint64_t base =
        (uint64_t(2) << 61) | (uint64_t(1) << 46) | (uint64_t(64) << 32) | (uint64_t(1) << 16);
    return base | ((uint64_t)(addr >> 4) & 0x3FFF);
}

__device__ __forceinline__ void mma_f16_ss(uint32_t d_tmem, uint64_t a_desc, uint64_t b_desc,
                                           uint32_t idesc, bool enable_d) {
    uint32_t en = enable_d ? 1u : 0u;
    asm volatile(
        "{\n\t.reg .pred p;\n\t"
        "setp.ne.u32 p, %5, 0;\n\t"
        "tcgen05.mma.cta_group::1.kind::f16 [%0], %1, %2, %3, {%4, %4, %4, %4}, p;\n\t}"
        :: "r"(d_tmem), "l"(a_desc), "l"(b_desc), "r"(idesc), "r"(0u), "r"(en)
        : "memory");
}
#endif // HAS_TCGEN05

__device__ __forceinline__ uint32_t sw128(uint32_t off) { return off ^ ((off >> 3) & 0x70); }

// fast exp2 on the FMA pipe (no MUFU). |x| < ~30, err ~2e-6 relative.
__device__ __forceinline__ float fast_exp2(float x) {
    float t = x + 12582912.0f;
    int   e = __float_as_int(t);
    float r = t - 12582912.0f;
    float f = x - r;
    float p = 1.3333558146e-3f;
    p = fmaf(p, f, 9.6181298421e-3f);
    p = fmaf(p, f, 5.5504108664e-2f);
    p = fmaf(p, f, 2.4022650696e-1f);
    p = fmaf(p, f, 6.9314718056e-1f);
    p = fmaf(p, f, 1.0f);
    return __int_as_float(__float_as_int(p) + (e << 23));
}

// ---------------- scratch (device globals; no allocs allowed) ----------------
__device__ float g_x1 [MROWS * DMODEL];

__device__ __nv_bfloat16 g_qkv[MROWS * QSTRIDE];                 // q,k used; v region unused
__device__ __nv_bfloat16 g_vT [BATCH * NHEADS * HDIM * SEQ];     // v transposed [b,h,d,s]

__device__ __nv_bfloat16 g_ln1h[MROWS * DMODEL], g_ln1l[MROWS * DMODEL];
__device__ __nv_bfloat16 g_atth[MROWS * DMODEL], g_attl[MROWS * DMODEL];
__device__ __nv_bfloat16 g_hh  [MROWS * DMODEL], g_hl  [MROWS * DMODEL];
__device__ __nv_bfloat16 g_f1h [MROWS * DFF],    g_f1l [MROWS * DFF];

__device__ __nv_bfloat16 g_wqkvth[QSTRIDE * DMODEL];   // fused Wq|Wk|Wv transposed (hi)
__device__ __nv_bfloat16 g_wscr  [QSTRIDE * DMODEL];   // lo scratch (unused by 1-term gemm)
__device__ __nv_bfloat16 g_woth[DMODEL * DMODEL], g_wotl[DMODEL * DMODEL];
__device__ __nv_bfloat16 g_w1th[DFF * DMODEL],    g_w1tl[DFF * DMODEL];
__device__ __nv_bfloat16 g_w2th[DMODEL * DFF],    g_w2tl[DMODEL * DFF];

// ---------------- vectorized weight transpose + fp32->bf16 hi/lo split --------
__device__ __forceinline__ void transpose_tile_body(const float* __restrict__ W,
                                                    __nv_bfloat16* __restrict__ Th,
                                                    __nv_bfloat16* __restrict__ Tl,
                                                    int K, int N, int n0, int k0) {
    __shared__ float sm[32][133];
    int t = threadIdx.x;
    int tx = t & 31, ty = t >> 5;              // 32 x 8
    #pragma unroll
    for (int i = 0; i < 4; i++) {
        int r = ty + 8 * i;
        float4 v = *(const float4*)(W + (size_t)(k0 + r) * N + n0 + tx * 4);
        sm[r][tx * 4 + 0] = v.x;
        sm[r][tx * 4 + 1] = v.y;
        sm[r][tx * 4 + 2] = v.z;
        sm[r][tx * 4 + 3] = v.w;
    }
    __syncthreads();
    int kb = (t & 3) * 8;                      // k chunk base (0,8,16,24)
    int nrow = t >> 2;                         // 0..63
    #pragma unroll
    for (int pass = 0; pass < 2; pass++) {
        int n = nrow + 64 * pass;
        __nv_bfloat16 hbuf[8], lbuf[8];
        #pragma unroll
        for (int j = 0; j < 8; j++) {
            float v = sm[kb + j][n];
            __nv_bfloat16 h = __float2bfloat16(v);
            hbuf[j] = h;
            lbuf[j] = __float2bfloat16(v - __bfloat162float(h));
        }
        size_t o = (size_t)(n0 + n) * K + k0 + kb;
        *(uint4*)(Th + o) = *(uint4*)hbuf;
        *(uint4*)(Tl + o) = *(uint4*)lbuf;
    }
}

__global__ __launch_bounds__(256)
void transpose_split_kernel(const float* __restrict__ W,
                            __nv_bfloat16* __restrict__ Th, __nv_bfloat16* __restrict__ Tl,
                            int K, int N) {
    transpose_tile_body(W, Th, Tl, K, N, blockIdx.x * 128, blockIdx.y * 32);
}

__global__ __launch_bounds__(256)
void transpose4_split_kernel(const float* __restrict__ W0, const float* __restrict__ W1,
                             const float* __restrict__ W2, const float* __restrict__ W3,
                             __nv_bfloat16* __restrict__ T0h, __nv_bfloat16* __restrict__ T0l,
                             __nv_bfloat16* __restrict__ T1h, __nv_bfloat16* __restrict__ T1l,
                             __nv_bfloat16* __restrict__ T2h, __nv_bfloat16* __restrict__ T2l,
                             __nv_bfloat16* __restrict__ T3h, __nv_bfloat16* __restrict__ T3l) {
    int z = blockIdx.z;
    const float* W = (z == 0) ? W0 : (z == 1) ? W1 : (z == 2) ? W2 : W3;
    __nv_bfloat16* Th = (z == 0) ? T0h : (z == 1) ? T1h : (z == 2) ? T2h : T3h;
    __nv_bfloat16* Tl = (z == 0) ? T0l : (z == 1) ? T1l : (z == 2) ? T2l : T3l;
    transpose_tile_body(W, Th, Tl, DMODEL, DMODEL, blockIdx.x * 128, blockIdx.y * 32);
}

// ---------------- block reduction ----------------
__device__ __forceinline__ float block_sum(float v) {
    __shared__ float sm[32];
    __syncthreads();
    int lane = threadIdx.x & 31;
    int wid  = threadIdx.x >> 5;
    #pragma unroll
    for (int o = 16; o > 0; o >>= 1) v += __shfl_down_sync(0xffffffffu, v, o);
    if (lane == 0) sm[wid] = v;
    __syncthreads();
    if (wid == 0) {
        int nw = (blockDim.x + 31) >> 5;
        v = (lane < nw) ? sm[lane] : 0.0f;
        #pragma unroll
        for (int o = 16; o > 0; o >>= 1) v += __shfl_down_sync(0xffffffffu, v, o);
        if (lane == 0) sm[0] = v;
    }
    __syncthreads();
    return sm[0];
}

// ---------------- LayerNorm -> bf16 hi/lo planes ----------------
__global__ __launch_bounds__(256)
void layernorm_split_kernel(const float* __restrict__ x,
                            const float* __restrict__ g,
                            const float* __restrict__ b,
                            __nv_bfloat16* __restrict__ oh,
                            __nv_bfloat16* __restrict__ ol) {
    int row = blockIdx.x;
    const float* xr = x + (size_t)row * DMODEL;
    int t = threadIdx.x;

    float v0 = xr[t], v1 = xr[t + 256], v2 = xr[t + 512];
    float mu = block_sum(v0 + v1 + v2) * (1.0f / DMODEL);
    float d0 = v0 - mu, d1 = v1 - mu, d2 = v2 - mu;
    float var = block_sum(d0 * d0 + d1 * d1 + d2 * d2) * (1.0f / DMODEL);
    float rs = rsqrtf(var + LN_EPS);

    size_t base = (size_t)row * DMODEL;
    #pragma unroll
    for (int i = 0; i < 3; i++) {
        int c = t + 256 * i;
        float d = (i == 0) ? d0 : (i == 1 ? d1 : d2);
        float v = d * rs * g[c] + b[c];
        __nv_bfloat16 h = __float2bfloat16(v);
        oh[base + c] = h;
        ol[base + c] = __float2bfloat16(v - __bfloat162float(h));
    }
}

// ---------------- fused QKV: 1-term bf16 tcgen05 GEMM, pipelined ----------------
#define G1_CTRL  33792
#define GEMM1_SMEM_BYTES (1024 + 33792 + 64)

__global__ __launch_bounds__(256)
void tc_gemm1_kernel(const __nv_bfloat16* __restrict__ Ah, const __nv_bfloat16* __restrict__ Bh,
                     const float* __restrict__ bq, const float* __restrict__ bk,
                     const float* __restrict__ bv, __nv_bfloat16* __restrict__ Cqk,
                     __nv_bfloat16* __restrict__ CvT, int M, int N, int K) {
#if HAS_TCGEN05
    extern __shared__ char dsm[];
    uint32_t sbase = smem_u32(dsm);
    uint32_t tile  = (sbase + 1023u) & ~1023u;
    char* tp = dsm + (tile - sbase);
    const int A_HI = 0, B_HI = 16384;
    const uint32_t CTRL = tile + G1_CTRL;

    int tid = threadIdx.x, wid = tid >> 5, lid = tid & 31;
    int brow = blockIdx.y * 128, bcol = blockIdx.x * 128;
    const float* bsel = (bcol < DMODEL) ? bq : (bcol < 2 * DMODEL ? bk : bv);
    int boff = (bcol < DMODEL) ? 0 : (bcol < 2 * DMODEL ? DMODEL : 2 * DMODEL);

    if (wid == 0) { TCGEN05_ALLOC(CTRL, 128); TCGEN05_RELINQUISH(); }
    if (tid == 0) MBARRIER_INIT(CTRL + 8, 1);
    __syncthreads();
    uint32_t tmem;
    asm volatile("ld.shared.b32 %0, [%1];" : "=r"(tmem) : "r"(CTRL));

    const uint32_t IDESC = (1u << 4) | (1u << 7) | (1u << 10) | (16u << 17) | (8u << 24);
    const uint64_t dah = make_desc_sw128(tile + A_HI);
    const uint64_t dbh = make_desc_sw128(tile + B_HI);

    uint32_t swo[4]; int eoff[4];
    #pragma unroll
    for (int j = 0; j < 4; j++) {
        int cid = tid + 256 * j;
        int r = cid >> 3, cb = (cid & 7) << 4;
        swo[j] = sw128((uint32_t)(r * 128 + cb));
        eoff[j] = r * K + (cb >> 1);
    }
    const __nv_bfloat16* Abase = Ah + (size_t)brow * K;
    const __nv_bfloat16* Bbase = Bh + (size_t)bcol * K;

    int T = K >> 6;
    uint4 ra[4], rb[4];
    #pragma unroll
    for (int j = 0; j < 4; j++) {
        ra[j] = *(const uint4*)(Abase + eoff[j]);
        rb[j] = *(const uint4*)(Bbase + eoff[j]);
    }
    for (int it = 0; it < T; ++it) {
        if (it > 0) MBARRIER_WAIT_PARITY(CTRL + 8, (it - 1) & 1);
        __syncthreads();
        #pragma unroll
        for (int j = 0; j < 4; j++) {
            *(uint4*)(tp + A_HI + swo[j]) = ra[j];
            *(uint4*)(tp + B_HI + swo[j]) = rb[j];
        }
        __syncthreads();
        if (wid == 0) {
            FENCE_PROXY_ASYNC_SHARED_CTA();
            if (elect_one()) {
                #pragma unroll
                for (int ch = 0; ch < 4; ch++)
                    mma_f16_ss(tmem, dah + ch * 2, dbh + ch * 2, IDESC, !(it == 0 && ch == 0));
                TCGEN05_COMMIT(CTRL + 8);
            }
        }
        if (it + 1 < T) {
            int k0 = (it + 1) << 6;
            #pragma unroll
            for (int j = 0; j < 4; j++) {
                ra[j] = *(const uint4*)(Abase + eoff[j] + k0);
                rb[j] = *(const uint4*)(Bbase + eoff[j] + k0);
            }
        }
    }
    MBARRIER_WAIT_PARITY(CTRL + 8, (T - 1) & 1);
    TCGEN05_FENCE_AFTER();
    __syncthreads();

    int sub = wid & 3, grp = wid >> 2;
    if (bcol < 2 * DMODEL) {
        float* tb = (float*)(tp + wid * 4224);
        #pragma unroll
        for (int c0 = 0; c0 < 64; c0 += 32) {
            int cbase = grp * 64 + c0;
            uint32_t d[32];
            TCGEN05_LD_X32(d, tmem + cbase);
            TCGEN05_WAIT_LD();
            #pragma unroll
            for (int j = 0; j < 32; j++) tb[lid * 33 + j] = __uint_as_float(d[j]);
            __syncwarp();
            #pragma unroll
            for (int j = 0; j < 32; j++) {
                int grow = brow + sub * 32 + j;
                int gcol = bcol + cbase + lid;
                Cqk[(size_t)grow * N + gcol] =
                    __float2bfloat16(tb[j * 33 + lid] + bsel[gcol - boff]);
            }
            __syncwarp();
        }
    } else {
        int grow = brow + sub * 32 + lid;
        int bb = grow >> 11, s = grow & (SEQ - 1);
        #pragma unroll
        for (int c0 = 0; c0 < 64; c0 += 32) {
            int cbase = grp * 64 + c0;
            uint32_t d[32];
            TCGEN05_LD_X32(d, tmem + cbase);
            TCGEN05_WAIT_LD();
            #pragma unroll
            for (int j = 0; j < 32; j++) {
                int gcol = bcol + cbase + j;
                int vcol = gcol - 2 * DMODEL;
                int hh2 = vcol >> 6, dl = vcol & 63;
                CvT[((size_t)(bb * NHEADS + hh2) * HDIM + dl) * SEQ + s] =
                    __float2bfloat16(__uint_as_float(d[j]) + bsel[gcol - boff]);
            }
        }
    }
    __syncthreads();
    if (wid == 0) TCGEN05_DEALLOC(tmem, 128);
#else
    int tid = threadIdx.x;
    int brow = blockIdx.y * 128, bcol = blockIdx.x * 128;
    for (int e = tid; e < 128 * 128; e += 256) {
        int r = e >> 7, c = e & 127;
        int grow = brow + r, gcol = bcol + c;
        float acc = 0.0f;
        for (int kk = 0; kk < K; kk++)
            acc = fmaf(__bfloat162float(Ah[(size_t)grow * K + kk]),
                       __bfloat162float(Bh[(size_t)gcol * K + kk]), acc);
        const float* bsel = (gcol < DMODEL) ? bq : (gcol < 2 * DMODEL ? bk : bv);
        int boff = (gcol < DMODEL) ? 0 : (gcol < 2 * DMODEL ? DMODEL : 2 * DMODEL);
        float v = acc + bsel[gcol - boff];
        if (gcol < 2 * DMODEL) {
            Cqk[(size_t)grow * N + gcol] = __float2bfloat16(v);
        } else {
            int vcol = gcol - 2 * DMODEL;
            int bb = grow >> 11, s = grow & (SEQ - 1);
            CvT[((size_t)(bb * NHEADS + (vcol >> 6)) * HDIM + (vcol & 63)) * SEQ + s] =
                __float2bfloat16(v);
        }
    }
#endif
}

// ---------------- 3-term split tcgen05 GEMM, 128x128, split-commit overlap ----
// Direct gmem->smem staging (no reg prefetch) -> ~50 regs -> 3 CTAs/SM.
// Per iter: stage HI -> commit#A (hi*hi); stage LO (overlaps A) -> commit#B.
#define GEMM_SMEM_BYTES (1024 + 65536 + 64)

template <bool RELU, bool ADDRES, int OUT>
__global__ __launch_bounds__(256, 3)
void tc_gemm_kernel(const __nv_bfloat16* __restrict__ Ah, const __nv_bfloat16* __restrict__ Al,
                    const __nv_bfloat16* __restrict__ Bh, const __nv_bfloat16* __restrict__ Bl,
                    const float* __restrict__ bias, const float* __restrict__ res,
                    float* __restrict__ Cf,
                    __nv_bfloat16* __restrict__ Ch, __nv_bfloat16* __restrict__ Cl,
                    int M, int N, int K) {
#if HAS_TCGEN05
    extern __shared__ char dsm[];
    uint32_t sbase = smem_u32(dsm);
    uint32_t tile  = (sbase + 1023u) & ~1023u;
    char* tp = dsm + (tile - sbase);

    const int A_HI = 0, A_LO = 16384, B_HI = 32768, B_LO = 49152;
    const uint32_t CTRL = tile + 65536;

    int tid = threadIdx.x, wid = tid >> 5, lid = tid & 31;
    int brow = blockIdx.y * 128, bcol = blockIdx.x * 128;

    if (wid == 0) { TCGEN05_ALLOC(CTRL, 128); TCGEN05_RELINQUISH(); }
    if (tid == 0) MBARRIER_INIT(CTRL + 8, 2);   // two commits per K-iter
    __syncthreads();
    uint32_t tmem;
    asm volatile("ld.shared.b32 %0, [%1];" : "=r"(tmem) : "r"(CTRL));

    const uint32_t IDESC = (1u << 4) | (1u << 7) | (1u << 10) | (16u << 17) | (8u << 24);
    const uint64_t dah = make_desc_sw128(tile + A_HI);
    const uint64_t dal = make_desc_sw128(tile + A_LO);
    const uint64_t dbh = make_desc_sw128(tile + B_HI);
    const uint64_t dbl = make_desc_sw128(tile + B_LO);

    uint32_t swo[4]; int eoff[4];
    #pragma unroll
    for (int j = 0; j < 4; j++) {
        int cid = tid + 256 * j;
        int r = cid >> 3, cb = (cid & 7) << 4;
        swo[j] = sw128((uint32_t)(r * 128 + cb));
        eoff[j] = r * K + (cb >> 1);
    }
    const __nv_bfloat16* Ahb = Ah + (size_t)brow * K;
    const __nv_bfloat16* Alb = Al + (size_t)brow * K;
    const __nv_bfloat16* Bhb = Bh + (size_t)bcol * K;
    const __nv_bfloat16* Blb = Bl + (size_t)bcol * K;

    int T = K >> 6;
    for (int it = 0; it < T; ++it) {
        int k0 = it << 6;
        if (it > 0) MBARRIER_WAIT_PARITY(CTRL + 8, (it - 1) & 1);
        __syncthreads();
        // phase A: stage hi planes (direct gmem->smem), launch hi*hi MMAs
        #pragma unroll
        for (int j = 0; j < 4; j++) {
            *(uint4*)(tp + A_HI + swo[j]) = *(const uint4*)(Ahb + eoff[j] + k0);
            *(uint4*)(tp + B_HI + swo[j]) = *(const uint4*)(Bhb + eoff[j] + k0);
        }
        __syncthreads();
        if (wid == 0) {
            FENCE_PROXY_ASYNC_SHARED_CTA();
            if (elect_one()) {
                #pragma unroll
                for (int ch = 0; ch < 4; ch++)
                    mma_f16_ss(tmem, dah + ch * 2, dbh + ch * 2, IDESC, !(it == 0 && ch == 0));
                TCGEN05_COMMIT(CTRL + 8);
            }
        }
        // phase B: stage lo planes (overlaps hi*hi MMAs)
        #pragma unroll
        for (int j = 0; j < 4; j++) {
            *(uint4*)(tp + A_LO + swo[j]) = *(const uint4*)(Alb + eoff[j] + k0);
            *(uint4*)(tp + B_LO + swo[j]) = *(const uint4*)(Blb + eoff[j] + k0);
        }
        __syncthreads();
        if (wid == 0) {
            FENCE_PROXY_ASYNC_SHARED_CTA();
            if (elect_one()) {
                #pragma unroll
                for (int ch = 0; ch < 4; ch++) {
                    uint64_t off = (uint64_t)(ch * 2);
                    mma_f16_ss(tmem, dah + off, dbl + off, IDESC, true);
                    mma_f16_ss(tmem, dal + off, dbh + off, IDESC, true);
                }
                TCGEN05_COMMIT(CTRL + 8);
            }
        }
    }
    MBARRIER_WAIT_PARITY(CTRL + 8, (T - 1) & 1);
    TCGEN05_FENCE_AFTER();
    __syncthreads();

    int sub = wid & 3, grp = wid >> 2;
    float* tb = (float*)(tp + wid * 4224);
    #pragma unroll
    for (int c0 = 0; c0 < 64; c0 += 32) {
        int cbase = grp * 64 + c0;
        uint32_t d[32];
        TCGEN05_LD_X32(d, tmem + cbase);
        TCGEN05_WAIT_LD();
        #pragma unroll
        for (int j = 0; j < 32; j++) tb[lid * 33 + j] = __uint_as_float(d[j]);
        __syncwarp();
        #pragma unroll
        for (int j = 0; j < 32; j++) {
            int grow = brow + sub * 32 + j;
            int gcol = bcol + cbase + lid;
            float v = tb[j * 33 + lid] + bias[gcol];
            if (RELU)   v = fmaxf(v, 0.0f);
            if (ADDRES) v += res[(size_t)grow * N + gcol];
            if (OUT == 1) {
                __nv_bfloat16 h = __float2bfloat16(v);
                Ch[(size_t)grow * N + gcol] = h;
                Cl[(size_t)grow * N + gcol] = __float2bfloat16(v - __bfloat162float(h));
            } else {
                Cf[(size_t)grow * N + gcol] = v;
            }
        }
        __syncwarp();
    }
    __syncthreads();
    if (wid == 0) TCGEN05_DEALLOC(tmem, 128);
#else
    int tid = threadIdx.x;
    int brow = blockIdx.y * 128, bcol = blockIdx.x * 128;
    for (int e = tid; e < 128 * 128; e += 256) {
        int r = e >> 7, c = e & 127;
        int grow = brow + r, gcol = bcol + c;
        float acc = 0.0f;
        for (int kk = 0; kk < K; kk++) {
            float a = __bfloat162float(Ah[(size_t)grow * K + kk]) +
                      __bfloat162float(Al[(size_t)grow * K + kk]);
            float b = __bfloat162float(Bh[(size_t)gcol * K + kk]) +
                      __bfloat162float(Bl[(size_t)gcol * K + kk]);
            acc = fmaf(a, b, acc);
        }
        float v = acc + bias[gcol];
        if (RELU)   v = fmaxf(v, 0.0f);
        if (ADDRES) v += res[(size_t)grow * N + gcol];
        if (OUT == 1) {
            __nv_bfloat16 h = __float2bfloat16(v);
            Ch[(size_t)grow * N + gcol] = h;
            Cl[(size_t)grow * N + gcol] = __float2bfloat16(v - __bfloat162float(h));
        } else {
            Cf[(size_t)grow * N + gcol] = v;
        }
    }
#endif
}

// ---------------- 3-term split GEMM, 128x256 tile, split-commit overlap -------
#define G256_A_HI 0
#define G256_A_LO 16384
#define G256_B_HI 32768
#define G256_B_LO 65536
#define G256_CTRL 98304
#define GEMM256_SMEM_BYTES (1024 + 98304 + 64)

__global__ __launch_bounds__(256)
void tc_gemm256_kernel(const __nv_bfloat16* __restrict__ Ah, const __nv_bfloat16* __restrict__ Al,
                       const __nv_bfloat16* __restrict__ Bh, const __nv_bfloat16* __restrict__ Bl,
                       const float* __restrict__ bias,
                       __nv_bfloat16* __restrict__ Ch, __nv_bfloat16* __restrict__ Cl,
                       int M, int N, int K) {
#if HAS_TCGEN05
    extern __shared__ char dsm[];
    uint32_t sbase = smem_u32(dsm);
    uint32_t tile  = (sbase + 1023u) & ~1023u;
    char* tp = dsm + (tile - sbase);
    const uint32_t CTRL = tile + G256_CTRL;

    int tid = threadIdx.x, wid = tid >> 5, lid = tid & 31;
    int brow = blockIdx.y * 128, bcol = blockIdx.x * 256;

    if (wid == 0) { TCGEN05_ALLOC(CTRL, 256); TCGEN05_RELINQUISH(); }
    if (tid == 0) MBARRIER_INIT(CTRL + 8, 2);   // two commits per K-iter
    __syncthreads();
    uint32_t tmem;
    asm volatile("ld.shared.b32 %0, [%1];" : "=r"(tmem) : "r"(CTRL));

    const uint32_t IDESC = (1u << 4) | (1u << 7) | (1u << 10) | (32u << 17) | (8u << 24);
    const uint64_t dah = make_desc_sw128(tile + G256_A_HI);
    const uint64_t dal = make_desc_sw128(tile + G256_A_LO);
    const uint64_t dbh = make_desc_sw128(tile + G256_B_HI);
    const uint64_t dbl = make_desc_sw128(tile + G256_B_LO);

    uint32_t aswo[4]; int aeoff[4];
    #pragma unroll
    for (int j = 0; j < 4; j++) {
        int cid = tid + 256 * j;
        int r = cid >> 3, cb = (cid & 7) << 4;
        aswo[j] = sw128((uint32_t)(r * 128 + cb));
        aeoff[j] = r * K + (cb >> 1);
    }
    uint32_t bswo[8]; int beoff[8];
    #pragma unroll
    for (int j = 0; j < 8; j++) {
        int cid = tid + 256 * j;
        int r = cid >> 3, cb = (cid & 7) << 4;
        bswo[j] = sw128((uint32_t)(r * 128 + cb));
        beoff[j] = r * K + (cb >> 1);
    }
    const __nv_bfloat16* Ahb = Ah + (size_t)brow * K;
    const __nv_bfloat16* Alb = Al + (size_t)brow * K;
    const __nv_bfloat16* Bhb = Bh + (size_t)bcol * K;
    const __nv_bfloat16* Blb = Bl + (size_t)bcol * K;

    int T = K >> 6;
    for (int it = 0; it < T; ++it) {
        int k0 = it << 6;
        if (it > 0) MBARRIER_WAIT_PARITY(CTRL + 8, (it - 1) & 1);
        __syncthreads();
        // phase A: stage hi planes
        #pragma unroll
        for (int j = 0; j < 4; j++)
            *(uint4*)(tp + G256_A_HI + aswo[j]) = *(const uint4*)(Ahb + aeoff[j] + k0);
        #pragma unroll
        for (int j = 0; j < 8; j++)
            *(uint4*)(tp + G256_B_HI + bswo[j]) = *(const uint4*)(Bhb + beoff[j] + k0);
        __syncthreads();
        if (wid == 0) {
            FENCE_PROXY_ASYNC_SHARED_CTA();
            if (elect_one()) {
                #pragma unroll
                for (int ch = 0; ch < 4; ch++)
                    mma_f16_ss(tmem, dah + ch * 2, dbh + ch * 2, IDESC, !(it == 0 && ch == 0));
                TCGEN05_COMMIT(CTRL + 8);
            }
        }
        // phase B: stage lo planes (overlaps hi*hi MMAs)
        #pragma unroll
        for (int j = 0; j < 4; j++)
            *(uint4*)(tp + G256_A_LO + aswo[j]) = *(const uint4*)(Alb + aeoff[j] + k0);
        #pragma unroll
        for (int j = 0; j < 8; j++)
            *(uint4*)(tp + G256_B_LO + bswo[j]) = *(const uint4*)(Blb + beoff[j] + k0);
        __syncthreads();
        if (wid == 0) {
            FENCE_PROXY_ASYNC_SHARED_CTA();
            if (elect_one()) {
                #pragma unroll
                for (int ch = 0; ch < 4; ch++) {
                    uint64_t off = (uint64_t)(ch * 2);
                    mma_f16_ss(tmem, dah + off, dbl + off, IDESC, true);
                    mma_f16_ss(tmem, dal + off, dbh + off, IDESC, true);
                }
                TCGEN05_COMMIT(CTRL + 8);
            }
        }
    }
    MBARRIER_WAIT_PARITY(CTRL + 8, (T - 1) & 1);
    TCGEN05_FENCE_AFTER();
    __syncthreads();

    int sub = wid & 3, grp = wid >> 2;
    float* tb = (float*)(tp + wid * 4224);
    #pragma unroll
    for (int c0 = 0; c0 < 128; c0 += 32) {
        int cbase = grp * 128 + c0;
        uint32_t d[32];
        TCGEN05_LD_X32(d, tmem + cbase);
        TCGEN05_WAIT_LD();
        #pragma unroll
        for (int j = 0; j < 32; j++) tb[lid * 33 + j] = __uint_as_float(d[j]);
        __syncwarp();
        #pragma unroll
        for (int j = 0; j < 32; j++) {
            int grow = brow + sub * 32 + j;
            int gcol = bcol + cbase + lid;
            float v = fmaxf(tb[j * 33 + lid] + bias[gcol], 0.0f);   // ReLU
            __nv_bfloat16 h = __float2bfloat16(v);
            Ch[(size_t)grow * N + gcol] = h;
            Cl[(size_t)grow * N + gcol] = __float2bfloat16(v - __bfloat162float(h));
        }
        __syncwarp();
    }
    __syncthreads();
    if (wid == 0) TCGEN05_DEALLOC(tmem, 256);
#else
    int tid = threadIdx.x;
    int brow = blockIdx.y * 128, bcol = blockIdx.x * 256;
    for (int e = tid; e < 128 * 256; e += 256) {
        int r = e >> 8, c = e & 255;
        int grow = brow + r, gcol = bcol + c;
        float acc = 0.0f;
        for (int kk = 0; kk < K; kk++) {
            float a = __bfloat162float(Ah[(size_t)grow * K + kk]) +
                      __bfloat162float(Al[(size_t)grow * K + kk]);
            float b = __bfloat162float(Bh[(size_t)gcol * K + kk]) +
                      __bfloat162float(Bl[(size_t)gcol * K + kk]);
            acc = fmaf(a, b, acc);
        }
        float v = fmaxf(acc + bias[gcol], 0.0f);
        __nv_bfloat16 h = __float2bfloat16(v);
        Ch[(size_t)grow * N + gcol] = h;
        Cl[(size_t)grow * N + gcol] = __float2bfloat16(v - __bfloat162float(h));
    }
#endif
}

// ---------------- tensor-core causal attention (batched PV+QK commit) --------
#define AQ_OFF   0
#define AK_OFF   16384
#define AV_OFF   32768
#define AP_OFF   49152
#define ALSM_OFF 81920
#define ACTRL    82944
#define ATTN_SMEM_BYTES (1024 + 82944 + 64)

__global__ __launch_bounds__(256)
void tc_attn_kernel(const __nv_bfloat16* __restrict__ qkv,
                    const __nv_bfloat16* __restrict__ vT,
                    __nv_bfloat16* __restrict__ oh,
                    __nv_bfloat16* __restrict__ ol) {
#if HAS_TCGEN05
    extern __shared__ char dsm[];
    uint32_t sbase = smem_u32(dsm);
    uint32_t tile  = (sbase + 1023u) & ~1023u;
    char* tp = dsm + (tile - sbase);
    float* lsm = (float*)(tp + ALSM_OFF);

    int qt = gridDim.x - 1 - blockIdx.x;   // longest tiles first
    int h = blockIdx.y, b = blockIdx.z;
    int tid = threadIdx.x, wid = tid >> 5, lid = tid & 31;
    int sp = wid & 3, half = wid >> 2;
    int r_local = sp * 32 + lid;
    int q_global = qt * 128 + r_local;

    const float SCALE_L2E = 0.125f * 1.4426950408889634f;
    size_t rowbase = (size_t)b * SEQ * QSTRIDE + (size_t)h * HDIM;
    const __nv_bfloat16* vTh = vT + ((size_t)(b * NHEADS + h) * HDIM) * SEQ;

    if (wid == 0) { TCGEN05_ALLOC(tile + ACTRL, 256); TCGEN05_RELINQUISH(); }
    if (tid == 0) MBARRIER_INIT(tile + ACTRL + 8, 1);
    __syncthreads();
    uint32_t tmem;
    asm volatile("ld.shared.b32 %0, [%1];" : "=r"(tmem) : "r"(tile + ACTRL));
    const uint32_t S_T = tmem;
    const uint32_t O_T = tmem + 128;
    const uint32_t MBAR = tile + ACTRL + 8;

    const uint32_t IDESC_QK = (1u << 4) | (1u << 7) | (1u << 10) | (16u << 17) | (8u << 24);
    const uint32_t IDESC_PV = (1u << 4) | (1u << 7) | (1u << 10) | (8u  << 17) | (8u << 24);
    const uint64_t dQ = make_desc_sw128(tile + AQ_OFF);
    const uint64_t dK = make_desc_sw128(tile + AK_OFF);
    const uint64_t dP = make_desc_sw128(tile + AP_OFF);
    const uint64_t dV = make_desc_sw128(tile + AV_OFF);

    uint32_t swo[4]; int rr[4], ce[4];
    uint32_t vsw[4]; size_t vgo[4];
    #pragma unroll
    for (int j = 0; j < 4; j++) {
        int cid = tid + 256 * j;
        rr[j] = cid >> 3;
        int cb = (cid & 7) << 4;
        swo[j] = sw128((uint32_t)(rr[j] * 128 + cb));
        ce[j] = cb >> 1;
        int d = cid >> 4;
        int s16 = cid & 15;
        vsw[j] = sw128((uint32_t)(((d >> 3) + ((s16 >> 3) << 3)) * 1024 +
                                  (d & 7) * 128 + (s16 & 7) * 16));
        vgo[j] = (size_t)d * SEQ + s16 * 8;
    }

    // load Q tile + stage K(0)
    {
        uint4 rk0[4];
        #pragma unroll
        for (int j = 0; j < 4; j++)
            rk0[j] = *(const uint4*)(qkv + DMODEL + rowbase +
                                     (size_t)(rr[j]) * QSTRIDE + ce[j]);
        #pragma unroll
        for (int j = 0; j < 4; j++) {
            *(uint4*)(tp + AQ_OFF + swo[j]) =
                *(const uint4*)(qkv + rowbase + (size_t)(qt * 128 + rr[j]) * QSTRIDE + ce[j]);
            *(uint4*)(tp + AK_OFF + swo[j]) = rk0[j];
        }
        __syncthreads();
        if (wid == 0) {
            FENCE_PROXY_ASYNC_SHARED_CTA();
            if (elect_one()) {
                #pragma unroll
                for (int ch = 0; ch < 4; ch++)
                    mma_f16_ss(S_T, dQ + ch * 2, dK + ch * 2, IDESC_QK, ch > 0);
                TCGEN05_COMMIT(MBAR);
            }
        }
    }

    float lsum = 0.0f;
    uint4 rv[4];
    #pragma unroll
    for (int j = 0; j < 4; j++) rv[j] = *(const uint4*)(vTh + vgo[j]);

    for (int kt = 0; kt <= qt; kt++) {
        uint4 rk[4];
        if (kt < qt) {
            #pragma unroll
            for (int j = 0; j < 4; j++)
                rk[j] = *(const uint4*)(qkv + DMODEL + rowbase +
                                        (size_t)((kt + 1) * 128 + rr[j]) * QSTRIDE + ce[j]);
        }
        MBARRIER_WAIT_PARITY(MBAR, kt & 1);
        TCGEN05_FENCE_AFTER();

        if (kt < qt) {
            // full tile: no causal masking needed
            #pragma unroll
            for (int c = 0; c < 64; c += 32) {
                uint32_t s[32];
                TCGEN05_LD_X32(s, S_T + half * 64 + c);
                TCGEN05_WAIT_LD();
                uint32_t pk[16];
                #pragma unroll
                for (int j2 = 0; j2 < 16; j2++) {
                    float p0 = fast_exp2(__uint_as_float(s[2 * j2])     * SCALE_L2E);
                    float p1 = fast_exp2(__uint_as_float(s[2 * j2 + 1]) * SCALE_L2E);
                    lsum += p0 + p1;
                    __nv_bfloat162 pr = __floats2bfloat162_rn(p0, p1);
                    pk[j2] = *(uint32_t*)&pr;
                }
                uint32_t pb = (uint32_t)(((r_local >> 3) + half * 16) * 1024 +
                                         (r_local & 7) * 128 + c * 2);
                uint4* pk4 = (uint4*)pk;
                #pragma unroll
                for (int i = 0; i < 4; i++)
                    *(uint4*)(tp + AP_OFF + sw128(pb + i * 16)) = pk4[i];
            }
        } else {
            // diagonal tile: apply causal mask
            #pragma unroll
            for (int c = 0; c < 64; c += 32) {
                uint32_t s[32];
                TCGEN05_LD_X32(s, S_T + half * 64 + c);
                TCGEN05_WAIT_LD();
                uint32_t pk[16];
                #pragma unroll
                for (int j2 = 0; j2 < 16; j2++) {
                    int col = kt * 128 + half * 64 + c + 2 * j2;
                    float p0 = fast_exp2(__uint_as_float(s[2 * j2])     * SCALE_L2E);
                    float p1 = fast_exp2(__uint_as_float(s[2 * j2 + 1]) * SCALE_L2E);
                    p0 = (col     <= q_global) ? p0 : 0.0f;
                    p1 = (col + 1 <= q_global) ? p1 : 0.0f;
                    lsum += p0 + p1;
                    __nv_bfloat162 pr = __floats2bfloat162_rn(p0, p1);
                    pk[j2] = *(uint32_t*)&pr;
                }
                uint32_t pb = (uint32_t)(((r_local >> 3) + half * 16) * 1024 +
                                         (r_local & 7) * 128 + c * 2);
                uint4* pk4 = (uint4*)pk;
                #pragma unroll
                for (int i = 0; i < 4; i++)
                    *(uint4*)(tp + AP_OFF + sw128(pb + i * 16)) = pk4[i];
            }
        }
        #pragma unroll
        for (int j = 0; j < 4; j++) *(uint4*)(tp + AV_OFF + vsw[j]) = rv[j];
        if (kt < qt) {
            #pragma unroll
            for (int j = 0; j < 4; j++) *(uint4*)(tp + AK_OFF + swo[j]) = rk[j];
        }
        __syncthreads();

        if (wid == 0) {
            FENCE_PROXY_ASYNC_SHARED_CTA();
            if (elect_one()) {
                #pragma unroll
                for (int ch = 0; ch < 8; ch++) {
                    uint64_t offP = (uint64_t)((ch & 3) * 2 + (ch >> 2) * 1024);
                    uint64_t offV = (uint64_t)((ch & 3) * 2 + (ch >> 2) * 512);
                    mma_f16_ss(O_T, dP + offP, dV + offV, IDESC_PV, !(kt == 0 && ch == 0));
                }
                if (kt < qt) {
                    #pragma unroll
                    for (int ch = 0; ch < 4; ch++)
                        mma_f16_ss(S_T, dQ + ch * 2, dK + ch * 2, IDESC_QK, ch > 0);
                }
                TCGEN05_COMMIT(MBAR);
            }
        }
        if (kt < qt) {
            #pragma unroll
            for (int j = 0; j < 4; j++)
                rv[j] = *(const uint4*)(vTh + vgo[j] + (kt + 1) * 128);
        }
    }
    MBARRIER_WAIT_PARITY(MBAR, (qt + 1) & 1);
    TCGEN05_FENCE_AFTER();

    lsm[half * 128 + r_local] = lsum;
    __syncthreads();
    float l = lsm[r_local] + lsm[128 + r_local];
    float inv_l = 1.0f / l;
    {
        uint32_t o[32];
        TCGEN05_LD_X32(o, O_T + half * 32);
        TCGEN05_WAIT_LD();
        uint4 hv[4], lv[4];
        __nv_bfloat16* hb = (__nv_bfloat16*)hv;
        __nv_bfloat16* lb = (__nv_bfloat16*)lv;
        #pragma unroll
        for (int j = 0; j < 32; j++) {
            float val = __uint_as_float(o[j]) * inv_l;
            __nv_bfloat16 h16 = __float2bfloat16(val);
            hb[j] = h16;
            lb[j] = __float2bfloat16(val - __bfloat162float(h16));
        }
        size_t gbase = (size_t)b * SEQ * DMODEL + (size_t)h * HDIM +
                       (size_t)(qt * 128 + r_local) * DMODEL + half * 32;
        uint4* oph = (uint4*)(oh + gbase);
        uint4* opl = (uint4*)(ol + gbase);
        #pragma unroll
        for (int i = 0; i < 4; i++) { oph[i] = hv[i]; opl[i] = lv[i]; }
    }
    __syncthreads();
    if (wid == 0) TCGEN05_DEALLOC(tmem, 256);
#else
    // compile-only fallback
    int qt = gridDim.x - 1 - blockIdx.x, h = blockIdx.y, b = blockIdx.z;
    int tid = threadIdx.x;
    size_t rowbase = (size_t)b * SEQ * QSTRIDE + (size_t)h * HDIM;
    size_t obase   = (size_t)b * SEQ * DMODEL + (size_t)h * HDIM;
    const __nv_bfloat16* vTh = vT + ((size_t)(b * NHEADS + h) * HDIM) * SEQ;
    for (int r = tid; r < 128; r += blockDim.x) {
        int qg = qt * 128 + r;
        float o[HDIM]; float l = 0.0f;
        for (int d = 0; d < HDIM; d++) o[d] = 0.0f;
        for (int kk = 0; kk <= qg; kk++) {
            float s = 0.0f;
            for (int d = 0; d < HDIM; d++)
                s += __bfloat162float(qkv[rowbase + (size_t)qg * QSTRIDE + d]) *
                     __bfloat162float(qkv[rowbase + (size_t)kk * QSTRIDE + DMODEL + d]);
            float p = fast_exp2(s * 0.125f * 1.4426950408889634f);
            l += p;
            for (int d = 0; d < HDIM; d++)
                o[d] += p * __bfloat162float(vTh[(size_t)d * SEQ + kk]);
        }
        for (int d = 0; d < HDIM; d++) {
            float val = o[d] / l;
            __nv_bfloat16 h16 = __float2bfloat16(val);
            oh[obase + (size_t)qg * DMODEL + d] = h16;
            ol[obase + (size_t)qg * DMODEL + d] = __float2bfloat16(val - __bfloat162float(h16));
        }
    }
#endif
}

// ---------------- launcher ----------------
extern "C" void kernel_launch(void* const* d_in, const int* in_sizes, int n_in,
                              void* d_out, int out_size) {
    (void)in_sizes; (void)n_in; (void)out_size;
    const float* x     = (const float*)d_in[0];
    const float* wq    = (const float*)d_in[1];
    const float* bq    = (const float*)d_in[2];
    const float* wk    = (const float*)d_in[3];
    const float* bk    = (const float*)d_in[4];
    const float* wv    = (const float*)d_in[5];
    const float* bv    = (const float*)d_in[6];
    const float* wo    = (const float*)d_in[7];
    const float* bo    = (const float*)d_in[8];
    const float* w1    = (const float*)d_in[9];
    const float* b1    = (const float*)d_in[10];
    const float* w2    = (const float*)d_in[11];
    const float* b2    = (const float*)d_in[12];
    const float* ln1_g = (const float*)d_in[13];
    const float* ln1_b = (const float*)d_in[14];
    const float* ln2_g = (const float*)d_in[15];
    const float* ln2_b = (const float*)d_in[16];
    float* out = (float*)d_out;

    float *x1;
    cudaGetSymbolAddress((void**)&x1, g_x1);
    __nv_bfloat16 *qkv, *vT, *wqkvth, *wscr;
    cudaGetSymbolAddress((void**)&qkv, g_qkv);
    cudaGetSymbolAddress((void**)&vT, g_vT);
    cudaGetSymbolAddress((void**)&wqkvth, g_wqkvth);
    cudaGetSymbolAddress((void**)&wscr, g_wscr);
    __nv_bfloat16 *ln1h, *ln1l, *atth, *attl, *hh, *hl, *f1h, *f1l;
    cudaGetSymbolAddress((void**)&ln1h, g_ln1h); cudaGetSymbolAddress((void**)&ln1l, g_ln1l);
    cudaGetSymbolAddress((void**)&atth, g_atth); cudaGetSymbolAddress((void**)&attl, g_attl);
    cudaGetSymbolAddress((void**)&hh,   g_hh);   cudaGetSymbolAddress((void**)&hl,   g_hl);
    cudaGetSymbolAddress((void**)&f1h,  g_f1h);  cudaGetSymbolAddress((void**)&f1l,  g_f1l);
    __nv_bfloat16 *woth, *wotl, *w1th, *w1tl, *w2th, *w2tl;
    cudaGetSymbolAddress((void**)&woth, g_woth); cudaGetSymbolAddress((void**)&wotl, g_wotl);
    cudaGetSymbolAddress((void**)&w1th, g_w1th); cudaGetSymbolAddress((void**)&w1tl, g_w1tl);
    cudaGetSymbolAddress((void**)&w2th, g_w2th); cudaGetSymbolAddress((void**)&w2tl, g_w2tl);

    cudaFuncSetAttribute(tc_gemm1_kernel,
                         cudaFuncAttributeMaxDynamicSharedMemorySize, GEMM1_SMEM_BYTES);
    cudaFuncSetAttribute(tc_gemm_kernel<false, true, 0>,
                         cudaFuncAttributeMaxDynamicSharedMemorySize, GEMM_SMEM_BYTES);
    cudaFuncSetAttribute(tc_gemm256_kernel,
                         cudaFuncAttributeMaxDynamicSharedMemorySize, GEMM256_SMEM_BYTES);
    cudaFuncSetAttribute(tc_attn_kernel,
                         cudaFuncAttributeMaxDynamicSharedMemorySize, ATTN_SMEM_BYTES);

    dim3 grid_d(DMODEL / 128, MROWS / 128);       // (6, 32)
    dim3 grid_qkv(QSTRIDE / 128, MROWS / 128);    // (18, 32)
    dim3 grid_ff1(DFF / 256, MROWS / 128);        // (12, 32)
    dim3 agrid(SEQ / 128, NHEADS, BATCH);

    layernorm_split_kernel<<<MROWS, 256>>>(x, ln1_g, ln1_b, ln1h, ln1l);
    transpose4_split_kernel<<<dim3(DMODEL / 128, DMODEL / 32, 4), 256>>>(
        wq, wk, wv, wo,
        wqkvth,                       wscr,
        wqkvth + DMODEL * DMODEL,     wscr + DMODEL * DMODEL,
        wqkvth + 2 * DMODEL * DMODEL, wscr + 2 * DMODEL * DMODEL,
        woth, wotl);
    tc_gemm1_kernel<<<grid_qkv, 256, GEMM1_SMEM_BYTES>>>(
        ln1h, wqkvth, bq, bk, bv, qkv, vT, MROWS, QSTRIDE, DMODEL);
    tc_attn_kernel<<<agrid, 256, ATTN_SMEM_BYTES>>>(qkv, vT, atth, attl);
    transpose_split_kernel<<<dim3(DFF / 128,    DMODEL / 32), 256>>>(w1, w1th, w1tl, DMODEL, DFF);
    transpose_split_kernel<<<dim3(DMODEL / 128, DFF / 32),    256>>>(w2, w2th, w2tl, DFF, DMODEL);
    tc_gemm_kernel<false, true, 0><<<grid_d, 256, GEMM_SMEM_BYTES>>>(
        atth, attl, woth, wotl, bo, x, x1, nullptr, nullptr, MROWS, DMODEL, DMODEL);
    layernorm_split_kernel<<<MROWS, 256>>>(x1, ln2_g, ln2_b, hh, hl);
    tc_gemm256_kernel<<<grid_ff1, 256, GEMM256_SMEM_BYTES>>>(
        hh, hl, w1th, w1tl, b1, f1h, f1l, MROWS, DFF, DMODEL);
    tc_gemm_kernel<false, true, 0><<<grid_d, 256, GEMM_SMEM_BYTES>>>(
        f1h, f1l, w2th, w2tl, b2, x1, out, nullptr, nullptr, MROWS, DMODEL, DFF);
}

// round 15
// speedup vs baseline: 1.0304x; 1.0304x over previous
#include <cuda_runtime.h>
#include <cuda_bf16.h>
#include <math.h>
#include <stdint.h>

// ---------------- problem constants ----------------
#define BATCH   2
#define SEQ     2048
#define DMODEL  768
#define NHEADS  12
#define HDIM    64
#define DFF     3072
#define MROWS   (BATCH * SEQ)        // 4096
#define LN_EPS  1e-5f
#define QSTRIDE 2304                 // fused qkv row stride

#if defined(__CUDA_ARCH__) && (defined(__CUDA_ARCH_FEAT_SM103_ALL) || defined(__CUDA_ARCH_FEAT_SM100_ALL) || defined(__CUDA_ARCH_FEAT_SM101_ALL))
#define HAS_TCGEN05 1
#else
#define HAS_TCGEN05 0
#endif

// ---------------- inline PTX helpers (sm_103a) ----------------
__device__ __forceinline__ uint32_t smem_u32(const void* p) {
    uint32_t a;
    asm("{ .reg .u64 t; cvta.to.shared.u64 t, %1; cvt.u32.u64 %0, t; }" : "=r"(a) : "l"(p));
    return a;
}

#if HAS_TCGEN05
__device__ __forceinline__ uint32_t elect_one() {
    uint32_t pred;
    asm volatile("{\n\t.reg .pred p;\n\telect.sync _|p, 0xFFFFFFFF;\n\tselp.b32 %0, 1, 0, p;\n\t}" : "=r"(pred));
    return pred;
}
#define MBARRIER_INIT(addr, cnt) \
    asm volatile("mbarrier.init.shared.b64 [%0], %1;" :: "r"((uint32_t)(addr)), "r"((uint32_t)(cnt)) : "memory")
#define MBARRIER_WAIT_PARITY(addr, par) do { \
    uint32_t _m = (uint32_t)(addr), _p = (uint32_t)(par), _d; \
    asm volatile("{\n\t.reg .pred p;\n\tmbarrier.try_wait.parity.acquire.cta.shared::cta.b64 p, [%1], %2;\n\tselp.b32 %0, 1, 0, p;\n\t}" \
        : "=r"(_d) : "r"(_m), "r"(_p) : "memory"); \
    if (!_d) { \
        asm volatile("{\n\t.reg .pred P1;\n\tWL_%=:\n\tmbarrier.try_wait.parity.acquire.cta.shared::cta.b64 P1, [%0], %1, 0x989680;\n\t@P1 bra.uni WD_%=;\n\tbra.uni WL_%=;\n\tWD_%=:\n\t}" \
            :: "r"(_m), "r"(_p) : "memory"); \
    } \
} while (0)
#define TCGEN05_ALLOC(saddr, ncols) \
    asm volatile("tcgen05.alloc.cta_group::1.sync.aligned.shared::cta.b32 [%0], %1;" :: "r"((uint32_t)(saddr)), "r"((uint32_t)(ncols)) : "memory")
#define TCGEN05_DEALLOC(tmem, ncols) \
    asm volatile("tcgen05.dealloc.cta_group::1.sync.aligned.b32 %0, %1;" :: "r"(tmem), "r"((uint32_t)(ncols)))
#define TCGEN05_RELINQUISH() \
    asm volatile("tcgen05.relinquish_alloc_permit.cta_group::1.sync.aligned;")
#define TCGEN05_COMMIT(mbar) \
    asm volatile("tcgen05.commit.cta_group::1.mbarrier::arrive::one.shared::cluster.b64 [%0];" :: "r"((uint32_t)(mbar)) : "memory")
#define TCGEN05_WAIT_LD() asm volatile("tcgen05.wait::ld.sync.aligned;" ::: "memory")
#define TCGEN05_FENCE_AFTER() asm volatile("tcgen05.fence::after_thread_sync;" ::: "memory")
#define FENCE_PROXY_ASYNC_SHARED_CTA() asm volatile("fence.proxy.async.shared::cta;" ::: "memory")
#define TCGEN05_LD_X32(r, tmem_addr) \
    asm volatile( \
        "tcgen05.ld.sync.aligned.32x32b.x32.b32 " \
        "{%0, %1, %2, %3, %4, %5, %6, %7, " \
        " %8, %9, %10, %11, %12, %13, %14, %15, " \
        " %16, %17, %18, %19, %20, %21, %22, %23, " \
        " %24, %25, %26, %27, %28, %29, %30, %31}, [%32];" \
        : "=r"((r)[0]),  "=r"((r)[1]),  "=r"((r)[2]),  "=r"((r)[3]), \
          "=r"((r)[4]),  "=r"((r)[5]),  "=r"((r)[6]),  "=r"((r)[7]), \
          "=r"((r)[8]),  "=r"((r)[9]),  "=r"((r)[10]), "=r"((r)[11]), \
          "=r"((r)[12]), "=r"((r)[13]), "=r"((r)[14]), "=r"((r)[15]), \
          "=r"((r)[16]), "=r"((r)[17]), "=r"((r)[18]), "=r"((r)[19]), \
          "=r"((r)[20]), "=r"((r)[21]), "=r"((r)[22]), "=r"((r)[23]), \
          "=r"((r)[24]), "=r"((r)[25]), "=r"((r)[26]), "=r"((r)[27]), \
          "=r"((r)[28]), "=r"((r)[29]), "=r"((r)[30]), "=r"((r)[31]) \
        : "r"(tmem_addr))

// K-major SW128 descriptor (LBO=1, SBO=64)
static __device__ __forceinline__ uint64_t make_desc_sw128(uint32_t addr) {
    const uint64_t base =
        (uint64_t(2) << 61) | (uint64_t(1) << 46) | (uint64_t(64) << 32) | (uint64_t(1) << 16);
    return base | ((uint64_t)(addr >> 4) & 0x3FFF);
}

__device__ __forceinline__ void mma_f16_ss(uint32_t d_tmem, uint64_t a_desc, uint64_t b_desc,
                                           uint32_t idesc, bool enable_d) {
    uint32_t en = enable_d ? 1u : 0u;
    asm volatile(
        "{\n\t.reg .pred p;\n\t"
        "setp.ne.u32 p, %5, 0;\n\t"
        "tcgen05.mma.cta_group::1.kind::f16 [%0], %1, %2, %3, {%4, %4, %4, %4}, p;\n\t}"
        :: "r"(d_tmem), "l"(a_desc), "l"(b_desc), "r"(idesc), "r"(0u), "r"(en)
        : "memory");
}
#endif // HAS_TCGEN05

__device__ __forceinline__ uint32_t sw128(uint32_t off) { return off ^ ((off >> 3) & 0x70); }

// fast exp2 on the FMA pipe (no MUFU). |x| < ~30, err ~2e-6 relative.
__device__ __forceinline__ float fast_exp2(float x) {
    float t = x + 12582912.0f;
    int   e = __float_as_int(t);
    float r = t - 12582912.0f;
    float f = x - r;
    float p = 1.3333558146e-3f;
    p = fmaf(p, f, 9.6181298421e-3f);
    p = fmaf(p, f, 5.5504108664e-2f);
    p = fmaf(p, f, 2.4022650696e-1f);
    p = fmaf(p, f, 6.9314718056e-1f);
    p = fmaf(p, f, 1.0f);
    return __int_as_float(__float_as_int(p) + (e << 23));
}

// ---------------- scratch (device globals; no allocs allowed) ----------------
__device__ float g_x1 [MROWS * DMODEL];

__device__ __nv_bfloat16 g_qkv[MROWS * QSTRIDE];                 // q,k used; v region unused
__device__ __nv_bfloat16 g_vT [BATCH * NHEADS * HDIM * SEQ];     // v transposed [b,h,d,s]

__device__ __nv_bfloat16 g_ln1h[MROWS * DMODEL], g_ln1l[MROWS * DMODEL];
__device__ __nv_bfloat16 g_atth[MROWS * DMODEL], g_attl[MROWS * DMODEL];
__device__ __nv_bfloat16 g_hh  [MROWS * DMODEL], g_hl  [MROWS * DMODEL];
__device__ __nv_bfloat16 g_f1h [MROWS * DFF],    g_f1l [MROWS * DFF];

__device__ __nv_bfloat16 g_wqkvth[QSTRIDE * DMODEL];   // fused Wq|Wk|Wv transposed (hi)
__device__ __nv_bfloat16 g_wscr  [QSTRIDE * DMODEL];   // lo scratch (unused by 1-term gemm)
__device__ __nv_bfloat16 g_woth[DMODEL * DMODEL], g_wotl[DMODEL * DMODEL];
__device__ __nv_bfloat16 g_w1th[DFF * DMODEL],    g_w1tl[DFF * DMODEL];
__device__ __nv_bfloat16 g_w2th[DMODEL * DFF],    g_w2tl[DMODEL * DFF];

// ---------------- vectorized weight transpose + fp32->bf16 hi/lo split --------
__device__ __forceinline__ void transpose_tile_body(const float* __restrict__ W,
                                                    __nv_bfloat16* __restrict__ Th,
                                                    __nv_bfloat16* __restrict__ Tl,
                                                    int K, int N, int n0, int k0) {
    __shared__ float sm[32][133];
    int t = threadIdx.x;
    int tx = t & 31, ty = t >> 5;              // 32 x 8
    #pragma unroll
    for (int i = 0; i < 4; i++) {
        int r = ty + 8 * i;
        float4 v = *(const float4*)(W + (size_t)(k0 + r) * N + n0 + tx * 4);
        sm[r][tx * 4 + 0] = v.x;
        sm[r][tx * 4 + 1] = v.y;
        sm[r][tx * 4 + 2] = v.z;
        sm[r][tx * 4 + 3] = v.w;
    }
    __syncthreads();
    int kb = (t & 3) * 8;                      // k chunk base (0,8,16,24)
    int nrow = t >> 2;                         // 0..63
    #pragma unroll
    for (int pass = 0; pass < 2; pass++) {
        int n = nrow + 64 * pass;
        __nv_bfloat16 hbuf[8], lbuf[8];
        #pragma unroll
        for (int j = 0; j < 8; j++) {
            float v = sm[kb + j][n];
            __nv_bfloat16 h = __float2bfloat16(v);
            hbuf[j] = h;
            lbuf[j] = __float2bfloat16(v - __bfloat162float(h));
        }
        size_t o = (size_t)(n0 + n) * K + k0 + kb;
        *(uint4*)(Th + o) = *(uint4*)hbuf;
        *(uint4*)(Tl + o) = *(uint4*)lbuf;
    }
}

// batched transpose of the four 768x768 weights in one launch (z = which matrix)
__global__ __launch_bounds__(256)
void transpose4_split_kernel(const float* __restrict__ W0, const float* __restrict__ W1,
                             const float* __restrict__ W2, const float* __restrict__ W3,
                             __nv_bfloat16* __restrict__ T0h, __nv_bfloat16* __restrict__ T0l,
                             __nv_bfloat16* __restrict__ T1h, __nv_bfloat16* __restrict__ T1l,
                             __nv_bfloat16* __restrict__ T2h, __nv_bfloat16* __restrict__ T2l,
                             __nv_bfloat16* __restrict__ T3h, __nv_bfloat16* __restrict__ T3l) {
    int z = blockIdx.z;
    const float* W = (z == 0) ? W0 : (z == 1) ? W1 : (z == 2) ? W2 : W3;
    __nv_bfloat16* Th = (z == 0) ? T0h : (z == 1) ? T1h : (z == 2) ? T2h : T3h;
    __nv_bfloat16* Tl = (z == 0) ? T0l : (z == 1) ? T1l : (z == 2) ? T2l : T3l;
    transpose_tile_body(W, Th, Tl, DMODEL, DMODEL, blockIdx.x * 128, blockIdx.y * 32);
}

// merged transpose of w1 [768,3072] and w2 [3072,768] in one launch.
// grid: (24, 24, 2). z=0 -> w1 (grid maps directly); z=1 -> w2 (flattened decode).
__global__ __launch_bounds__(256)
void transpose2_split_kernel(const float* __restrict__ W1f, const float* __restrict__ W2f,
                             __nv_bfloat16* __restrict__ T1h, __nv_bfloat16* __restrict__ T1l,
                             __nv_bfloat16* __restrict__ T2h, __nv_bfloat16* __restrict__ T2l) {
    if (blockIdx.z == 0) {
        // w1: K=DMODEL, N=DFF. grid x: DFF/128 = 24, y: DMODEL/32 = 24
        transpose_tile_body(W1f, T1h, T1l, DMODEL, DFF,
                            blockIdx.x * 128, blockIdx.y * 32);
    } else {
        // w2: K=DFF, N=DMODEL. need (DMODEL/128=6) x (DFF/32=96) = 576 blocks
        int idx = blockIdx.y * 24 + blockIdx.x;      // 0..575
        int n0 = (idx % 6) * 128;
        int k0 = (idx / 6) * 32;
        transpose_tile_body(W2f, T2h, T2l, DFF, DMODEL, n0, k0);
    }
}

// ---------------- block reduction ----------------
__device__ __forceinline__ float block_sum(float v) {
    __shared__ float sm[32];
    __syncthreads();
    int lane = threadIdx.x & 31;
    int wid  = threadIdx.x >> 5;
    #pragma unroll
    for (int o = 16; o > 0; o >>= 1) v += __shfl_down_sync(0xffffffffu, v, o);
    if (lane == 0) sm[wid] = v;
    __syncthreads();
    if (wid == 0) {
        int nw = (blockDim.x + 31) >> 5;
        v = (lane < nw) ? sm[lane] : 0.0f;
        #pragma unroll
        for (int o = 16; o > 0; o >>= 1) v += __shfl_down_sync(0xffffffffu, v, o);
        if (lane == 0) sm[0] = v;
    }
    __syncthreads();
    return sm[0];
}

// ---------------- LayerNorm -> bf16 hi/lo planes ----------------
__global__ __launch_bounds__(256)
void layernorm_split_kernel(const float* __restrict__ x,
                            const float* __restrict__ g,
                            const float* __restrict__ b,
                            __nv_bfloat16* __restrict__ oh,
                            __nv_bfloat16* __restrict__ ol) {
    int row = blockIdx.x;
    const float* xr = x + (size_t)row * DMODEL;
    int t = threadIdx.x;

    float v0 = xr[t], v1 = xr[t + 256], v2 = xr[t + 512];
    float mu = block_sum(v0 + v1 + v2) * (1.0f / DMODEL);
    float d0 = v0 - mu, d1 = v1 - mu, d2 = v2 - mu;
    float var = block_sum(d0 * d0 + d1 * d1 + d2 * d2) * (1.0f / DMODEL);
    float rs = rsqrtf(var + LN_EPS);

    size_t base = (size_t)row * DMODEL;
    #pragma unroll
    for (int i = 0; i < 3; i++) {
        int c = t + 256 * i;
        float d = (i == 0) ? d0 : (i == 1 ? d1 : d2);
        float v = d * rs * g[c] + b[c];
        __nv_bfloat16 h = __float2bfloat16(v);
        oh[base + c] = h;
        ol[base + c] = __float2bfloat16(v - __bfloat162float(h));
    }
}

// ---------------- fused QKV: 1-term bf16 tcgen05 GEMM, pipelined ----------------
#define G1_CTRL  33792
#define GEMM1_SMEM_BYTES (1024 + 33792 + 64)

__global__ __launch_bounds__(256)
void tc_gemm1_kernel(const __nv_bfloat16* __restrict__ Ah, const __nv_bfloat16* __restrict__ Bh,
                     const float* __restrict__ bq, const float* __restrict__ bk,
                     const float* __restrict__ bv, __nv_bfloat16* __restrict__ Cqk,
                     __nv_bfloat16* __restrict__ CvT, int M, int N, int K) {
#if HAS_TCGEN05
    extern __shared__ char dsm[];
    uint32_t sbase = smem_u32(dsm);
    uint32_t tile  = (sbase + 1023u) & ~1023u;
    char* tp = dsm + (tile - sbase);
    const int A_HI = 0, B_HI = 16384;
    const uint32_t CTRL = tile + G1_CTRL;

    int tid = threadIdx.x, wid = tid >> 5, lid = tid & 31;
    int brow = blockIdx.y * 128, bcol = blockIdx.x * 128;
    const float* bsel = (bcol < DMODEL) ? bq : (bcol < 2 * DMODEL ? bk : bv);
    int boff = (bcol < DMODEL) ? 0 : (bcol < 2 * DMODEL ? DMODEL : 2 * DMODEL);

    if (wid == 0) { TCGEN05_ALLOC(CTRL, 128); TCGEN05_RELINQUISH(); }
    if (tid == 0) MBARRIER_INIT(CTRL + 8, 1);
    __syncthreads();
    uint32_t tmem;
    asm volatile("ld.shared.b32 %0, [%1];" : "=r"(tmem) : "r"(CTRL));

    const uint32_t IDESC = (1u << 4) | (1u << 7) | (1u << 10) | (16u << 17) | (8u << 24);
    const uint64_t dah = make_desc_sw128(tile + A_HI);
    const uint64_t dbh = make_desc_sw128(tile + B_HI);

    uint32_t swo[4]; int eoff[4];
    #pragma unroll
    for (int j = 0; j < 4; j++) {
        int cid = tid + 256 * j;
        int r = cid >> 3, cb = (cid & 7) << 4;
        swo[j] = sw128((uint32_t)(r * 128 + cb));
        eoff[j] = r * K + (cb >> 1);
    }
    const __nv_bfloat16* Abase = Ah + (size_t)brow * K;
    const __nv_bfloat16* Bbase = Bh + (size_t)bcol * K;

    int T = K >> 6;
    uint4 ra[4], rb[4];
    #pragma unroll
    for (int j = 0; j < 4; j++) {
        ra[j] = *(const uint4*)(Abase + eoff[j]);
        rb[j] = *(const uint4*)(Bbase + eoff[j]);
    }
    for (int it = 0; it < T; ++it) {
        if (it > 0) MBARRIER_WAIT_PARITY(CTRL + 8, (it - 1) & 1);
        __syncthreads();
        #pragma unroll
        for (int j = 0; j < 4; j++) {
            *(uint4*)(tp + A_HI + swo[j]) = ra[j];
            *(uint4*)(tp + B_HI + swo[j]) = rb[j];
        }
        __syncthreads();
        if (wid == 0) {
            FENCE_PROXY_ASYNC_SHARED_CTA();
            if (elect_one()) {
                #pragma unroll
                for (int ch = 0; ch < 4; ch++)
                    mma_f16_ss(tmem, dah + ch * 2, dbh + ch * 2, IDESC, !(it == 0 && ch == 0));
                TCGEN05_COMMIT(CTRL + 8);
            }
        }
        if (it + 1 < T) {
            int k0 = (it + 1) << 6;
            #pragma unroll
            for (int j = 0; j < 4; j++) {
                ra[j] = *(const uint4*)(Abase + eoff[j] + k0);
                rb[j] = *(const uint4*)(Bbase + eoff[j] + k0);
            }
        }
    }
    MBARRIER_WAIT_PARITY(CTRL + 8, (T - 1) & 1);
    TCGEN05_FENCE_AFTER();
    __syncthreads();

    int sub = wid & 3, grp = wid >> 2;
    if (bcol < 2 * DMODEL) {
        float* tb = (float*)(tp + wid * 4224);
        #pragma unroll
        for (int c0 = 0; c0 < 64; c0 += 32) {
            int cbase = grp * 64 + c0;
            uint32_t d[32];
            TCGEN05_LD_X32(d, tmem + cbase);
            TCGEN05_WAIT_LD();
            #pragma unroll
            for (int j = 0; j < 32; j++) tb[lid * 33 + j] = __uint_as_float(d[j]);
            __syncwarp();
            #pragma unroll
            for (int j = 0; j < 32; j++) {
                int grow = brow + sub * 32 + j;
                int gcol = bcol + cbase + lid;
                Cqk[(size_t)grow * N + gcol] =
                    __float2bfloat16(tb[j * 33 + lid] + bsel[gcol - boff]);
            }
            __syncwarp();
        }
    } else {
        int grow = brow + sub * 32 + lid;
        int bb = grow >> 11, s = grow & (SEQ - 1);
        #pragma unroll
        for (int c0 = 0; c0 < 64; c0 += 32) {
            int cbase = grp * 64 + c0;
            uint32_t d[32];
            TCGEN05_LD_X32(d, tmem + cbase);
            TCGEN05_WAIT_LD();
            #pragma unroll
            for (int j = 0; j < 32; j++) {
                int gcol = bcol + cbase + j;
                int vcol = gcol - 2 * DMODEL;
                int hh2 = vcol >> 6, dl = vcol & 63;
                CvT[((size_t)(bb * NHEADS + hh2) * HDIM + dl) * SEQ + s] =
                    __float2bfloat16(__uint_as_float(d[j]) + bsel[gcol - boff]);
            }
        }
    }
    __syncthreads();
    if (wid == 0) TCGEN05_DEALLOC(tmem, 128);
#else
    int tid = threadIdx.x;
    int brow = blockIdx.y * 128, bcol = blockIdx.x * 128;
    for (int e = tid; e < 128 * 128; e += 256) {
        int r = e >> 7, c = e & 127;
        int grow = brow + r, gcol = bcol + c;
        float acc = 0.0f;
        for (int kk = 0; kk < K; kk++)
            acc = fmaf(__bfloat162float(Ah[(size_t)grow * K + kk]),
                       __bfloat162float(Bh[(size_t)gcol * K + kk]), acc);
        const float* bsel = (gcol < DMODEL) ? bq : (gcol < 2 * DMODEL ? bk : bv);
        int boff = (gcol < DMODEL) ? 0 : (gcol < 2 * DMODEL ? DMODEL : 2 * DMODEL);
        float v = acc + bsel[gcol - boff];
        if (gcol < 2 * DMODEL) {
            Cqk[(size_t)grow * N + gcol] = __float2bfloat16(v);
        } else {
            int vcol = gcol - 2 * DMODEL;
            int bb = grow >> 11, s = grow & (SEQ - 1);
            CvT[((size_t)(bb * NHEADS + (vcol >> 6)) * HDIM + (vcol & 63)) * SEQ + s] =
                __float2bfloat16(v);
        }
    }
#endif
}

// ---------------- 3-term split tcgen05 GEMM, 128x128 (R13 form) --------------
// Register prefetch + split-commit overlap; no min-blocks bound (2 CTAs/SM).
#define GEMM_SMEM_BYTES (1024 + 65536 + 64)

template <bool RELU, bool ADDRES, int OUT>
__global__ __launch_bounds__(256)
void tc_gemm_kernel(const __nv_bfloat16* __restrict__ Ah, const __nv_bfloat16* __restrict__ Al,
                    const __nv_bfloat16* __restrict__ Bh, const __nv_bfloat16* __restrict__ Bl,
                    const float* __restrict__ bias, const float* __restrict__ res,
                    float* __restrict__ Cf,
                    __nv_bfloat16* __restrict__ Ch, __nv_bfloat16* __restrict__ Cl,
                    int M, int N, int K) {
#if HAS_TCGEN05
    extern __shared__ char dsm[];
    uint32_t sbase = smem_u32(dsm);
    uint32_t tile  = (sbase + 1023u) & ~1023u;
    char* tp = dsm + (tile - sbase);

    const int A_HI = 0, A_LO = 16384, B_HI = 32768, B_LO = 49152;
    const uint32_t CTRL = tile + 65536;

    int tid = threadIdx.x, wid = tid >> 5, lid = tid & 31;
    int brow = blockIdx.y * 128, bcol = blockIdx.x * 128;

    if (wid == 0) { TCGEN05_ALLOC(CTRL, 128); TCGEN05_RELINQUISH(); }
    if (tid == 0) MBARRIER_INIT(CTRL + 8, 2);   // two commits per K-iter
    __syncthreads();
    uint32_t tmem;
    asm volatile("ld.shared.b32 %0, [%1];" : "=r"(tmem) : "r"(CTRL));

    const uint32_t IDESC = (1u << 4) | (1u << 7) | (1u << 10) | (16u << 17) | (8u << 24);
    const uint64_t dah = make_desc_sw128(tile + A_HI);
    const uint64_t dal = make_desc_sw128(tile + A_LO);
    const uint64_t dbh = make_desc_sw128(tile + B_HI);
    const uint64_t dbl = make_desc_sw128(tile + B_LO);

    uint32_t swo[4]; int eoff[4];
    #pragma unroll
    for (int j = 0; j < 4; j++) {
        int cid = tid + 256 * j;
        int r = cid >> 3, cb = (cid & 7) << 4;
        swo[j] = sw128((uint32_t)(r * 128 + cb));
        eoff[j] = r * K + (cb >> 1);
    }
    const __nv_bfloat16* Ahb = Ah + (size_t)brow * K;
    const __nv_bfloat16* Alb = Al + (size_t)brow * K;
    const __nv_bfloat16* Bhb = Bh + (size_t)bcol * K;
    const __nv_bfloat16* Blb = Bl + (size_t)bcol * K;

    int T = K >> 6;
    uint4 rah[4], ral[4], rbh[4], rbl[4];
    #pragma unroll
    for (int j = 0; j < 4; j++) {
        rah[j] = *(const uint4*)(Ahb + eoff[j]);
        ral[j] = *(const uint4*)(Alb + eoff[j]);
        rbh[j] = *(const uint4*)(Bhb + eoff[j]);
        rbl[j] = *(const uint4*)(Blb + eoff[j]);
    }
    for (int it = 0; it < T; ++it) {
        if (it > 0) MBARRIER_WAIT_PARITY(CTRL + 8, (it - 1) & 1);
        __syncthreads();
        // phase A: stage hi planes, launch hi*hi MMAs
        #pragma unroll
        for (int j = 0; j < 4; j++) {
            *(uint4*)(tp + A_HI + swo[j]) = rah[j];
            *(uint4*)(tp + B_HI + swo[j]) = rbh[j];
        }
        __syncthreads();
        if (wid == 0) {
            FENCE_PROXY_ASYNC_SHARED_CTA();
            if (elect_one()) {
                #pragma unroll
                for (int ch = 0; ch < 4; ch++)
                    mma_f16_ss(tmem, dah + ch * 2, dbh + ch * 2, IDESC, !(it == 0 && ch == 0));
                TCGEN05_COMMIT(CTRL + 8);
            }
        }
        // phase B: stage lo planes + prefetch next (overlaps hi*hi MMAs)
        #pragma unroll
        for (int j = 0; j < 4; j++) {
            *(uint4*)(tp + A_LO + swo[j]) = ral[j];
            *(uint4*)(tp + B_LO + swo[j]) = rbl[j];
        }
        if (it + 1 < T) {
            int k0 = (it + 1) << 6;
            #pragma unroll
            for (int j = 0; j < 4; j++) {
                rah[j] = *(const uint4*)(Ahb + eoff[j] + k0);
                ral[j] = *(const uint4*)(Alb + eoff[j] + k0);
                rbh[j] = *(const uint4*)(Bhb + eoff[j] + k0);
                rbl[j] = *(const uint4*)(Blb + eoff[j] + k0);
            }
        }
        __syncthreads();
        if (wid == 0) {
            FENCE_PROXY_ASYNC_SHARED_CTA();
            if (elect_one()) {
                #pragma unroll
                for (int ch = 0; ch < 4; ch++) {
                    uint64_t off = (uint64_t)(ch * 2);
                    mma_f16_ss(tmem, dah + off, dbl + off, IDESC, true);
                    mma_f16_ss(tmem, dal + off, dbh + off, IDESC, true);
                }
                TCGEN05_COMMIT(CTRL + 8);
            }
        }
    }
    MBARRIER_WAIT_PARITY(CTRL + 8, (T - 1) & 1);
    TCGEN05_FENCE_AFTER();
    __syncthreads();

    int sub = wid & 3, grp = wid >> 2;
    float* tb = (float*)(tp + wid * 4224);
    #pragma unroll
    for (int c0 = 0; c0 < 64; c0 += 32) {
        int cbase = grp * 64 + c0;
        uint32_t d[32];
        TCGEN05_LD_X32(d, tmem + cbase);
        TCGEN05_WAIT_LD();
        #pragma unroll
        for (int j = 0; j < 32; j++) tb[lid * 33 + j] = __uint_as_float(d[j]);
        __syncwarp();
        #pragma unroll
        for (int j = 0; j < 32; j++) {
            int grow = brow + sub * 32 + j;
            int gcol = bcol + cbase + lid;
            float v = tb[j * 33 + lid] + bias[gcol];
            if (RELU)   v = fmaxf(v, 0.0f);
            if (ADDRES) v += res[(size_t)grow * N + gcol];
            if (OUT == 1) {
                __nv_bfloat16 h = __float2bfloat16(v);
                Ch[(size_t)grow * N + gcol] = h;
                Cl[(size_t)grow * N + gcol] = __float2bfloat16(v - __bfloat162float(h));
            } else {
                Cf[(size_t)grow * N + gcol] = v;
            }
        }
        __syncwarp();
    }
    __syncthreads();
    if (wid == 0) TCGEN05_DEALLOC(tmem, 128);
#else
    int tid = threadIdx.x;
    int brow = blockIdx.y * 128, bcol = blockIdx.x * 128;
    for (int e = tid; e < 128 * 128; e += 256) {
        int r = e >> 7, c = e & 127;
        int grow = brow + r, gcol = bcol + c;
        float acc = 0.0f;
        for (int kk = 0; kk < K; kk++) {
            float a = __bfloat162float(Ah[(size_t)grow * K + kk]) +
                      __bfloat162float(Al[(size_t)grow * K + kk]);
            float b = __bfloat162float(Bh[(size_t)gcol * K + kk]) +
                      __bfloat162float(Bl[(size_t)gcol * K + kk]);
            acc = fmaf(a, b, acc);
        }
        float v = acc + bias[gcol];
        if (RELU)   v = fmaxf(v, 0.0f);
        if (ADDRES) v += res[(size_t)grow * N + gcol];
        if (OUT == 1) {
            __nv_bfloat16 h = __float2bfloat16(v);
            Ch[(size_t)grow * N + gcol] = h;
            Cl[(size_t)grow * N + gcol] = __float2bfloat16(v - __bfloat162float(h));
        } else {
            Cf[(size_t)grow * N + gcol] = v;
        }
    }
#endif
}

// ---------------- 3-term split GEMM, 128x256 tile, split-commit overlap -------
#define G256_A_HI 0
#define G256_A_LO 16384
#define G256_B_HI 32768
#define G256_B_LO 65536
#define G256_CTRL 98304
#define GEMM256_SMEM_BYTES (1024 + 98304 + 64)

__global__ __launch_bounds__(256)
void tc_gemm256_kernel(const __nv_bfloat16* __restrict__ Ah, const __nv_bfloat16* __restrict__ Al,
                       const __nv_bfloat16* __restrict__ Bh, const __nv_bfloat16* __restrict__ Bl,
                       const float* __restrict__ bias,
                       __nv_bfloat16* __restrict__ Ch, __nv_bfloat16* __restrict__ Cl,
                       int M, int N, int K) {
#if HAS_TCGEN05
    extern __shared__ char dsm[];
    uint32_t sbase = smem_u32(dsm);
    uint32_t tile  = (sbase + 1023u) & ~1023u;
    char* tp = dsm + (tile - sbase);
    const uint32_t CTRL = tile + G256_CTRL;

    int tid = threadIdx.x, wid = tid >> 5, lid = tid & 31;
    int brow = blockIdx.y * 128, bcol = blockIdx.x * 256;

    if (wid == 0) { TCGEN05_ALLOC(CTRL, 256); TCGEN05_RELINQUISH(); }
    if (tid == 0) MBARRIER_INIT(CTRL + 8, 2);   // two commits per K-iter
    __syncthreads();
    uint32_t tmem;
    asm volatile("ld.shared.b32 %0, [%1];" : "=r"(tmem) : "r"(CTRL));

    const uint32_t IDESC = (1u << 4) | (1u << 7) | (1u << 10) | (32u << 17) | (8u << 24);
    const uint64_t dah = make_desc_sw128(tile + G256_A_HI);
    const uint64_t dal = make_desc_sw128(tile + G256_A_LO);
    const uint64_t dbh = make_desc_sw128(tile + G256_B_HI);
    const uint64_t dbl = make_desc_sw128(tile + G256_B_LO);

    uint32_t aswo[4]; int aeoff[4];
    #pragma unroll
    for (int j = 0; j < 4; j++) {
        int cid = tid + 256 * j;
        int r = cid >> 3, cb = (cid & 7) << 4;
        aswo[j] = sw128((uint32_t)(r * 128 + cb));
        aeoff[j] = r * K + (cb >> 1);
    }
    uint32_t bswo[8]; int beoff[8];
    #pragma unroll
    for (int j = 0; j < 8; j++) {
        int cid = tid + 256 * j;
        int r = cid >> 3, cb = (cid & 7) << 4;
        bswo[j] = sw128((uint32_t)(r * 128 + cb));
        beoff[j] = r * K + (cb >> 1);
    }
    const __nv_bfloat16* Ahb = Ah + (size_t)brow * K;
    const __nv_bfloat16* Alb = Al + (size_t)brow * K;
    const __nv_bfloat16* Bhb = Bh + (size_t)bcol * K;
    const __nv_bfloat16* Blb = Bl + (size_t)bcol * K;

    int T = K >> 6;
    for (int it = 0; it < T; ++it) {
        int k0 = it << 6;
        if (it > 0) MBARRIER_WAIT_PARITY(CTRL + 8, (it - 1) & 1);
        __syncthreads();
        // phase A: stage hi planes
        #pragma unroll
        for (int j = 0; j < 4; j++)
            *(uint4*)(tp + G256_A_HI + aswo[j]) = *(const uint4*)(Ahb + aeoff[j] + k0);
        #pragma unroll
        for (int j = 0; j < 8; j++)
            *(uint4*)(tp + G256_B_HI + bswo[j]) = *(const uint4*)(Bhb + beoff[j] + k0);
        __syncthreads();
        if (wid == 0) {
            FENCE_PROXY_ASYNC_SHARED_CTA();
            if (elect_one()) {
                #pragma unroll
                for (int ch = 0; ch < 4; ch++)
                    mma_f16_ss(tmem, dah + ch * 2, dbh + ch * 2, IDESC, !(it == 0 && ch == 0));
                TCGEN05_COMMIT(CTRL + 8);
            }
        }
        // phase B: stage lo planes (overlaps hi*hi MMAs)
        #pragma unroll
        for (int j = 0; j < 4; j++)
            *(uint4*)(tp + G256_A_LO + aswo[j]) = *(const uint4*)(Alb + aeoff[j] + k0);
        #pragma unroll
        for (int j = 0; j < 8; j++)
            *(uint4*)(tp + G256_B_LO + bswo[j]) = *(const uint4*)(Blb + beoff[j] + k0);
        __syncthreads();
        if (wid == 0) {
            FENCE_PROXY_ASYNC_SHARED_CTA();
            if (elect_one()) {
                #pragma unroll
                for (int ch = 0; ch < 4; ch++) {
                    uint64_t off = (uint64_t)(ch * 2);
                    mma_f16_ss(tmem, dah + off, dbl + off, IDESC, true);
                    mma_f16_ss(tmem, dal + off, dbh + off, IDESC, true);
                }
                TCGEN05_COMMIT(CTRL + 8);
            }
        }
    }
    MBARRIER_WAIT_PARITY(CTRL + 8, (T - 1) & 1);
    TCGEN05_FENCE_AFTER();
    __syncthreads();

    int sub = wid & 3, grp = wid >> 2;
    float* tb = (float*)(tp + wid * 4224);
    #pragma unroll
    for (int c0 = 0; c0 < 128; c0 += 32) {
        int cbase = grp * 128 + c0;
        uint32_t d[32];
        TCGEN05_LD_X32(d, tmem + cbase);
        TCGEN05_WAIT_LD();
        #pragma unroll
        for (int j = 0; j < 32; j++) tb[lid * 33 + j] = __uint_as_float(d[j]);
        __syncwarp();
        #pragma unroll
        for (int j = 0; j < 32; j++) {
            int grow = brow + sub * 32 + j;
            int gcol = bcol + cbase + lid;
            float v = fmaxf(tb[j * 33 + lid] + bias[gcol], 0.0f);   // ReLU
            __nv_bfloat16 h = __float2bfloat16(v);
            Ch[(size_t)grow * N + gcol] = h;
            Cl[(size_t)grow * N + gcol] = __float2bfloat16(v - __bfloat162float(h));
        }
        __syncwarp();
    }
    __syncthreads();
    if (wid == 0) TCGEN05_DEALLOC(tmem, 256);
#else
    int tid = threadIdx.x;
    int brow = blockIdx.y * 128, bcol = blockIdx.x * 256;
    for (int e = tid; e < 128 * 256; e += 256) {
        int r = e >> 8, c = e & 255;
        int grow = brow + r, gcol = bcol + c;
        float acc = 0.0f;
        for (int kk = 0; kk < K; kk++) {
            float a = __bfloat162float(Ah[(size_t)grow * K + kk]) +
                      __bfloat162float(Al[(size_t)grow * K + kk]);
            float b = __bfloat162float(Bh[(size_t)gcol * K + kk]) +
                      __bfloat162float(Bl[(size_t)gcol * K + kk]);
            acc = fmaf(a, b, acc);
        }
        float v = fmaxf(acc + bias[gcol], 0.0f);
        __nv_bfloat16 h = __float2bfloat16(v);
        Ch[(size_t)grow * N + gcol] = h;
        Cl[(size_t)grow * N + gcol] = __float2bfloat16(v - __bfloat162float(h));
    }
#endif
}

// ---------------- tensor-core causal attention (batched PV+QK commit) --------
#define AQ_OFF   0
#define AK_OFF   16384
#define AV_OFF   32768
#define AP_OFF   49152
#define ALSM_OFF 81920
#define ACTRL    82944
#define ATTN_SMEM_BYTES (1024 + 82944 + 64)

__global__ __launch_bounds__(256)
void tc_attn_kernel(const __nv_bfloat16* __restrict__ qkv,
                    const __nv_bfloat16* __restrict__ vT,
                    __nv_bfloat16* __restrict__ oh,
                    __nv_bfloat16* __restrict__ ol) {
#if HAS_TCGEN05
    extern __shared__ char dsm[];
    uint32_t sbase = smem_u32(dsm);
    uint32_t tile  = (sbase + 1023u) & ~1023u;
    char* tp = dsm + (tile - sbase);
    float* lsm = (float*)(tp + ALSM_OFF);

    int qt = gridDim.x - 1 - blockIdx.x;   // longest tiles first
    int h = blockIdx.y, b = blockIdx.z;
    int tid = threadIdx.x, wid = tid >> 5, lid = tid & 31;
    int sp = wid & 3, half = wid >> 2;
    int r_local = sp * 32 + lid;
    int q_global = qt * 128 + r_local;

    const float SCALE_L2E = 0.125f * 1.4426950408889634f;
    size_t rowbase = (size_t)b * SEQ * QSTRIDE + (size_t)h * HDIM;
    const __nv_bfloat16* vTh = vT + ((size_t)(b * NHEADS + h) * HDIM) * SEQ;

    if (wid == 0) { TCGEN05_ALLOC(tile + ACTRL, 256); TCGEN05_RELINQUISH(); }
    if (tid == 0) MBARRIER_INIT(tile + ACTRL + 8, 1);
    __syncthreads();
    uint32_t tmem;
    asm volatile("ld.shared.b32 %0, [%1];" : "=r"(tmem) : "r"(tile + ACTRL));
    const uint32_t S_T = tmem;
    const uint32_t O_T = tmem + 128;
    const uint32_t MBAR = tile + ACTRL + 8;

    const uint32_t IDESC_QK = (1u << 4) | (1u << 7) | (1u << 10) | (16u << 17) | (8u << 24);
    const uint32_t IDESC_PV = (1u << 4) | (1u << 7) | (1u << 10) | (8u  << 17) | (8u << 24);
    const uint64_t dQ = make_desc_sw128(tile + AQ_OFF);
    const uint64_t dK = make_desc_sw128(tile + AK_OFF);
    const uint64_t dP = make_desc_sw128(tile + AP_OFF);
    const uint64_t dV = make_desc_sw128(tile + AV_OFF);

    uint32_t swo[4]; int rr[4], ce[4];
    uint32_t vsw[4]; size_t vgo[4];
    #pragma unroll
    for (int j = 0; j < 4; j++) {
        int cid = tid + 256 * j;
        rr[j] = cid >> 3;
        int cb = (cid & 7) << 4;
        swo[j] = sw128((uint32_t)(rr[j] * 128 + cb));
        ce[j] = cb >> 1;
        int d = cid >> 4;
        int s16 = cid & 15;
        vsw[j] = sw128((uint32_t)(((d >> 3) + ((s16 >> 3) << 3)) * 1024 +
                                  (d & 7) * 128 + (s16 & 7) * 16));
        vgo[j] = (size_t)d * SEQ + s16 * 8;
    }

    // load Q tile + stage K(0)
    {
        uint4 rk0[4];
        #pragma unroll
        for (int j = 0; j < 4; j++)
            rk0[j] = *(const uint4*)(qkv + DMODEL + rowbase +
                                     (size_t)(rr[j]) * QSTRIDE + ce[j]);
        #pragma unroll
        for (int j = 0; j < 4; j++) {
            *(uint4*)(tp + AQ_OFF + swo[j]) =
                *(const uint4*)(qkv + rowbase + (size_t)(qt * 128 + rr[j]) * QSTRIDE + ce[j]);
            *(uint4*)(tp + AK_OFF + swo[j]) = rk0[j];
        }
        __syncthreads();
        if (wid == 0) {
            FENCE_PROXY_ASYNC_SHARED_CTA();
            if (elect_one()) {
                #pragma unroll
                for (int ch = 0; ch < 4; ch++)
                    mma_f16_ss(S_T, dQ + ch * 2, dK + ch * 2, IDESC_QK, ch > 0);
                TCGEN05_COMMIT(MBAR);
            }
        }
    }

    float lsum = 0.0f;
    uint4 rv[4];
    #pragma unroll
    for (int j = 0; j < 4; j++) rv[j] = *(const uint4*)(vTh + vgo[j]);

    for (int kt = 0; kt <= qt; kt++) {
        uint4 rk[4];
        if (kt < qt) {
            #pragma unroll
            for (int j = 0; j < 4; j++)
                rk[j] = *(const uint4*)(qkv + DMODEL + rowbase +
                                        (size_t)((kt + 1) * 128 + rr[j]) * QSTRIDE + ce[j]);
        }
        MBARRIER_WAIT_PARITY(MBAR, kt & 1);
        TCGEN05_FENCE_AFTER();

        if (kt < qt) {
            // full tile: no causal masking needed
            #pragma unroll
            for (int c = 0; c < 64; c += 32) {
                uint32_t s[32];
                TCGEN05_LD_X32(s, S_T + half * 64 + c);
                TCGEN05_WAIT_LD();
                uint32_t pk[16];
                #pragma unroll
                for (int j2 = 0; j2 < 16; j2++) {
                    float p0 = fast_exp2(__uint_as_float(s[2 * j2])     * SCALE_L2E);
                    float p1 = fast_exp2(__uint_as_float(s[2 * j2 + 1]) * SCALE_L2E);
                    lsum += p0 + p1;
                    __nv_bfloat162 pr = __floats2bfloat162_rn(p0, p1);
                    pk[j2] = *(uint32_t*)&pr;
                }
                uint32_t pb = (uint32_t)(((r_local >> 3) + half * 16) * 1024 +
                                         (r_local & 7) * 128 + c * 2);
                uint4* pk4 = (uint4*)pk;
                #pragma unroll
                for (int i = 0; i < 4; i++)
                    *(uint4*)(tp + AP_OFF + sw128(pb + i * 16)) = pk4[i];
            }
        } else {
            // diagonal tile: apply causal mask
            #pragma unroll
            for (int c = 0; c < 64; c += 32) {
                uint32_t s[32];
                TCGEN05_LD_X32(s, S_T + half * 64 + c);
                TCGEN05_WAIT_LD();
                uint32_t pk[16];
                #pragma unroll
                for (int j2 = 0; j2 < 16; j2++) {
                    int col = kt * 128 + half * 64 + c + 2 * j2;
                    float p0 = fast_exp2(__uint_as_float(s[2 * j2])     * SCALE_L2E);
                    float p1 = fast_exp2(__uint_as_float(s[2 * j2 + 1]) * SCALE_L2E);
                    p0 = (col     <= q_global) ? p0 : 0.0f;
                    p1 = (col + 1 <= q_global) ? p1 : 0.0f;
                    lsum += p0 + p1;
                    __nv_bfloat162 pr = __floats2bfloat162_rn(p0, p1);
                    pk[j2] = *(uint32_t*)&pr;
                }
                uint32_t pb = (uint32_t)(((r_local >> 3) + half * 16) * 1024 +
                                         (r_local & 7) * 128 + c * 2);
                uint4* pk4 = (uint4*)pk;
                #pragma unroll
                for (int i = 0; i < 4; i++)
                    *(uint4*)(tp + AP_OFF + sw128(pb + i * 16)) = pk4[i];
            }
        }
        #pragma unroll
        for (int j = 0; j < 4; j++) *(uint4*)(tp + AV_OFF + vsw[j]) = rv[j];
        if (kt < qt) {
            #pragma unroll
            for (int j = 0; j < 4; j++) *(uint4*)(tp + AK_OFF + swo[j]) = rk[j];
        }
        __syncthreads();

        if (wid == 0) {
            FENCE_PROXY_ASYNC_SHARED_CTA();
            if (elect_one()) {
                #pragma unroll
                for (int ch = 0; ch < 8; ch++) {
                    uint64_t offP = (uint64_t)((ch & 3) * 2 + (ch >> 2) * 1024);
                    uint64_t offV = (uint64_t)((ch & 3) * 2 + (ch >> 2) * 512);
                    mma_f16_ss(O_T, dP + offP, dV + offV, IDESC_PV, !(kt == 0 && ch == 0));
                }
                if (kt < qt) {
                    #pragma unroll
                    for (int ch = 0; ch < 4; ch++)
                        mma_f16_ss(S_T, dQ + ch * 2, dK + ch * 2, IDESC_QK, ch > 0);
                }
                TCGEN05_COMMIT(MBAR);
            }
        }
        if (kt < qt) {
            #pragma unroll
            for (int j = 0; j < 4; j++)
                rv[j] = *(const uint4*)(vTh + vgo[j] + (kt + 1) * 128);
        }
    }
    MBARRIER_WAIT_PARITY(MBAR, (qt + 1) & 1);
    TCGEN05_FENCE_AFTER();

    lsm[half * 128 + r_local] = lsum;
    __syncthreads();
    float l = lsm[r_local] + lsm[128 + r_local];
    float inv_l = 1.0f / l;
    {
        uint32_t o[32];
        TCGEN05_LD_X32(o, O_T + half * 32);
        TCGEN05_WAIT_LD();
        uint4 hv[4], lv[4];
        __nv_bfloat16* hb = (__nv_bfloat16*)hv;
        __nv_bfloat16* lb = (__nv_bfloat16*)lv;
        #pragma unroll
        for (int j = 0; j < 32; j++) {
            float val = __uint_as_float(o[j]) * inv_l;
            __nv_bfloat16 h16 = __float2bfloat16(val);
            hb[j] = h16;
            lb[j] = __float2bfloat16(val - __bfloat162float(h16));
        }
        size_t gbase = (size_t)b * SEQ * DMODEL + (size_t)h * HDIM +
                       (size_t)(qt * 128 + r_local) * DMODEL + half * 32;
        uint4* oph = (uint4*)(oh + gbase);
        uint4* opl = (uint4*)(ol + gbase);
        #pragma unroll
        for (int i = 0; i < 4; i++) { oph[i] = hv[i]; opl[i] = lv[i]; }
    }
    __syncthreads();
    if (wid == 0) TCGEN05_DEALLOC(tmem, 256);
#else
    // compile-only fallback
    int qt = gridDim.x - 1 - blockIdx.x, h = blockIdx.y, b = blockIdx.z;
    int tid = threadIdx.x;
    size_t rowbase = (size_t)b * SEQ * QSTRIDE + (size_t)h * HDIM;
    size_t obase   = (size_t)b * SEQ * DMODEL + (size_t)h * HDIM;
    const __nv_bfloat16* vTh = vT + ((size_t)(b * NHEADS + h) * HDIM) * SEQ;
    for (int r = tid; r < 128; r += blockDim.x) {
        int qg = qt * 128 + r;
        float o[HDIM]; float l = 0.0f;
        for (int d = 0; d < HDIM; d++) o[d] = 0.0f;
        for (int kk = 0; kk <= qg; kk++) {
            float s = 0.0f;
            for (int d = 0; d < HDIM; d++)
                s += __bfloat162float(qkv[rowbase + (size_t)qg * QSTRIDE + d]) *
                     __bfloat162float(qkv[rowbase + (size_t)kk * QSTRIDE + DMODEL + d]);
            float p = fast_exp2(s * 0.125f * 1.4426950408889634f);
            l += p;
            for (int d = 0; d < HDIM; d++)
                o[d] += p * __bfloat162float(vTh[(size_t)d * SEQ + kk]);
        }
        for (int d = 0; d < HDIM; d++) {
            float val = o[d] / l;
            __nv_bfloat16 h16 = __float2bfloat16(val);
            oh[obase + (size_t)qg * DMODEL + d] = h16;
            ol[obase + (size_t)qg * DMODEL + d] = __float2bfloat16(val - __bfloat162float(h16));
        }
    }
#endif
}

// ---------------- launcher ----------------
extern "C" void kernel_launch(void* const* d_in, const int* in_sizes, int n_in,
                              void* d_out, int out_size) {
    (void)in_sizes; (void)n_in; (void)out_size;
    const float* x     = (const float*)d_in[0];
    const float* wq    = (const float*)d_in[1];
    const float* bq    = (const float*)d_in[2];
    const float* wk    = (const float*)d_in[3];
    const float* bk    = (const float*)d_in[4];
    const float* wv    = (const float*)d_in[5];
    const float* bv    = (const float*)d_in[6];
    const float* wo    = (const float*)d_in[7];
    const float* bo    = (const float*)d_in[8];
    const float* w1    = (const float*)d_in[9];
    const float* b1    = (const float*)d_in[10];
    const float* w2    = (const float*)d_in[11];
    const float* b2    = (const float*)d_in[12];
    const float* ln1_g = (const float*)d_in[13];
    const float* ln1_b = (const float*)d_in[14];
    const float* ln2_g = (const float*)d_in[15];
    const float* ln2_b = (const float*)d_in[16];
    float* out = (float*)d_out;

    float *x1;
    cudaGetSymbolAddress((void**)&x1, g_x1);
    __nv_bfloat16 *qkv, *vT, *wqkvth, *wscr;
    cudaGetSymbolAddress((void**)&qkv, g_qkv);
    cudaGetSymbolAddress((void**)&vT, g_vT);
    cudaGetSymbolAddress((void**)&wqkvth, g_wqkvth);
    cudaGetSymbolAddress((void**)&wscr, g_wscr);
    __nv_bfloat16 *ln1h, *ln1l, *atth, *attl, *hh, *hl, *f1h, *f1l;
    cudaGetSymbolAddress((void**)&ln1h, g_ln1h); cudaGetSymbolAddress((void**)&ln1l, g_ln1l);
    cudaGetSymbolAddress((void**)&atth, g_atth); cudaGetSymbolAddress((void**)&attl, g_attl);
    cudaGetSymbolAddress((void**)&hh,   g_hh);   cudaGetSymbolAddress((void**)&hl,   g_hl);
    cudaGetSymbolAddress((void**)&f1h,  g_f1h);  cudaGetSymbolAddress((void**)&f1l,  g_f1l);
    __nv_bfloat16 *woth, *wotl, *w1th, *w1tl, *w2th, *w2tl;
    cudaGetSymbolAddress((void**)&woth, g_woth); cudaGetSymbolAddress((void**)&wotl, g_wotl);
    cudaGetSymbolAddress((void**)&w1th, g_w1th); cudaGetSymbolAddress((void**)&w1tl, g_w1tl);
    cudaGetSymbolAddress((void**)&w2th, g_w2th); cudaGetSymbolAddress((void**)&w2tl, g_w2tl);

    cudaFuncSetAttribute(tc_gemm1_kernel,
                         cudaFuncAttributeMaxDynamicSharedMemorySize, GEMM1_SMEM_BYTES);
    cudaFuncSetAttribute(tc_gemm_kernel<false, true, 0>,
                         cudaFuncAttributeMaxDynamicSharedMemorySize, GEMM_SMEM_BYTES);
    cudaFuncSetAttribute(tc_gemm256_kernel,
                         cudaFuncAttributeMaxDynamicSharedMemorySize, GEMM256_SMEM_BYTES);
    cudaFuncSetAttribute(tc_attn_kernel,
                         cudaFuncAttributeMaxDynamicSharedMemorySize, ATTN_SMEM_BYTES);

    dim3 grid_d(DMODEL / 128, MROWS / 128);       // (6, 32)
    dim3 grid_qkv(QSTRIDE / 128, MROWS / 128);    // (18, 32)
    dim3 grid_ff1(DFF / 256, MROWS / 128);        // (12, 32)
    dim3 agrid(SEQ / 128, NHEADS, BATCH);

    layernorm_split_kernel<<<MROWS, 256>>>(x, ln1_g, ln1_b, ln1h, ln1l);
    transpose4_split_kernel<<<dim3(DMODEL / 128, DMODEL / 32, 4), 256>>>(
        wq, wk, wv, wo,
        wqkvth,                       wscr,
        wqkvth + DMODEL * DMODEL,     wscr + DMODEL * DMODEL,
        wqkvth + 2 * DMODEL * DMODEL, wscr + 2 * DMODEL * DMODEL,
        woth, wotl);
    tc_gemm1_kernel<<<grid_qkv, 256, GEMM1_SMEM_BYTES>>>(
        ln1h, wqkvth, bq, bk, bv, qkv, vT, MROWS, QSTRIDE, DMODEL);
    tc_attn_kernel<<<agrid, 256, ATTN_SMEM_BYTES>>>(qkv, vT, atth, attl);
    // merged w1 + w2 transpose (one launch)
    transpose2_split_kernel<<<dim3(24, 24, 2), 256>>>(w1, w2, w1th, w1tl, w2th, w2tl);
    tc_gemm_kernel<false, true, 0><<<grid_d, 256, GEMM_SMEM_BYTES>>>(
        atth, attl, woth, wotl, bo, x, x1, nullptr, nullptr, MROWS, DMODEL, DMODEL);
    layernorm_split_kernel<<<MROWS, 256>>>(x1, ln2_g, ln2_b, hh, hl);
    tc_gemm256_kernel<<<grid_ff1, 256, GEMM256_SMEM_BYTES>>>(
        hh, hl, w1th, w1tl, b1, f1h, f1l, MROWS, DFF, DMODEL);
    tc_gemm_kernel<false, true, 0><<<grid_d, 256, GEMM_SMEM_BYTES>>>(
        f1h, f1l, w2th, w2tl, b2, x1, out, nullptr, nullptr, MROWS, DMODEL, DFF);
}

// round 16
// speedup vs baseline: 1.0448x; 1.0139x over previous
#include <cuda_runtime.h>
#include <cuda_bf16.h>
#include <math.h>
#include <stdint.h>

// ---------------- problem constants ----------------
#define BATCH   2
#define SEQ     2048
#define DMODEL  768
#define NHEADS  12
#define HDIM    64
#define DFF     3072
#define MROWS   (BATCH * SEQ)        // 4096
#define LN_EPS  1e-5f
#define QSTRIDE 2304                 // fused qkv row stride

#if defined(__CUDA_ARCH__) && (defined(__CUDA_ARCH_FEAT_SM103_ALL) || defined(__CUDA_ARCH_FEAT_SM100_ALL) || defined(__CUDA_ARCH_FEAT_SM101_ALL))
#define HAS_TCGEN05 1
#else
#define HAS_TCGEN05 0
#endif

// ---------------- inline PTX helpers (sm_103a) ----------------
__device__ __forceinline__ uint32_t smem_u32(const void* p) {
    uint32_t a;
    asm("{ .reg .u64 t; cvta.to.shared.u64 t, %1; cvt.u32.u64 %0, t; }" : "=r"(a) : "l"(p));
    return a;
}

#if HAS_TCGEN05
__device__ __forceinline__ uint32_t elect_one() {
    uint32_t pred;
    asm volatile("{\n\t.reg .pred p;\n\telect.sync _|p, 0xFFFFFFFF;\n\tselp.b32 %0, 1, 0, p;\n\t}" : "=r"(pred));
    return pred;
}
#define MBARRIER_INIT(addr, cnt) \
    asm volatile("mbarrier.init.shared.b64 [%0], %1;" :: "r"((uint32_t)(addr)), "r"((uint32_t)(cnt)) : "memory")
#define MBARRIER_WAIT_PARITY(addr, par) do { \
    uint32_t _m = (uint32_t)(addr), _p = (uint32_t)(par), _d; \
    asm volatile("{\n\t.reg .pred p;\n\tmbarrier.try_wait.parity.acquire.cta.shared::cta.b64 p, [%1], %2;\n\tselp.b32 %0, 1, 0, p;\n\t}" \
        : "=r"(_d) : "r"(_m), "r"(_p) : "memory"); \
    if (!_d) { \
        asm volatile("{\n\t.reg .pred P1;\n\tWL_%=:\n\tmbarrier.try_wait.parity.acquire.cta.shared::cta.b64 P1, [%0], %1, 0x989680;\n\t@P1 bra.uni WD_%=;\n\tbra.uni WL_%=;\n\tWD_%=:\n\t}" \
            :: "r"(_m), "r"(_p) : "memory"); \
    } \
} while (0)
#define TCGEN05_ALLOC(saddr, ncols) \
    asm volatile("tcgen05.alloc.cta_group::1.sync.aligned.shared::cta.b32 [%0], %1;" :: "r"((uint32_t)(saddr)), "r"((uint32_t)(ncols)) : "memory")
#define TCGEN05_DEALLOC(tmem, ncols) \
    asm volatile("tcgen05.dealloc.cta_group::1.sync.aligned.b32 %0, %1;" :: "r"(tmem), "r"((uint32_t)(ncols)))
#define TCGEN05_RELINQUISH() \
    asm volatile("tcgen05.relinquish_alloc_permit.cta_group::1.sync.aligned;")
#define TCGEN05_COMMIT(mbar) \
    asm volatile("tcgen05.commit.cta_group::1.mbarrier::arrive::one.shared::cluster.b64 [%0];" :: "r"((uint32_t)(mbar)) : "memory")
#define TCGEN05_WAIT_LD() asm volatile("tcgen05.wait::ld.sync.aligned;" ::: "memory")
#define TCGEN05_FENCE_AFTER() asm volatile("tcgen05.fence::after_thread_sync;" ::: "memory")
#define FENCE_PROXY_ASYNC_SHARED_CTA() asm volatile("fence.proxy.async.shared::cta;" ::: "memory")
#define TCGEN05_LD_X32(r, tmem_addr) \
    asm volatile( \
        "tcgen05.ld.sync.aligned.32x32b.x32.b32 " \
        "{%0, %1, %2, %3, %4, %5, %6, %7, " \
        " %8, %9, %10, %11, %12, %13, %14, %15, " \
        " %16, %17, %18, %19, %20, %21, %22, %23, " \
        " %24, %25, %26, %27, %28, %29, %30, %31}, [%32];" \
        : "=r"((r)[0]),  "=r"((r)[1]),  "=r"((r)[2]),  "=r"((r)[3]), \
          "=r"((r)[4]),  "=r"((r)[5]),  "=r"((r)[6]),  "=r"((r)[7]), \
          "=r"((r)[8]),  "=r"((r)[9]),  "=r"((r)[10]), "=r"((r)[11]), \
          "=r"((r)[12]), "=r"((r)[13]), "=r"((r)[14]), "=r"((r)[15]), \
          "=r"((r)[16]), "=r"((r)[17]), "=r"((r)[18]), "=r"((r)[19]), \
          "=r"((r)[20]), "=r"((r)[21]), "=r"((r)[22]), "=r"((r)[23]), \
          "=r"((r)[24]), "=r"((r)[25]), "=r"((r)[26]), "=r"((r)[27]), \
          "=r"((r)[28]), "=r"((r)[29]), "=r"((r)[30]), "=r"((r)[31]) \
        : "r"(tmem_addr))

// K-major SW128 descriptor (LBO=1, SBO=64)
static __device__ __forceinline__ uint64_t make_desc_sw128(uint32_t addr) {
    const uint64_t base =
        (uint64_t(2) << 61) | (uint64_t(1) << 46) | (uint64_t(64) << 32) | (uint64_t(1) << 16);
    return base | ((uint64_t)(addr >> 4) & 0x3FFF);
}

__device__ __forceinline__ void mma_f16_ss(uint32_t d_tmem, uint64_t a_desc, uint64_t b_desc,
                                           uint32_t idesc, bool enable_d) {
    uint32_t en = enable_d ? 1u : 0u;
    asm volatile(
        "{\n\t.reg .pred p;\n\t"
        "setp.ne.u32 p, %5, 0;\n\t"
        "tcgen05.mma.cta_group::1.kind::f16 [%0], %1, %2, %3, {%4, %4, %4, %4}, p;\n\t}"
        :: "r"(d_tmem), "l"(a_desc), "l"(b_desc), "r"(idesc), "r"(0u), "r"(en)
        : "memory");
}
#endif // HAS_TCGEN05

__device__ __forceinline__ uint32_t sw128(uint32_t off) { return off ^ ((off >> 3) & 0x70); }

// fast exp2 on the FMA pipe (no MUFU). |x| < ~30, err ~2e-6 relative.
__device__ __forceinline__ float fast_exp2(float x) {
    float t = x + 12582912.0f;
    int   e = __float_as_int(t);
    float r = t - 12582912.0f;
    float f = x - r;
    float p = 1.3333558146e-3f;
    p = fmaf(p, f, 9.6181298421e-3f);
    p = fmaf(p, f, 5.5504108664e-2f);
    p = fmaf(p, f, 2.4022650696e-1f);
    p = fmaf(p, f, 6.9314718056e-1f);
    p = fmaf(p, f, 1.0f);
    return __int_as_float(__float_as_int(p) + (e << 23));
}

// ---------------- scratch (device globals; no allocs allowed) ----------------
__device__ float g_x1 [MROWS * DMODEL];

__device__ __nv_bfloat16 g_qkv[MROWS * QSTRIDE];                 // q,k used; v region unused
__device__ __nv_bfloat16 g_vT [BATCH * NHEADS * HDIM * SEQ];     // v transposed [b,h,d,s]

__device__ __nv_bfloat16 g_ln1h[MROWS * DMODEL], g_ln1l[MROWS * DMODEL];
__device__ __nv_bfloat16 g_atth[MROWS * DMODEL], g_attl[MROWS * DMODEL];
__device__ __nv_bfloat16 g_hh  [MROWS * DMODEL], g_hl  [MROWS * DMODEL];
__device__ __nv_bfloat16 g_f1h [MROWS * DFF],    g_f1l [MROWS * DFF];

__device__ __nv_bfloat16 g_wqkvth[QSTRIDE * DMODEL];   // fused Wq|Wk|Wv transposed (hi)
__device__ __nv_bfloat16 g_wscr  [QSTRIDE * DMODEL];   // lo scratch (unused by 1-term gemm)
__device__ __nv_bfloat16 g_woth[DMODEL * DMODEL], g_wotl[DMODEL * DMODEL];
__device__ __nv_bfloat16 g_w1th[DFF * DMODEL],    g_w1tl[DFF * DMODEL];
__device__ __nv_bfloat16 g_w2th[DMODEL * DFF],    g_w2tl[DMODEL * DFF];

// ---------------- vectorized weight transpose + fp32->bf16 hi/lo split --------
__device__ __forceinline__ void transpose_tile_body(const float* __restrict__ W,
                                                    __nv_bfloat16* __restrict__ Th,
                                                    __nv_bfloat16* __restrict__ Tl,
                                                    int K, int N, int n0, int k0) {
    __shared__ float sm[32][133];
    int t = threadIdx.x;
    int tx = t & 31, ty = t >> 5;              // 32 x 8
    #pragma unroll
    for (int i = 0; i < 4; i++) {
        int r = ty + 8 * i;
        float4 v = *(const float4*)(W + (size_t)(k0 + r) * N + n0 + tx * 4);
        sm[r][tx * 4 + 0] = v.x;
        sm[r][tx * 4 + 1] = v.y;
        sm[r][tx * 4 + 2] = v.z;
        sm[r][tx * 4 + 3] = v.w;
    }
    __syncthreads();
    int kb = (t & 3) * 8;                      // k chunk base (0,8,16,24)
    int nrow = t >> 2;                         // 0..63
    #pragma unroll
    for (int pass = 0; pass < 2; pass++) {
        int n = nrow + 64 * pass;
        __nv_bfloat16 hbuf[8], lbuf[8];
        #pragma unroll
        for (int j = 0; j < 8; j++) {
            float v = sm[kb + j][n];
            __nv_bfloat16 h = __float2bfloat16(v);
            hbuf[j] = h;
            lbuf[j] = __float2bfloat16(v - __bfloat162float(h));
        }
        size_t o = (size_t)(n0 + n) * K + k0 + kb;
        *(uint4*)(Th + o) = *(uint4*)hbuf;
        *(uint4*)(Tl + o) = *(uint4*)lbuf;
    }
}

// batched transpose of the four 768x768 weights in one launch (z = which matrix)
__global__ __launch_bounds__(256)
void transpose4_split_kernel(const float* __restrict__ W0, const float* __restrict__ W1,
                             const float* __restrict__ W2, const float* __restrict__ W3,
                             __nv_bfloat16* __restrict__ T0h, __nv_bfloat16* __restrict__ T0l,
                             __nv_bfloat16* __restrict__ T1h, __nv_bfloat16* __restrict__ T1l,
                             __nv_bfloat16* __restrict__ T2h, __nv_bfloat16* __restrict__ T2l,
                             __nv_bfloat16* __restrict__ T3h, __nv_bfloat16* __restrict__ T3l) {
    int z = blockIdx.z;
    const float* W = (z == 0) ? W0 : (z == 1) ? W1 : (z == 2) ? W2 : W3;
    __nv_bfloat16* Th = (z == 0) ? T0h : (z == 1) ? T1h : (z == 2) ? T2h : T3h;
    __nv_bfloat16* Tl = (z == 0) ? T0l : (z == 1) ? T1l : (z == 2) ? T2l : T3l;
    transpose_tile_body(W, Th, Tl, DMODEL, DMODEL, blockIdx.x * 128, blockIdx.y * 32);
}

// merged transpose of w1 [768,3072] and w2 [3072,768] in one launch.
__global__ __launch_bounds__(256)
void transpose2_split_kernel(const float* __restrict__ W1f, const float* __restrict__ W2f,
                             __nv_bfloat16* __restrict__ T1h, __nv_bfloat16* __restrict__ T1l,
                             __nv_bfloat16* __restrict__ T2h, __nv_bfloat16* __restrict__ T2l) {
    if (blockIdx.z == 0) {
        transpose_tile_body(W1f, T1h, T1l, DMODEL, DFF,
                            blockIdx.x * 128, blockIdx.y * 32);
    } else {
        int idx = blockIdx.y * 24 + blockIdx.x;      // 0..575
        int n0 = (idx % 6) * 128;
        int k0 = (idx / 6) * 32;
        transpose_tile_body(W2f, T2h, T2l, DFF, DMODEL, n0, k0);
    }
}

// ---------------- block reduction ----------------
__device__ __forceinline__ float block_sum(float v) {
    __shared__ float sm[32];
    __syncthreads();
    int lane = threadIdx.x & 31;
    int wid  = threadIdx.x >> 5;
    #pragma unroll
    for (int o = 16; o > 0; o >>= 1) v += __shfl_down_sync(0xffffffffu, v, o);
    if (lane == 0) sm[wid] = v;
    __syncthreads();
    if (wid == 0) {
        int nw = (blockDim.x + 31) >> 5;
        v = (lane < nw) ? sm[lane] : 0.0f;
        #pragma unroll
        for (int o = 16; o > 0; o >>= 1) v += __shfl_down_sync(0xffffffffu, v, o);
        if (lane == 0) sm[0] = v;
    }
    __syncthreads();
    return sm[0];
}

// ---------------- LayerNorm -> bf16 hi/lo planes ----------------
__global__ __launch_bounds__(256)
void layernorm_split_kernel(const float* __restrict__ x,
                            const float* __restrict__ g,
                            const float* __restrict__ b,
                            __nv_bfloat16* __restrict__ oh,
                            __nv_bfloat16* __restrict__ ol) {
    int row = blockIdx.x;
    const float* xr = x + (size_t)row * DMODEL;
    int t = threadIdx.x;

    float v0 = xr[t], v1 = xr[t + 256], v2 = xr[t + 512];
    float mu = block_sum(v0 + v1 + v2) * (1.0f / DMODEL);
    float d0 = v0 - mu, d1 = v1 - mu, d2 = v2 - mu;
    float var = block_sum(d0 * d0 + d1 * d1 + d2 * d2) * (1.0f / DMODEL);
    float rs = rsqrtf(var + LN_EPS);

    size_t base = (size_t)row * DMODEL;
    #pragma unroll
    for (int i = 0; i < 3; i++) {
        int c = t + 256 * i;
        float d = (i == 0) ? d0 : (i == 1 ? d1 : d2);
        float v = d * rs * g[c] + b[c];
        __nv_bfloat16 h = __float2bfloat16(v);
        oh[base + c] = h;
        ol[base + c] = __float2bfloat16(v - __bfloat162float(h));
    }
}

// ---------------- fused QKV: 1-term bf16 tcgen05 GEMM, pipelined ----------------
#define G1_CTRL  33792
#define GEMM1_SMEM_BYTES (1024 + 33792 + 64)

__global__ __launch_bounds__(256)
void tc_gemm1_kernel(const __nv_bfloat16* __restrict__ Ah, const __nv_bfloat16* __restrict__ Bh,
                     const float* __restrict__ bq, const float* __restrict__ bk,
                     const float* __restrict__ bv, __nv_bfloat16* __restrict__ Cqk,
                     __nv_bfloat16* __restrict__ CvT, int M, int N, int K) {
#if HAS_TCGEN05
    extern __shared__ char dsm[];
    uint32_t sbase = smem_u32(dsm);
    uint32_t tile  = (sbase + 1023u) & ~1023u;
    char* tp = dsm + (tile - sbase);
    const int A_HI = 0, B_HI = 16384;
    const uint32_t CTRL = tile + G1_CTRL;

    int tid = threadIdx.x, wid = tid >> 5, lid = tid & 31;
    int brow = blockIdx.y * 128, bcol = blockIdx.x * 128;
    const float* bsel = (bcol < DMODEL) ? bq : (bcol < 2 * DMODEL ? bk : bv);
    int boff = (bcol < DMODEL) ? 0 : (bcol < 2 * DMODEL ? DMODEL : 2 * DMODEL);

    if (wid == 0) { TCGEN05_ALLOC(CTRL, 128); TCGEN05_RELINQUISH(); }
    if (tid == 0) MBARRIER_INIT(CTRL + 8, 1);
    __syncthreads();
    uint32_t tmem;
    asm volatile("ld.shared.b32 %0, [%1];" : "=r"(tmem) : "r"(CTRL));

    const uint32_t IDESC = (1u << 4) | (1u << 7) | (1u << 10) | (16u << 17) | (8u << 24);
    const uint64_t dah = make_desc_sw128(tile + A_HI);
    const uint64_t dbh = make_desc_sw128(tile + B_HI);

    uint32_t swo[4]; int eoff[4];
    #pragma unroll
    for (int j = 0; j < 4; j++) {
        int cid = tid + 256 * j;
        int r = cid >> 3, cb = (cid & 7) << 4;
        swo[j] = sw128((uint32_t)(r * 128 + cb));
        eoff[j] = r * K + (cb >> 1);
    }
    const __nv_bfloat16* Abase = Ah + (size_t)brow * K;
    const __nv_bfloat16* Bbase = Bh + (size_t)bcol * K;

    int T = K >> 6;
    uint4 ra[4], rb[4];
    #pragma unroll
    for (int j = 0; j < 4; j++) {
        ra[j] = *(const uint4*)(Abase + eoff[j]);
        rb[j] = *(const uint4*)(Bbase + eoff[j]);
    }
    for (int it = 0; it < T; ++it) {
        if (it > 0) MBARRIER_WAIT_PARITY(CTRL + 8, (it - 1) & 1);
        __syncthreads();
        #pragma unroll
        for (int j = 0; j < 4; j++) {
            *(uint4*)(tp + A_HI + swo[j]) = ra[j];
            *(uint4*)(tp + B_HI + swo[j]) = rb[j];
        }
        __syncthreads();
        if (wid == 0) {
            FENCE_PROXY_ASYNC_SHARED_CTA();
            if (elect_one()) {
                #pragma unroll
                for (int ch = 0; ch < 4; ch++)
                    mma_f16_ss(tmem, dah + ch * 2, dbh + ch * 2, IDESC, !(it == 0 && ch == 0));
                TCGEN05_COMMIT(CTRL + 8);
            }
        }
        if (it + 1 < T) {
            int k0 = (it + 1) << 6;
            #pragma unroll
            for (int j = 0; j < 4; j++) {
                ra[j] = *(const uint4*)(Abase + eoff[j] + k0);
                rb[j] = *(const uint4*)(Bbase + eoff[j] + k0);
            }
        }
    }
    MBARRIER_WAIT_PARITY(CTRL + 8, (T - 1) & 1);
    TCGEN05_FENCE_AFTER();
    __syncthreads();

    int sub = wid & 3, grp = wid >> 2;
    if (bcol < 2 * DMODEL) {
        float* tb = (float*)(tp + wid * 4224);
        #pragma unroll
        for (int c0 = 0; c0 < 64; c0 += 32) {
            int cbase = grp * 64 + c0;
            uint32_t d[32];
            TCGEN05_LD_X32(d, tmem + cbase);
            TCGEN05_WAIT_LD();
            #pragma unroll
            for (int j = 0; j < 32; j++) tb[lid * 33 + j] = __uint_as_float(d[j]);
            __syncwarp();
            #pragma unroll
            for (int j = 0; j < 32; j++) {
                int grow = brow + sub * 32 + j;
                int gcol = bcol + cbase + lid;
                Cqk[(size_t)grow * N + gcol] =
                    __float2bfloat16(tb[j * 33 + lid] + bsel[gcol - boff]);
            }
            __syncwarp();
        }
    } else {
        int grow = brow + sub * 32 + lid;
        int bb = grow >> 11, s = grow & (SEQ - 1);
        #pragma unroll
        for (int c0 = 0; c0 < 64; c0 += 32) {
            int cbase = grp * 64 + c0;
            uint32_t d[32];
            TCGEN05_LD_X32(d, tmem + cbase);
            TCGEN05_WAIT_LD();
            #pragma unroll
            for (int j = 0; j < 32; j++) {
                int gcol = bcol + cbase + j;
                int vcol = gcol - 2 * DMODEL;
                int hh2 = vcol >> 6, dl = vcol & 63;
                CvT[((size_t)(bb * NHEADS + hh2) * HDIM + dl) * SEQ + s] =
                    __float2bfloat16(__uint_as_float(d[j]) + bsel[gcol - boff]);
            }
        }
    }
    __syncthreads();
    if (wid == 0) TCGEN05_DEALLOC(tmem, 128);
#else
    int tid = threadIdx.x;
    int brow = blockIdx.y * 128, bcol = blockIdx.x * 128;
    for (int e = tid; e < 128 * 128; e += 256) {
        int r = e >> 7, c = e & 127;
        int grow = brow + r, gcol = bcol + c;
        float acc = 0.0f;
        for (int kk = 0; kk < K; kk++)
            acc = fmaf(__bfloat162float(Ah[(size_t)grow * K + kk]),
                       __bfloat162float(Bh[(size_t)gcol * K + kk]), acc);
        const float* bsel = (gcol < DMODEL) ? bq : (gcol < 2 * DMODEL ? bk : bv);
        int boff = (gcol < DMODEL) ? 0 : (gcol < 2 * DMODEL ? DMODEL : 2 * DMODEL);
        float v = acc + bsel[gcol - boff];
        if (gcol < 2 * DMODEL) {
            Cqk[(size_t)grow * N + gcol] = __float2bfloat16(v);
        } else {
            int vcol = gcol - 2 * DMODEL;
            int bb = grow >> 11, s = grow & (SEQ - 1);
            CvT[((size_t)(bb * NHEADS + (vcol >> 6)) * HDIM + (vcol & 63)) * SEQ + s] =
                __float2bfloat16(v);
        }
    }
#endif
}

// ---------------- 3-term split tcgen05 GEMM, 128x128 (R13 form) --------------
#define GEMM_SMEM_BYTES (1024 + 65536 + 64)

template <bool RELU, bool ADDRES, int OUT>
__global__ __launch_bounds__(256)
void tc_gemm_kernel(const __nv_bfloat16* __restrict__ Ah, const __nv_bfloat16* __restrict__ Al,
                    const __nv_bfloat16* __restrict__ Bh, const __nv_bfloat16* __restrict__ Bl,
                    const float* __restrict__ bias, const float* __restrict__ res,
                    float* __restrict__ Cf,
                    __nv_bfloat16* __restrict__ Ch, __nv_bfloat16* __restrict__ Cl,
                    int M, int N, int K) {
#if HAS_TCGEN05
    extern __shared__ char dsm[];
    uint32_t sbase = smem_u32(dsm);
    uint32_t tile  = (sbase + 1023u) & ~1023u;
    char* tp = dsm + (tile - sbase);

    const int A_HI = 0, A_LO = 16384, B_HI = 32768, B_LO = 49152;
    const uint32_t CTRL = tile + 65536;

    int tid = threadIdx.x, wid = tid >> 5, lid = tid & 31;
    int brow = blockIdx.y * 128, bcol = blockIdx.x * 128;

    if (wid == 0) { TCGEN05_ALLOC(CTRL, 128); TCGEN05_RELINQUISH(); }
    if (tid == 0) MBARRIER_INIT(CTRL + 8, 2);   // two commits per K-iter
    __syncthreads();
    uint32_t tmem;
    asm volatile("ld.shared.b32 %0, [%1];" : "=r"(tmem) : "r"(CTRL));

    const uint32_t IDESC = (1u << 4) | (1u << 7) | (1u << 10) | (16u << 17) | (8u << 24);
    const uint64_t dah = make_desc_sw128(tile + A_HI);
    const uint64_t dal = make_desc_sw128(tile + A_LO);
    const uint64_t dbh = make_desc_sw128(tile + B_HI);
    const uint64_t dbl = make_desc_sw128(tile + B_LO);

    uint32_t swo[4]; int eoff[4];
    #pragma unroll
    for (int j = 0; j < 4; j++) {
        int cid = tid + 256 * j;
        int r = cid >> 3, cb = (cid & 7) << 4;
        swo[j] = sw128((uint32_t)(r * 128 + cb));
        eoff[j] = r * K + (cb >> 1);
    }
    const __nv_bfloat16* Ahb = Ah + (size_t)brow * K;
    const __nv_bfloat16* Alb = Al + (size_t)brow * K;
    const __nv_bfloat16* Bhb = Bh + (size_t)bcol * K;
    const __nv_bfloat16* Blb = Bl + (size_t)bcol * K;

    int T = K >> 6;
    uint4 rah[4], ral[4], rbh[4], rbl[4];
    #pragma unroll
    for (int j = 0; j < 4; j++) {
        rah[j] = *(const uint4*)(Ahb + eoff[j]);
        ral[j] = *(const uint4*)(Alb + eoff[j]);
        rbh[j] = *(const uint4*)(Bhb + eoff[j]);
        rbl[j] = *(const uint4*)(Blb + eoff[j]);
    }
    for (int it = 0; it < T; ++it) {
        if (it > 0) MBARRIER_WAIT_PARITY(CTRL + 8, (it - 1) & 1);
        __syncthreads();
        // phase A: stage hi planes, launch hi*hi MMAs
        #pragma unroll
        for (int j = 0; j < 4; j++) {
            *(uint4*)(tp + A_HI + swo[j]) = rah[j];
            *(uint4*)(tp + B_HI + swo[j]) = rbh[j];
        }
        __syncthreads();
        if (wid == 0) {
            FENCE_PROXY_ASYNC_SHARED_CTA();
            if (elect_one()) {
                #pragma unroll
                for (int ch = 0; ch < 4; ch++)
                    mma_f16_ss(tmem, dah + ch * 2, dbh + ch * 2, IDESC, !(it == 0 && ch == 0));
                TCGEN05_COMMIT(CTRL + 8);
            }
        }
        // phase B: stage lo planes + prefetch next (overlaps hi*hi MMAs)
        #pragma unroll
        for (int j = 0; j < 4; j++) {
            *(uint4*)(tp + A_LO + swo[j]) = ral[j];
            *(uint4*)(tp + B_LO + swo[j]) = rbl[j];
        }
        if (it + 1 < T) {
            int k0 = (it + 1) << 6;
            #pragma unroll
            for (int j = 0; j < 4; j++) {
                rah[j] = *(const uint4*)(Ahb + eoff[j] + k0);
                ral[j] = *(const uint4*)(Alb + eoff[j] + k0);
                rbh[j] = *(const uint4*)(Bhb + eoff[j] + k0);
                rbl[j] = *(const uint4*)(Blb + eoff[j] + k0);
            }
        }
        __syncthreads();
        if (wid == 0) {
            FENCE_PROXY_ASYNC_SHARED_CTA();
            if (elect_one()) {
                #pragma unroll
                for (int ch = 0; ch < 4; ch++) {
                    uint64_t off = (uint64_t)(ch * 2);
                    mma_f16_ss(tmem, dah + off, dbl + off, IDESC, true);
                    mma_f16_ss(tmem, dal + off, dbh + off, IDESC, true);
                }
                TCGEN05_COMMIT(CTRL + 8);
            }
        }
    }
    MBARRIER_WAIT_PARITY(CTRL + 8, (T - 1) & 1);
    TCGEN05_FENCE_AFTER();
    __syncthreads();

    int sub = wid & 3, grp = wid >> 2;
    float* tb = (float*)(tp + wid * 4224);
    #pragma unroll
    for (int c0 = 0; c0 < 64; c0 += 32) {
        int cbase = grp * 64 + c0;
        uint32_t d[32];
        TCGEN05_LD_X32(d, tmem + cbase);
        TCGEN05_WAIT_LD();
        #pragma unroll
        for (int j = 0; j < 32; j++) tb[lid * 33 + j] = __uint_as_float(d[j]);
        __syncwarp();
        #pragma unroll
        for (int j = 0; j < 32; j++) {
            int grow = brow + sub * 32 + j;
            int gcol = bcol + cbase + lid;
            float v = tb[j * 33 + lid] + bias[gcol];
            if (RELU)   v = fmaxf(v, 0.0f);
            if (ADDRES) v += res[(size_t)grow * N + gcol];
            if (OUT == 1) {
                __nv_bfloat16 h = __float2bfloat16(v);
                Ch[(size_t)grow * N + gcol] = h;
                Cl[(size_t)grow * N + gcol] = __float2bfloat16(v - __bfloat162float(h));
            } else {
                Cf[(size_t)grow * N + gcol] = v;
            }
        }
        __syncwarp();
    }
    __syncthreads();
    if (wid == 0) TCGEN05_DEALLOC(tmem, 128);
#else
    int tid = threadIdx.x;
    int brow = blockIdx.y * 128, bcol = blockIdx.x * 128;
    for (int e = tid; e < 128 * 128; e += 256) {
        int r = e >> 7, c = e & 127;
        int grow = brow + r, gcol = bcol + c;
        float acc = 0.0f;
        for (int kk = 0; kk < K; kk++) {
            float a = __bfloat162float(Ah[(size_t)grow * K + kk]) +
                      __bfloat162float(Al[(size_t)grow * K + kk]);
            float b = __bfloat162float(Bh[(size_t)gcol * K + kk]) +
                      __bfloat162float(Bl[(size_t)gcol * K + kk]);
            acc = fmaf(a, b, acc);
        }
        float v = acc + bias[gcol];
        if (RELU)   v = fmaxf(v, 0.0f);
        if (ADDRES) v += res[(size_t)grow * N + gcol];
        if (OUT == 1) {
            __nv_bfloat16 h = __float2bfloat16(v);
            Ch[(size_t)grow * N + gcol] = h;
            Cl[(size_t)grow * N + gcol] = __float2bfloat16(v - __bfloat162float(h));
        } else {
            Cf[(size_t)grow * N + gcol] = v;
        }
    }
#endif
}

// ---------------- 3-term split GEMM, 128x256 tile, split-commit overlap -------
// Templated like tc_gemm: OUT 0 = fp32 (+res), 1 = bf16 hi/lo (+relu).
#define G256_A_HI 0
#define G256_A_LO 16384
#define G256_B_HI 32768
#define G256_B_LO 65536
#define G256_CTRL 98304
#define GEMM256_SMEM_BYTES (1024 + 98304 + 64)

template <bool RELU, bool ADDRES, int OUT>
__global__ __launch_bounds__(256)
void tc_gemm256_kernel(const __nv_bfloat16* __restrict__ Ah, const __nv_bfloat16* __restrict__ Al,
                       const __nv_bfloat16* __restrict__ Bh, const __nv_bfloat16* __restrict__ Bl,
                       const float* __restrict__ bias, const float* __restrict__ res,
                       float* __restrict__ Cf,
                       __nv_bfloat16* __restrict__ Ch, __nv_bfloat16* __restrict__ Cl,
                       int M, int N, int K) {
#if HAS_TCGEN05
    extern __shared__ char dsm[];
    uint32_t sbase = smem_u32(dsm);
    uint32_t tile  = (sbase + 1023u) & ~1023u;
    char* tp = dsm + (tile - sbase);
    const uint32_t CTRL = tile + G256_CTRL;

    int tid = threadIdx.x, wid = tid >> 5, lid = tid & 31;
    int brow = blockIdx.y * 128, bcol = blockIdx.x * 256;

    if (wid == 0) { TCGEN05_ALLOC(CTRL, 256); TCGEN05_RELINQUISH(); }
    if (tid == 0) MBARRIER_INIT(CTRL + 8, 2);   // two commits per K-iter
    __syncthreads();
    uint32_t tmem;
    asm volatile("ld.shared.b32 %0, [%1];" : "=r"(tmem) : "r"(CTRL));

    const uint32_t IDESC = (1u << 4) | (1u << 7) | (1u << 10) | (32u << 17) | (8u << 24);
    const uint64_t dah = make_desc_sw128(tile + G256_A_HI);
    const uint64_t dal = make_desc_sw128(tile + G256_A_LO);
    const uint64_t dbh = make_desc_sw128(tile + G256_B_HI);
    const uint64_t dbl = make_desc_sw128(tile + G256_B_LO);

    uint32_t aswo[4]; int aeoff[4];
    #pragma unroll
    for (int j = 0; j < 4; j++) {
        int cid = tid + 256 * j;
        int r = cid >> 3, cb = (cid & 7) << 4;
        aswo[j] = sw128((uint32_t)(r * 128 + cb));
        aeoff[j] = r * K + (cb >> 1);
    }
    uint32_t bswo[8]; int beoff[8];
    #pragma unroll
    for (int j = 0; j < 8; j++) {
        int cid = tid + 256 * j;
        int r = cid >> 3, cb = (cid & 7) << 4;
        bswo[j] = sw128((uint32_t)(r * 128 + cb));
        beoff[j] = r * K + (cb >> 1);
    }
    const __nv_bfloat16* Ahb = Ah + (size_t)brow * K;
    const __nv_bfloat16* Alb = Al + (size_t)brow * K;
    const __nv_bfloat16* Bhb = Bh + (size_t)bcol * K;
    const __nv_bfloat16* Blb = Bl + (size_t)bcol * K;

    int T = K >> 6;
    for (int it = 0; it < T; ++it) {
        int k0 = it << 6;
        if (it > 0) MBARRIER_WAIT_PARITY(CTRL + 8, (it - 1) & 1);
        __syncthreads();
        // phase A: stage hi planes
        #pragma unroll
        for (int j = 0; j < 4; j++)
            *(uint4*)(tp + G256_A_HI + aswo[j]) = *(const uint4*)(Ahb + aeoff[j] + k0);
        #pragma unroll
        for (int j = 0; j < 8; j++)
            *(uint4*)(tp + G256_B_HI + bswo[j]) = *(const uint4*)(Bhb + beoff[j] + k0);
        __syncthreads();
        if (wid == 0) {
            FENCE_PROXY_ASYNC_SHARED_CTA();
            if (elect_one()) {
                #pragma unroll
                for (int ch = 0; ch < 4; ch++)
                    mma_f16_ss(tmem, dah + ch * 2, dbh + ch * 2, IDESC, !(it == 0 && ch == 0));
                TCGEN05_COMMIT(CTRL + 8);
            }
        }
        // phase B: stage lo planes (overlaps hi*hi MMAs)
        #pragma unroll
        for (int j = 0; j < 4; j++)
            *(uint4*)(tp + G256_A_LO + aswo[j]) = *(const uint4*)(Alb + aeoff[j] + k0);
        #pragma unroll
        for (int j = 0; j < 8; j++)
            *(uint4*)(tp + G256_B_LO + bswo[j]) = *(const uint4*)(Blb + beoff[j] + k0);
        __syncthreads();
        if (wid == 0) {
            FENCE_PROXY_ASYNC_SHARED_CTA();
            if (elect_one()) {
                #pragma unroll
                for (int ch = 0; ch < 4; ch++) {
                    uint64_t off = (uint64_t)(ch * 2);
                    mma_f16_ss(tmem, dah + off, dbl + off, IDESC, true);
                    mma_f16_ss(tmem, dal + off, dbh + off, IDESC, true);
                }
                TCGEN05_COMMIT(CTRL + 8);
            }
        }
    }
    MBARRIER_WAIT_PARITY(CTRL + 8, (T - 1) & 1);
    TCGEN05_FENCE_AFTER();
    __syncthreads();

    int sub = wid & 3, grp = wid >> 2;
    float* tb = (float*)(tp + wid * 4224);
    #pragma unroll
    for (int c0 = 0; c0 < 128; c0 += 32) {
        int cbase = grp * 128 + c0;
        uint32_t d[32];
        TCGEN05_LD_X32(d, tmem + cbase);
        TCGEN05_WAIT_LD();
        #pragma unroll
        for (int j = 0; j < 32; j++) tb[lid * 33 + j] = __uint_as_float(d[j]);
        __syncwarp();
        #pragma unroll
        for (int j = 0; j < 32; j++) {
            int grow = brow + sub * 32 + j;
            int gcol = bcol + cbase + lid;
            float v = tb[j * 33 + lid] + bias[gcol];
            if (RELU)   v = fmaxf(v, 0.0f);
            if (ADDRES) v += res[(size_t)grow * N + gcol];
            if (OUT == 1) {
                __nv_bfloat16 h = __float2bfloat16(v);
                Ch[(size_t)grow * N + gcol] = h;
                Cl[(size_t)grow * N + gcol] = __float2bfloat16(v - __bfloat162float(h));
            } else {
                Cf[(size_t)grow * N + gcol] = v;
            }
        }
        __syncwarp();
    }
    __syncthreads();
    if (wid == 0) TCGEN05_DEALLOC(tmem, 256);
#else
    int tid = threadIdx.x;
    int brow = blockIdx.y * 128, bcol = blockIdx.x * 256;
    for (int e = tid; e < 128 * 256; e += 256) {
        int r = e >> 8, c = e & 255;
        int grow = brow + r, gcol = bcol + c;
        float acc = 0.0f;
        for (int kk = 0; kk < K; kk++) {
            float a = __bfloat162float(Ah[(size_t)grow * K + kk]) +
                      __bfloat162float(Al[(size_t)grow * K + kk]);
            float b = __bfloat162float(Bh[(size_t)gcol * K + kk]) +
                      __bfloat162float(Bl[(size_t)gcol * K + kk]);
            acc = fmaf(a, b, acc);
        }
        float v = acc + bias[gcol];
        if (RELU)   v = fmaxf(v, 0.0f);
        if (ADDRES) v += res[(size_t)grow * N + gcol];
        if (OUT == 1) {
            __nv_bfloat16 h = __float2bfloat16(v);
            Ch[(size_t)grow * N + gcol] = h;
            Cl[(size_t)grow * N + gcol] = __float2bfloat16(v - __bfloat162float(h));
        } else {
            Cf[(size_t)grow * N + gcol] = v;
        }
    }
#endif
}

// ---------------- tensor-core causal attention (batched PV+QK commit) --------
#define AQ_OFF   0
#define AK_OFF   16384
#define AV_OFF   32768
#define AP_OFF   49152
#define ALSM_OFF 81920
#define ACTRL    82944
#define ATTN_SMEM_BYTES (1024 + 82944 + 64)

__global__ __launch_bounds__(256)
void tc_attn_kernel(const __nv_bfloat16* __restrict__ qkv,
                    const __nv_bfloat16* __restrict__ vT,
                    __nv_bfloat16* __restrict__ oh,
                    __nv_bfloat16* __restrict__ ol) {
#if HAS_TCGEN05
    extern __shared__ char dsm[];
    uint32_t sbase = smem_u32(dsm);
    uint32_t tile  = (sbase + 1023u) & ~1023u;
    char* tp = dsm + (tile - sbase);
    float* lsm = (float*)(tp + ALSM_OFF);

    int qt = gridDim.x - 1 - blockIdx.x;   // longest tiles first
    int h = blockIdx.y, b = blockIdx.z;
    int tid = threadIdx.x, wid = tid >> 5, lid = tid & 31;
    int sp = wid & 3, half = wid >> 2;
    int r_local = sp * 32 + lid;
    int q_global = qt * 128 + r_local;

    const float SCALE_L2E = 0.125f * 1.4426950408889634f;
    size_t rowbase = (size_t)b * SEQ * QSTRIDE + (size_t)h * HDIM;
    const __nv_bfloat16* vTh = vT + ((size_t)(b * NHEADS + h) * HDIM) * SEQ;

    if (wid == 0) { TCGEN05_ALLOC(tile + ACTRL, 256); TCGEN05_RELINQUISH(); }
    if (tid == 0) MBARRIER_INIT(tile + ACTRL + 8, 1);
    __syncthreads();
    uint32_t tmem;
    asm volatile("ld.shared.b32 %0, [%1];" : "=r"(tmem) : "r"(tile + ACTRL));
    const uint32_t S_T = tmem;
    const uint32_t O_T = tmem + 128;
    const uint32_t MBAR = tile + ACTRL + 8;

    const uint32_t IDESC_QK = (1u << 4) | (1u << 7) | (1u << 10) | (16u << 17) | (8u << 24);
    const uint32_t IDESC_PV = (1u << 4) | (1u << 7) | (1u << 10) | (8u  << 17) | (8u << 24);
    const uint64_t dQ = make_desc_sw128(tile + AQ_OFF);
    const uint64_t dK = make_desc_sw128(tile + AK_OFF);
    const uint64_t dP = make_desc_sw128(tile + AP_OFF);
    const uint64_t dV = make_desc_sw128(tile + AV_OFF);

    uint32_t swo[4]; int rr[4], ce[4];
    uint32_t vsw[4]; size_t vgo[4];
    #pragma unroll
    for (int j = 0; j < 4; j++) {
        int cid = tid + 256 * j;
        rr[j] = cid >> 3;
        int cb = (cid & 7) << 4;
        swo[j] = sw128((uint32_t)(rr[j] * 128 + cb));
        ce[j] = cb >> 1;
        int d = cid >> 4;
        int s16 = cid & 15;
        vsw[j] = sw128((uint32_t)(((d >> 3) + ((s16 >> 3) << 3)) * 1024 +
                                  (d & 7) * 128 + (s16 & 7) * 16));
        vgo[j] = (size_t)d * SEQ + s16 * 8;
    }

    // load Q tile + stage K(0)
    {
        uint4 rk0[4];
        #pragma unroll
        for (int j = 0; j < 4; j++)
            rk0[j] = *(const uint4*)(qkv + DMODEL + rowbase +
                                     (size_t)(rr[j]) * QSTRIDE + ce[j]);
        #pragma unroll
        for (int j = 0; j < 4; j++) {
            *(uint4*)(tp + AQ_OFF + swo[j]) =
                *(const uint4*)(qkv + rowbase + (size_t)(qt * 128 + rr[j]) * QSTRIDE + ce[j]);
            *(uint4*)(tp + AK_OFF + swo[j]) = rk0[j];
        }
        __syncthreads();
        if (wid == 0) {
            FENCE_PROXY_ASYNC_SHARED_CTA();
            if (elect_one()) {
                #pragma unroll
                for (int ch = 0; ch < 4; ch++)
                    mma_f16_ss(S_T, dQ + ch * 2, dK + ch * 2, IDESC_QK, ch > 0);
                TCGEN05_COMMIT(MBAR);
            }
        }
    }

    float lsum = 0.0f;
    uint4 rv[4];
    #pragma unroll
    for (int j = 0; j < 4; j++) rv[j] = *(const uint4*)(vTh + vgo[j]);

    for (int kt = 0; kt <= qt; kt++) {
        uint4 rk[4];
        if (kt < qt) {
            #pragma unroll
            for (int j = 0; j < 4; j++)
                rk[j] = *(const uint4*)(qkv + DMODEL + rowbase +
                                        (size_t)((kt + 1) * 128 + rr[j]) * QSTRIDE + ce[j]);
        }
        MBARRIER_WAIT_PARITY(MBAR, kt & 1);
        TCGEN05_FENCE_AFTER();

        if (kt < qt) {
            // full tile: no causal masking needed
            #pragma unroll
            for (int c = 0; c < 64; c += 32) {
                uint32_t s[32];
                TCGEN05_LD_X32(s, S_T + half * 64 + c);
                TCGEN05_WAIT_LD();
                uint32_t pk[16];
                #pragma unroll
                for (int j2 = 0; j2 < 16; j2++) {
                    float p0 = fast_exp2(__uint_as_float(s[2 * j2])     * SCALE_L2E);
                    float p1 = fast_exp2(__uint_as_float(s[2 * j2 + 1]) * SCALE_L2E);
                    lsum += p0 + p1;
                    __nv_bfloat162 pr = __floats2bfloat162_rn(p0, p1);
                    pk[j2] = *(uint32_t*)&pr;
                }
                uint32_t pb = (uint32_t)(((r_local >> 3) + half * 16) * 1024 +
                                         (r_local & 7) * 128 + c * 2);
                uint4* pk4 = (uint4*)pk;
                #pragma unroll
                for (int i = 0; i < 4; i++)
                    *(uint4*)(tp + AP_OFF + sw128(pb + i * 16)) = pk4[i];
            }
        } else {
            // diagonal tile: apply causal mask
            #pragma unroll
            for (int c = 0; c < 64; c += 32) {
                uint32_t s[32];
                TCGEN05_LD_X32(s, S_T + half * 64 + c);
                TCGEN05_WAIT_LD();
                uint32_t pk[16];
                #pragma unroll
                for (int j2 = 0; j2 < 16; j2++) {
                    int col = kt * 128 + half * 64 + c + 2 * j2;
                    float p0 = fast_exp2(__uint_as_float(s[2 * j2])     * SCALE_L2E);
                    float p1 = fast_exp2(__uint_as_float(s[2 * j2 + 1]) * SCALE_L2E);
                    p0 = (col     <= q_global) ? p0 : 0.0f;
                    p1 = (col + 1 <= q_global) ? p1 : 0.0f;
                    lsum += p0 + p1;
                    __nv_bfloat162 pr = __floats2bfloat162_rn(p0, p1);
                    pk[j2] = *(uint32_t*)&pr;
                }
                uint32_t pb = (uint32_t)(((r_local >> 3) + half * 16) * 1024 +
                                         (r_local & 7) * 128 + c * 2);
                uint4* pk4 = (uint4*)pk;
                #pragma unroll
                for (int i = 0; i < 4; i++)
                    *(uint4*)(tp + AP_OFF + sw128(pb + i * 16)) = pk4[i];
            }
        }
        #pragma unroll
        for (int j = 0; j < 4; j++) *(uint4*)(tp + AV_OFF + vsw[j]) = rv[j];
        if (kt < qt) {
            #pragma unroll
            for (int j = 0; j < 4; j++) *(uint4*)(tp + AK_OFF + swo[j]) = rk[j];
        }
        __syncthreads();

        if (wid == 0) {
            FENCE_PROXY_ASYNC_SHARED_CTA();
            if (elect_one()) {
                #pragma unroll
                for (int ch = 0; ch < 8; ch++) {
                    uint64_t offP = (uint64_t)((ch & 3) * 2 + (ch >> 2) * 1024);
                    uint64_t offV = (uint64_t)((ch & 3) * 2 + (ch >> 2) * 512);
                    mma_f16_ss(O_T, dP + offP, dV + offV, IDESC_PV, !(kt == 0 && ch == 0));
                }
                if (kt < qt) {
                    #pragma unroll
                    for (int ch = 0; ch < 4; ch++)
                        mma_f16_ss(S_T, dQ + ch * 2, dK + ch * 2, IDESC_QK, ch > 0);
                }
                TCGEN05_COMMIT(MBAR);
            }
        }
        if (kt < qt) {
            #pragma unroll
            for (int j = 0; j < 4; j++)
                rv[j] = *(const uint4*)(vTh + vgo[j] + (kt + 1) * 128);
        }
    }
    MBARRIER_WAIT_PARITY(MBAR, (qt + 1) & 1);
    TCGEN05_FENCE_AFTER();

    lsm[half * 128 + r_local] = lsum;
    __syncthreads();
    float l = lsm[r_local] + lsm[128 + r_local];
    float inv_l = 1.0f / l;
    {
        uint32_t o[32];
        TCGEN05_LD_X32(o, O_T + half * 32);
        TCGEN05_WAIT_LD();
        uint4 hv[4], lv[4];
        __nv_bfloat16* hb = (__nv_bfloat16*)hv;
        __nv_bfloat16* lb = (__nv_bfloat16*)lv;
        #pragma unroll
        for (int j = 0; j < 32; j++) {
            float val = __uint_as_float(o[j]) * inv_l;
            __nv_bfloat16 h16 = __float2bfloat16(val);
            hb[j] = h16;
            lb[j] = __float2bfloat16(val - __bfloat162float(h16));
        }
        size_t gbase = (size_t)b * SEQ * DMODEL + (size_t)h * HDIM +
                       (size_t)(qt * 128 + r_local) * DMODEL + half * 32;
        uint4* oph = (uint4*)(oh + gbase);
        uint4* opl = (uint4*)(ol + gbase);
        #pragma unroll
        for (int i = 0; i < 4; i++) { oph[i] = hv[i]; opl[i] = lv[i]; }
    }
    __syncthreads();
    if (wid == 0) TCGEN05_DEALLOC(tmem, 256);
#else
    // compile-only fallback
    int qt = gridDim.x - 1 - blockIdx.x, h = blockIdx.y, b = blockIdx.z;
    int tid = threadIdx.x;
    size_t rowbase = (size_t)b * SEQ * QSTRIDE + (size_t)h * HDIM;
    size_t obase   = (size_t)b * SEQ * DMODEL + (size_t)h * HDIM;
    const __nv_bfloat16* vTh = vT + ((size_t)(b * NHEADS + h) * HDIM) * SEQ;
    for (int r = tid; r < 128; r += blockDim.x) {
        int qg = qt * 128 + r;
        float o[HDIM]; float l = 0.0f;
        for (int d = 0; d < HDIM; d++) o[d] = 0.0f;
        for (int kk = 0; kk <= qg; kk++) {
            float s = 0.0f;
            for (int d = 0; d < HDIM; d++)
                s += __bfloat162float(qkv[rowbase + (size_t)qg * QSTRIDE + d]) *
                     __bfloat162float(qkv[rowbase + (size_t)kk * QSTRIDE + DMODEL + d]);
            float p = fast_exp2(s * 0.125f * 1.4426950408889634f);
            l += p;
            for (int d = 0; d < HDIM; d++)
                o[d] += p * __bfloat162float(vTh[(size_t)d * SEQ + kk]);
        }
        for (int d = 0; d < HDIM; d++) {
            float val = o[d] / l;
            __nv_bfloat16 h16 = __float2bfloat16(val);
            oh[obase + (size_t)qg * DMODEL + d] = h16;
            ol[obase + (size_t)qg * DMODEL + d] = __float2bfloat16(val - __bfloat162float(h16));
        }
    }
#endif
}

// ---------------- launcher ----------------
extern "C" void kernel_launch(void* const* d_in, const int* in_sizes, int n_in,
                              void* d_out, int out_size) {
    (void)in_sizes; (void)n_in; (void)out_size;
    const float* x     = (const float*)d_in[0];
    const float* wq    = (const float*)d_in[1];
    const float* bq    = (const float*)d_in[2];
    const float* wk    = (const float*)d_in[3];
    const float* bk    = (const float*)d_in[4];
    const float* wv    = (const float*)d_in[5];
    const float* bv    = (const float*)d_in[6];
    const float* wo    = (const float*)d_in[7];
    const float* bo    = (const float*)d_in[8];
    const float* w1    = (const float*)d_in[9];
    const float* b1    = (const float*)d_in[10];
    const float* w2    = (const float*)d_in[11];
    const float* b2    = (const float*)d_in[12];
    const float* ln1_g = (const float*)d_in[13];
    const float* ln1_b = (const float*)d_in[14];
    const float* ln2_g = (const float*)d_in[15];
    const float* ln2_b = (const float*)d_in[16];
    float* out = (float*)d_out;

    float *x1;
    cudaGetSymbolAddress((void**)&x1, g_x1);
    __nv_bfloat16 *qkv, *vT, *wqkvth, *wscr;
    cudaGetSymbolAddress((void**)&qkv, g_qkv);
    cudaGetSymbolAddress((void**)&vT, g_vT);
    cudaGetSymbolAddress((void**)&wqkvth, g_wqkvth);
    cudaGetSymbolAddress((void**)&wscr, g_wscr);
    __nv_bfloat16 *ln1h, *ln1l, *atth, *attl, *hh, *hl, *f1h, *f1l;
    cudaGetSymbolAddress((void**)&ln1h, g_ln1h); cudaGetSymbolAddress((void**)&ln1l, g_ln1l);
    cudaGetSymbolAddress((void**)&atth, g_atth); cudaGetSymbolAddress((void**)&attl, g_attl);
    cudaGetSymbolAddress((void**)&hh,   g_hh);   cudaGetSymbolAddress((void**)&hl,   g_hl);
    cudaGetSymbolAddress((void**)&f1h,  g_f1h);  cudaGetSymbolAddress((void**)&f1l,  g_f1l);
    __nv_bfloat16 *woth, *wotl, *w1th, *w1tl, *w2th, *w2tl;
    cudaGetSymbolAddress((void**)&woth, g_woth); cudaGetSymbolAddress((void**)&wotl, g_wotl);
    cudaGetSymbolAddress((void**)&w1th, g_w1th); cudaGetSymbolAddress((void**)&w1tl, g_w1tl);
    cudaGetSymbolAddress((void**)&w2th, g_w2th); cudaGetSymbolAddress((void**)&w2tl, g_w2tl);

    cudaFuncSetAttribute(tc_gemm1_kernel,
                         cudaFuncAttributeMaxDynamicSharedMemorySize, GEMM1_SMEM_BYTES);
    cudaFuncSetAttribute(tc_gemm_kernel<false, true, 0>,
                         cudaFuncAttributeMaxDynamicSharedMemorySize, GEMM_SMEM_BYTES);
    cudaFuncSetAttribute(tc_gemm256_kernel<true, false, 1>,
                         cudaFuncAttributeMaxDynamicSharedMemorySize, GEMM256_SMEM_BYTES);
    cudaFuncSetAttribute(tc_gemm256_kernel<false, true, 0>,
                         cudaFuncAttributeMaxDynamicSharedMemorySize, GEMM256_SMEM_BYTES);
    cudaFuncSetAttribute(tc_attn_kernel,
                         cudaFuncAttributeMaxDynamicSharedMemorySize, ATTN_SMEM_BYTES);

    dim3 grid_d(DMODEL / 128, MROWS / 128);       // (6, 32)
    dim3 grid_qkv(QSTRIDE / 128, MROWS / 128);    // (18, 32)
    dim3 grid_ff1(DFF / 256, MROWS / 128);        // (12, 32)
    dim3 grid_ff2(DMODEL / 256, MROWS / 128);     // (3, 32)
    dim3 agrid(SEQ / 128, NHEADS, BATCH);

    layernorm_split_kernel<<<MROWS, 256>>>(x, ln1_g, ln1_b, ln1h, ln1l);
    transpose4_split_kernel<<<dim3(DMODEL / 128, DMODEL / 32, 4), 256>>>(
        wq, wk, wv, wo,
        wqkvth,                       wscr,
        wqkvth + DMODEL * DMODEL,     wscr + DMODEL * DMODEL,
        wqkvth + 2 * DMODEL * DMODEL, wscr + 2 * DMODEL * DMODEL,
        woth, wotl);
    tc_gemm1_kernel<<<grid_qkv, 256, GEMM1_SMEM_BYTES>>>(
        ln1h, wqkvth, bq, bk, bv, qkv, vT, MROWS, QSTRIDE, DMODEL);
    tc_attn_kernel<<<agrid, 256, ATTN_SMEM_BYTES>>>(qkv, vT, atth, attl);
    transpose2_split_kernel<<<dim3(24, 24, 2), 256>>>(w1, w2, w1th, w1tl, w2th, w2tl);
    tc_gemm_kernel<false, true, 0><<<grid_d, 256, GEMM_SMEM_BYTES>>>(
        atth, attl, woth, wotl, bo, x, x1, nullptr, nullptr, MROWS, DMODEL, DMODEL);
    layernorm_split_kernel<<<MROWS, 256>>>(x1, ln2_g, ln2_b, hh, hl);
    // FFN1: 128x256 tile, ReLU + bf16 hi/lo out
    tc_gemm256_kernel<true, false, 1><<<grid_ff1, 256, GEMM256_SMEM_BYTES>>>(
        hh, hl, w1th, w1tl, b1, nullptr, nullptr, f1h, f1l, MROWS, DFF, DMODEL);
    // FFN2: 128x256 tile, residual(x1) + fp32 out (halves A re-fetch traffic)
    tc_gemm256_kernel<false, true, 0><<<grid_ff2, 256, GEMM256_SMEM_BYTES>>>(
        f1h, f1l, w2th, w2tl, b2, x1, out, nullptr, nullptr, MROWS, DMODEL, DFF);
}

// round 17
// speedup vs baseline: 1.0508x; 1.0058x over previous
#include <cuda_runtime.h>
#include <cuda_bf16.h>
#include <math.h>
#include <stdint.h>

// ---------------- problem constants ----------------
#define BATCH   2
#define SEQ     2048
#define DMODEL  768
#define NHEADS  12
#define HDIM    64
#define DFF     3072
#define MROWS   (BATCH * SEQ)        // 4096
#define LN_EPS  1e-5f
#define QSTRIDE 2304                 // fused qkv row stride

#if defined(__CUDA_ARCH__) && (defined(__CUDA_ARCH_FEAT_SM103_ALL) || defined(__CUDA_ARCH_FEAT_SM100_ALL) || defined(__CUDA_ARCH_FEAT_SM101_ALL))
#define HAS_TCGEN05 1
#else
#define HAS_TCGEN05 0
#endif

// ---------------- inline PTX helpers (sm_103a) ----------------
__device__ __forceinline__ uint32_t smem_u32(const void* p) {
    uint32_t a;
    asm("{ .reg .u64 t; cvta.to.shared.u64 t, %1; cvt.u32.u64 %0, t; }" : "=r"(a) : "l"(p));
    return a;
}

#if HAS_TCGEN05
__device__ __forceinline__ uint32_t elect_one() {
    uint32_t pred;
    asm volatile("{\n\t.reg .pred p;\n\telect.sync _|p, 0xFFFFFFFF;\n\tselp.b32 %0, 1, 0, p;\n\t}" : "=r"(pred));
    return pred;
}
#define MBARRIER_INIT(addr, cnt) \
    asm volatile("mbarrier.init.shared.b64 [%0], %1;" :: "r"((uint32_t)(addr)), "r"((uint32_t)(cnt)) : "memory")
#define MBARRIER_WAIT_PARITY(addr, par) do { \
    uint32_t _m = (uint32_t)(addr), _p = (uint32_t)(par), _d; \
    asm volatile("{\n\t.reg .pred p;\n\tmbarrier.try_wait.parity.acquire.cta.shared::cta.b64 p, [%1], %2;\n\tselp.b32 %0, 1, 0, p;\n\t}" \
        : "=r"(_d) : "r"(_m), "r"(_p) : "memory"); \
    if (!_d) { \
        asm volatile("{\n\t.reg .pred P1;\n\tWL_%=:\n\tmbarrier.try_wait.parity.acquire.cta.shared::cta.b64 P1, [%0], %1, 0x989680;\n\t@P1 bra.uni WD_%=;\n\tbra.uni WL_%=;\n\tWD_%=:\n\t}" \
            :: "r"(_m), "r"(_p) : "memory"); \
    } \
} while (0)
#define TCGEN05_ALLOC(saddr, ncols) \
    asm volatile("tcgen05.alloc.cta_group::1.sync.aligned.shared::cta.b32 [%0], %1;" :: "r"((uint32_t)(saddr)), "r"((uint32_t)(ncols)) : "memory")
#define TCGEN05_DEALLOC(tmem, ncols) \
    asm volatile("tcgen05.dealloc.cta_group::1.sync.aligned.b32 %0, %1;" :: "r"(tmem), "r"((uint32_t)(ncols)))
#define TCGEN05_RELINQUISH() \
    asm volatile("tcgen05.relinquish_alloc_permit.cta_group::1.sync.aligned;")
#define TCGEN05_COMMIT(mbar) \
    asm volatile("tcgen05.commit.cta_group::1.mbarrier::arrive::one.shared::cluster.b64 [%0];" :: "r"((uint32_t)(mbar)) : "memory")
#define TCGEN05_WAIT_LD() asm volatile("tcgen05.wait::ld.sync.aligned;" ::: "memory")
#define TCGEN05_FENCE_AFTER() asm volatile("tcgen05.fence::after_thread_sync;" ::: "memory")
#define FENCE_PROXY_ASYNC_SHARED_CTA() asm volatile("fence.proxy.async.shared::cta;" ::: "memory")
#define TCGEN05_LD_X32(r, tmem_addr) \
    asm volatile( \
        "tcgen05.ld.sync.aligned.32x32b.x32.b32 " \
        "{%0, %1, %2, %3, %4, %5, %6, %7, " \
        " %8, %9, %10, %11, %12, %13, %14, %15, " \
        " %16, %17, %18, %19, %20, %21, %22, %23, " \
        " %24, %25, %26, %27, %28, %29, %30, %31}, [%32];" \
        : "=r"((r)[0]),  "=r"((r)[1]),  "=r"((r)[2]),  "=r"((r)[3]), \
          "=r"((r)[4]),  "=r"((r)[5]),  "=r"((r)[6]),  "=r"((r)[7]), \
          "=r"((r)[8]),  "=r"((r)[9]),  "=r"((r)[10]), "=r"((r)[11]), \
          "=r"((r)[12]), "=r"((r)[13]), "=r"((r)[14]), "=r"((r)[15]), \
          "=r"((r)[16]), "=r"((r)[17]), "=r"((r)[18]), "=r"((r)[19]), \
          "=r"((r)[20]), "=r"((r)[21]), "=r"((r)[22]), "=r"((r)[23]), \
          "=r"((r)[24]), "=r"((r)[25]), "=r"((r)[26]), "=r"((r)[27]), \
          "=r"((r)[28]), "=r"((r)[29]), "=r"((r)[30]), "=r"((r)[31]) \
        : "r"(tmem_addr))

// K-major SW128 descriptor (LBO=1, SBO=64)
static __device__ __forceinline__ uint64_t make_desc_sw128(uint32_t addr) {
    const uint64_t base =
        (uint64_t(2) << 61) | (uint64_t(1) << 46) | (uint64_t(64) << 32) | (uint64_t(1) << 16);
    return base | ((uint64_t)(addr >> 4) & 0x3FFF);
}

__device__ __forceinline__ void mma_f16_ss(uint32_t d_tmem, uint64_t a_desc, uint64_t b_desc,
                                           uint32_t idesc, bool enable_d) {
    uint32_t en = enable_d ? 1u : 0u;
    asm volatile(
        "{\n\t.reg .pred p;\n\t"
        "setp.ne.u32 p, %5, 0;\n\t"
        "tcgen05.mma.cta_group::1.kind::f16 [%0], %1, %2, %3, {%4, %4, %4, %4}, p;\n\t}"
        :: "r"(d_tmem), "l"(a_desc), "l"(b_desc), "r"(idesc), "r"(0u), "r"(en)
        : "memory");
}
#endif // HAS_TCGEN05

__device__ __forceinline__ uint32_t sw128(uint32_t off) { return off ^ ((off >> 3) & 0x70); }

// fast exp2 on the FMA pipe (no MUFU). |x| < ~30, err ~2e-6 relative.
__device__ __forceinline__ float fast_exp2(float x) {
    float t = x + 12582912.0f;
    int   e = __float_as_int(t);
    float r = t - 12582912.0f;
    float f = x - r;
    float p = 1.3333558146e-3f;
    p = fmaf(p, f, 9.6181298421e-3f);
    p = fmaf(p, f, 5.5504108664e-2f);
    p = fmaf(p, f, 2.4022650696e-1f);
    p = fmaf(p, f, 6.9314718056e-1f);
    p = fmaf(p, f, 1.0f);
    return __int_as_float(__float_as_int(p) + (e << 23));
}

// ---------------- scratch (device globals; no allocs allowed) ----------------
__device__ float g_x1 [MROWS * DMODEL];

__device__ __nv_bfloat16 g_qkv[MROWS * QSTRIDE];                 // q,k used; v region unused
__device__ __nv_bfloat16 g_vT [BATCH * NHEADS * HDIM * SEQ];     // v transposed [b,h,d,s]

__device__ __nv_bfloat16 g_ln1h[MROWS * DMODEL], g_ln1l[MROWS * DMODEL];
__device__ __nv_bfloat16 g_atth[MROWS * DMODEL], g_attl[MROWS * DMODEL];
__device__ __nv_bfloat16 g_hh  [MROWS * DMODEL], g_hl  [MROWS * DMODEL];
__device__ __nv_bfloat16 g_f1h [MROWS * DFF],    g_f1l [MROWS * DFF];

__device__ __nv_bfloat16 g_wqkvth[QSTRIDE * DMODEL];   // fused Wq|Wk|Wv transposed (hi)
__device__ __nv_bfloat16 g_wscr  [QSTRIDE * DMODEL];   // lo scratch (unused by 1-term gemm)
__device__ __nv_bfloat16 g_woth[DMODEL * DMODEL], g_wotl[DMODEL * DMODEL];
__device__ __nv_bfloat16 g_w1th[DFF * DMODEL],    g_w1tl[DFF * DMODEL];
__device__ __nv_bfloat16 g_w2th[DMODEL * DFF],    g_w2tl[DMODEL * DFF];

// ---------------- vectorized weight transpose + fp32->bf16 hi/lo split --------
__device__ __forceinline__ void transpose_tile_body(const float* __restrict__ W,
                                                    __nv_bfloat16* __restrict__ Th,
                                                    __nv_bfloat16* __restrict__ Tl,
                                                    int K, int N, int n0, int k0) {
    __shared__ float sm[32][133];
    int t = threadIdx.x;
    int tx = t & 31, ty = t >> 5;              // 32 x 8
    #pragma unroll
    for (int i = 0; i < 4; i++) {
        int r = ty + 8 * i;
        float4 v = *(const float4*)(W + (size_t)(k0 + r) * N + n0 + tx * 4);
        sm[r][tx * 4 + 0] = v.x;
        sm[r][tx * 4 + 1] = v.y;
        sm[r][tx * 4 + 2] = v.z;
        sm[r][tx * 4 + 3] = v.w;
    }
    __syncthreads();
    int kb = (t & 3) * 8;                      // k chunk base (0,8,16,24)
    int nrow = t >> 2;                         // 0..63
    #pragma unroll
    for (int pass = 0; pass < 2; pass++) {
        int n = nrow + 64 * pass;
        __nv_bfloat16 hbuf[8], lbuf[8];
        #pragma unroll
        for (int j = 0; j < 8; j++) {
            float v = sm[kb + j][n];
            __nv_bfloat16 h = __float2bfloat16(v);
            hbuf[j] = h;
            lbuf[j] = __float2bfloat16(v - __bfloat162float(h));
        }
        size_t o = (size_t)(n0 + n) * K + k0 + kb;
        *(uint4*)(Th + o) = *(uint4*)hbuf;
        *(uint4*)(Tl + o) = *(uint4*)lbuf;
    }
}

// batched transpose of the four 768x768 weights in one launch (z = which matrix)
__global__ __launch_bounds__(256)
void transpose4_split_kernel(const float* __restrict__ W0, const float* __restrict__ W1,
                             const float* __restrict__ W2, const float* __restrict__ W3,
                             __nv_bfloat16* __restrict__ T0h, __nv_bfloat16* __restrict__ T0l,
                             __nv_bfloat16* __restrict__ T1h, __nv_bfloat16* __restrict__ T1l,
                             __nv_bfloat16* __restrict__ T2h, __nv_bfloat16* __restrict__ T2l,
                             __nv_bfloat16* __restrict__ T3h, __nv_bfloat16* __restrict__ T3l) {
    int z = blockIdx.z;
    const float* W = (z == 0) ? W0 : (z == 1) ? W1 : (z == 2) ? W2 : W3;
    __nv_bfloat16* Th = (z == 0) ? T0h : (z == 1) ? T1h : (z == 2) ? T2h : T3h;
    __nv_bfloat16* Tl = (z == 0) ? T0l : (z == 1) ? T1l : (z == 2) ? T2l : T3l;
    transpose_tile_body(W, Th, Tl, DMODEL, DMODEL, blockIdx.x * 128, blockIdx.y * 32);
}

// merged transpose of w1 [768,3072] and w2 [3072,768] in one launch.
__global__ __launch_bounds__(256)
void transpose2_split_kernel(const float* __restrict__ W1f, const float* __restrict__ W2f,
                             __nv_bfloat16* __restrict__ T1h, __nv_bfloat16* __restrict__ T1l,
                             __nv_bfloat16* __restrict__ T2h, __nv_bfloat16* __restrict__ T2l) {
    if (blockIdx.z == 0) {
        transpose_tile_body(W1f, T1h, T1l, DMODEL, DFF,
                            blockIdx.x * 128, blockIdx.y * 32);
    } else {
        int idx = blockIdx.y * 24 + blockIdx.x;      // 0..575
        int n0 = (idx % 6) * 128;
        int k0 = (idx / 6) * 32;
        transpose_tile_body(W2f, T2h, T2l, DFF, DMODEL, n0, k0);
    }
}

// ---------------- block reduction ----------------
__device__ __forceinline__ float block_sum(float v) {
    __shared__ float sm[32];
    __syncthreads();
    int lane = threadIdx.x & 31;
    int wid  = threadIdx.x >> 5;
    #pragma unroll
    for (int o = 16; o > 0; o >>= 1) v += __shfl_down_sync(0xffffffffu, v, o);
    if (lane == 0) sm[wid] = v;
    __syncthreads();
    if (wid == 0) {
        int nw = (blockDim.x + 31) >> 5;
        v = (lane < nw) ? sm[lane] : 0.0f;
        #pragma unroll
        for (int o = 16; o > 0; o >>= 1) v += __shfl_down_sync(0xffffffffu, v, o);
        if (lane == 0) sm[0] = v;
    }
    __syncthreads();
    return sm[0];
}

// ---------------- LayerNorm -> bf16 hi/lo planes ----------------
__global__ __launch_bounds__(256)
void layernorm_split_kernel(const float* __restrict__ x,
                            const float* __restrict__ g,
                            const float* __restrict__ b,
                            __nv_bfloat16* __restrict__ oh,
                            __nv_bfloat16* __restrict__ ol) {
    int row = blockIdx.x;
    const float* xr = x + (size_t)row * DMODEL;
    int t = threadIdx.x;

    float v0 = xr[t], v1 = xr[t + 256], v2 = xr[t + 512];
    float mu = block_sum(v0 + v1 + v2) * (1.0f / DMODEL);
    float d0 = v0 - mu, d1 = v1 - mu, d2 = v2 - mu;
    float var = block_sum(d0 * d0 + d1 * d1 + d2 * d2) * (1.0f / DMODEL);
    float rs = rsqrtf(var + LN_EPS);

    size_t base = (size_t)row * DMODEL;
    #pragma unroll
    for (int i = 0; i < 3; i++) {
        int c = t + 256 * i;
        float d = (i == 0) ? d0 : (i == 1 ? d1 : d2);
        float v = d * rs * g[c] + b[c];
        __nv_bfloat16 h = __float2bfloat16(v);
        oh[base + c] = h;
        ol[base + c] = __float2bfloat16(v - __bfloat162float(h));
    }
}

// ---------------- fused QKV: 1-term bf16 GEMM, 128x256 tile, pipelined --------
// A traffic halved vs 128-wide tiles (9 B-strips instead of 18).
// smem: A_HI 16K | B_HI 32K | ctrl. TMEM 256 cols.
#define G1_A_HI  0
#define G1_B_HI  16384
#define G1_CTRL  49152
#define GEMM1_SMEM_BYTES (1024 + 49152 + 64)

__global__ __launch_bounds__(256)
void tc_gemm1_kernel(const __nv_bfloat16* __restrict__ Ah, const __nv_bfloat16* __restrict__ Bh,
                     const float* __restrict__ bq, const float* __restrict__ bk,
                     const float* __restrict__ bv, __nv_bfloat16* __restrict__ Cqk,
                     __nv_bfloat16* __restrict__ CvT, int M, int N, int K) {
#if HAS_TCGEN05
    extern __shared__ char dsm[];
    uint32_t sbase = smem_u32(dsm);
    uint32_t tile  = (sbase + 1023u) & ~1023u;
    char* tp = dsm + (tile - sbase);
    const uint32_t CTRL = tile + G1_CTRL;

    int tid = threadIdx.x, wid = tid >> 5, lid = tid & 31;
    int brow = blockIdx.y * 128, bcol = blockIdx.x * 256;
    // tile (256 wide) stays within one q/k/v segment (768 = 3*256)
    const float* bsel = (bcol < DMODEL) ? bq : (bcol < 2 * DMODEL ? bk : bv);
    int boff = (bcol < DMODEL) ? 0 : (bcol < 2 * DMODEL ? DMODEL : 2 * DMODEL);

    if (wid == 0) { TCGEN05_ALLOC(CTRL, 256); TCGEN05_RELINQUISH(); }
    if (tid == 0) MBARRIER_INIT(CTRL + 8, 1);
    __syncthreads();
    uint32_t tmem;
    asm volatile("ld.shared.b32 %0, [%1];" : "=r"(tmem) : "r"(CTRL));

    const uint32_t IDESC = (1u << 4) | (1u << 7) | (1u << 10) | (32u << 17) | (8u << 24);
    const uint64_t dah = make_desc_sw128(tile + G1_A_HI);
    const uint64_t dbh = make_desc_sw128(tile + G1_B_HI);

    uint32_t aswo[4]; int aeoff[4];
    #pragma unroll
    for (int j = 0; j < 4; j++) {
        int cid = tid + 256 * j;
        int r = cid >> 3, cb = (cid & 7) << 4;
        aswo[j] = sw128((uint32_t)(r * 128 + cb));
        aeoff[j] = r * K + (cb >> 1);
    }
    uint32_t bswo[8]; int beoff[8];
    #pragma unroll
    for (int j = 0; j < 8; j++) {
        int cid = tid + 256 * j;
        int r = cid >> 3, cb = (cid & 7) << 4;
        bswo[j] = sw128((uint32_t)(r * 128 + cb));
        beoff[j] = r * K + (cb >> 1);
    }
    const __nv_bfloat16* Abase = Ah + (size_t)brow * K;
    const __nv_bfloat16* Bbase = Bh + (size_t)bcol * K;

    int T = K >> 6;
    uint4 ra[4], rb[8];
    #pragma unroll
    for (int j = 0; j < 4; j++) ra[j] = *(const uint4*)(Abase + aeoff[j]);
    #pragma unroll
    for (int j = 0; j < 8; j++) rb[j] = *(const uint4*)(Bbase + beoff[j]);
    for (int it = 0; it < T; ++it) {
        if (it > 0) MBARRIER_WAIT_PARITY(CTRL + 8, (it - 1) & 1);
        __syncthreads();
        #pragma unroll
        for (int j = 0; j < 4; j++) *(uint4*)(tp + G1_A_HI + aswo[j]) = ra[j];
        #pragma unroll
        for (int j = 0; j < 8; j++) *(uint4*)(tp + G1_B_HI + bswo[j]) = rb[j];
        __syncthreads();
        if (wid == 0) {
            FENCE_PROXY_ASYNC_SHARED_CTA();
            if (elect_one()) {
                #pragma unroll
                for (int ch = 0; ch < 4; ch++)
                    mma_f16_ss(tmem, dah + ch * 2, dbh + ch * 2, IDESC, !(it == 0 && ch == 0));
                TCGEN05_COMMIT(CTRL + 8);
            }
        }
        if (it + 1 < T) {
            int k0 = (it + 1) << 6;
            #pragma unroll
            for (int j = 0; j < 4; j++) ra[j] = *(const uint4*)(Abase + aeoff[j] + k0);
            #pragma unroll
            for (int j = 0; j < 8; j++) rb[j] = *(const uint4*)(Bbase + beoff[j] + k0);
        }
    }
    MBARRIER_WAIT_PARITY(CTRL + 8, (T - 1) & 1);
    TCGEN05_FENCE_AFTER();
    __syncthreads();

    int sub = wid & 3, grp = wid >> 2;     // warp handles rows sub*32..+31, cols grp*128..+127
    if (bcol < 2 * DMODEL) {
        float* tb = (float*)(tp + wid * 4224);
        #pragma unroll
        for (int c0 = 0; c0 < 128; c0 += 32) {
            int cbase = grp * 128 + c0;
            uint32_t d[32];
            TCGEN05_LD_X32(d, tmem + cbase);
            TCGEN05_WAIT_LD();
            #pragma unroll
            for (int j = 0; j < 32; j++) tb[lid * 33 + j] = __uint_as_float(d[j]);
            __syncwarp();
            #pragma unroll
            for (int j = 0; j < 32; j++) {
                int grow = brow + sub * 32 + j;
                int gcol = bcol + cbase + lid;
                Cqk[(size_t)grow * N + gcol] =
                    __float2bfloat16(tb[j * 33 + lid] + bsel[gcol - boff]);
            }
            __syncwarp();
        }
    } else {
        int grow = brow + sub * 32 + lid;
        int bb = grow >> 11, s = grow & (SEQ - 1);
        #pragma unroll
        for (int c0 = 0; c0 < 128; c0 += 32) {
            int cbase = grp * 128 + c0;
            uint32_t d[32];
            TCGEN05_LD_X32(d, tmem + cbase);
            TCGEN05_WAIT_LD();
            #pragma unroll
            for (int j = 0; j < 32; j++) {
                int gcol = bcol + cbase + j;
                int vcol = gcol - 2 * DMODEL;
                int hh2 = vcol >> 6, dl = vcol & 63;
                CvT[((size_t)(bb * NHEADS + hh2) * HDIM + dl) * SEQ + s] =
                    __float2bfloat16(__uint_as_float(d[j]) + bsel[gcol - boff]);
            }
        }
    }
    __syncthreads();
    if (wid == 0) TCGEN05_DEALLOC(tmem, 256);
#else
    int tid = threadIdx.x;
    int brow = blockIdx.y * 128, bcol = blockIdx.x * 256;
    for (int e = tid; e < 128 * 256; e += 256) {
        int r = e >> 8, c = e & 255;
        int grow = brow + r, gcol = bcol + c;
        float acc = 0.0f;
        for (int kk = 0; kk < K; kk++)
            acc = fmaf(__bfloat162float(Ah[(size_t)grow * K + kk]),
                       __bfloat162float(Bh[(size_t)gcol * K + kk]), acc);
        const float* bsel = (gcol < DMODEL) ? bq : (gcol < 2 * DMODEL ? bk : bv);
        int boff = (gcol < DMODEL) ? 0 : (gcol < 2 * DMODEL ? DMODEL : 2 * DMODEL);
        float v = acc + bsel[gcol - boff];
        if (gcol < 2 * DMODEL) {
            Cqk[(size_t)grow * N + gcol] = __float2bfloat16(v);
        } else {
            int vcol = gcol - 2 * DMODEL;
            int bb = grow >> 11, s = grow & (SEQ - 1);
            CvT[((size_t)(bb * NHEADS + (vcol >> 6)) * HDIM + (vcol & 63)) * SEQ + s] =
                __float2bfloat16(v);
        }
    }
#endif
}

// ---------------- 3-term split GEMM, 128x256 tile, split-commit overlap -------
// Templated: OUT 0 = fp32 (+res), 1 = bf16 hi/lo (+relu). Used for O-proj,
// FFN1, FFN2 (all GEMMs after attention).
#define G256_A_HI 0
#define G256_A_LO 16384
#define G256_B_HI 32768
#define G256_B_LO 65536
#define G256_CTRL 98304
#define GEMM256_SMEM_BYTES (1024 + 98304 + 64)

template <bool RELU, bool ADDRES, int OUT>
__global__ __launch_bounds__(256)
void tc_gemm256_kernel(const __nv_bfloat16* __restrict__ Ah, const __nv_bfloat16* __restrict__ Al,
                       const __nv_bfloat16* __restrict__ Bh, const __nv_bfloat16* __restrict__ Bl,
                       const float* __restrict__ bias, const float* __restrict__ res,
                       float* __restrict__ Cf,
                       __nv_bfloat16* __restrict__ Ch, __nv_bfloat16* __restrict__ Cl,
                       int M, int N, int K) {
#if HAS_TCGEN05
    extern __shared__ char dsm[];
    uint32_t sbase = smem_u32(dsm);
    uint32_t tile  = (sbase + 1023u) & ~1023u;
    char* tp = dsm + (tile - sbase);
    const uint32_t CTRL = tile + G256_CTRL;

    int tid = threadIdx.x, wid = tid >> 5, lid = tid & 31;
    int brow = blockIdx.y * 128, bcol = blockIdx.x * 256;

    if (wid == 0) { TCGEN05_ALLOC(CTRL, 256); TCGEN05_RELINQUISH(); }
    if (tid == 0) MBARRIER_INIT(CTRL + 8, 2);   // two commits per K-iter
    __syncthreads();
    uint32_t tmem;
    asm volatile("ld.shared.b32 %0, [%1];" : "=r"(tmem) : "r"(CTRL));

    const uint32_t IDESC = (1u << 4) | (1u << 7) | (1u << 10) | (32u << 17) | (8u << 24);
    const uint64_t dah = make_desc_sw128(tile + G256_A_HI);
    const uint64_t dal = make_desc_sw128(tile + G256_A_LO);
    const uint64_t dbh = make_desc_sw128(tile + G256_B_HI);
    const uint64_t dbl = make_desc_sw128(tile + G256_B_LO);

    uint32_t aswo[4]; int aeoff[4];
    #pragma unroll
    for (int j = 0; j < 4; j++) {
        int cid = tid + 256 * j;
        int r = cid >> 3, cb = (cid & 7) << 4;
        aswo[j] = sw128((uint32_t)(r * 128 + cb));
        aeoff[j] = r * K + (cb >> 1);
    }
    uint32_t bswo[8]; int beoff[8];
    #pragma unroll
    for (int j = 0; j < 8; j++) {
        int cid = tid + 256 * j;
        int r = cid >> 3, cb = (cid & 7) << 4;
        bswo[j] = sw128((uint32_t)(r * 128 + cb));
        beoff[j] = r * K + (cb >> 1);
    }
    const __nv_bfloat16* Ahb = Ah + (size_t)brow * K;
    const __nv_bfloat16* Alb = Al + (size_t)brow * K;
    const __nv_bfloat16* Bhb = Bh + (size_t)bcol * K;
    const __nv_bfloat16* Blb = Bl + (size_t)bcol * K;

    int T = K >> 6;
    for (int it = 0; it < T; ++it) {
        int k0 = it << 6;
        if (it > 0) MBARRIER_WAIT_PARITY(CTRL + 8, (it - 1) & 1);
        __syncthreads();
        // phase A: stage hi planes
        #pragma unroll
        for (int j = 0; j < 4; j++)
            *(uint4*)(tp + G256_A_HI + aswo[j]) = *(const uint4*)(Ahb + aeoff[j] + k0);
        #pragma unroll
        for (int j = 0; j < 8; j++)
            *(uint4*)(tp + G256_B_HI + bswo[j]) = *(const uint4*)(Bhb + beoff[j] + k0);
        __syncthreads();
        if (wid == 0) {
            FENCE_PROXY_ASYNC_SHARED_CTA();
            if (elect_one()) {
                #pragma unroll
                for (int ch = 0; ch < 4; ch++)
                    mma_f16_ss(tmem, dah + ch * 2, dbh + ch * 2, IDESC, !(it == 0 && ch == 0));
                TCGEN05_COMMIT(CTRL + 8);
            }
        }
        // phase B: stage lo planes (overlaps hi*hi MMAs)
        #pragma unroll
        for (int j = 0; j < 4; j++)
            *(uint4*)(tp + G256_A_LO + aswo[j]) = *(const uint4*)(Alb + aeoff[j] + k0);
        #pragma unroll
        for (int j = 0; j < 8; j++)
            *(uint4*)(tp + G256_B_LO + bswo[j]) = *(const uint4*)(Blb + beoff[j] + k0);
        __syncthreads();
        if (wid == 0) {
            FENCE_PROXY_ASYNC_SHARED_CTA();
            if (elect_one()) {
                #pragma unroll
                for (int ch = 0; ch < 4; ch++) {
                    uint64_t off = (uint64_t)(ch * 2);
                    mma_f16_ss(tmem, dah + off, dbl + off, IDESC, true);
                    mma_f16_ss(tmem, dal + off, dbh + off, IDESC, true);
                }
                TCGEN05_COMMIT(CTRL + 8);
            }
        }
    }
    MBARRIER_WAIT_PARITY(CTRL + 8, (T - 1) & 1);
    TCGEN05_FENCE_AFTER();
    __syncthreads();

    int sub = wid & 3, grp = wid >> 2;
    float* tb = (float*)(tp + wid * 4224);
    #pragma unroll
    for (int c0 = 0; c0 < 128; c0 += 32) {
        int cbase = grp * 128 + c0;
        uint32_t d[32];
        TCGEN05_LD_X32(d, tmem + cbase);
        TCGEN05_WAIT_LD();
        #pragma unroll
        for (int j = 0; j < 32; j++) tb[lid * 33 + j] = __uint_as_float(d[j]);
        __syncwarp();
        #pragma unroll
        for (int j = 0; j < 32; j++) {
            int grow = brow + sub * 32 + j;
            int gcol = bcol + cbase + lid;
            float v = tb[j * 33 + lid] + bias[gcol];
            if (RELU)   v = fmaxf(v, 0.0f);
            if (ADDRES) v += res[(size_t)grow * N + gcol];
            if (OUT == 1) {
                __nv_bfloat16 h = __float2bfloat16(v);
                Ch[(size_t)grow * N + gcol] = h;
                Cl[(size_t)grow * N + gcol] = __float2bfloat16(v - __bfloat162float(h));
            } else {
                Cf[(size_t)grow * N + gcol] = v;
            }
        }
        __syncwarp();
    }
    __syncthreads();
    if (wid == 0) TCGEN05_DEALLOC(tmem, 256);
#else
    int tid = threadIdx.x;
    int brow = blockIdx.y * 128, bcol = blockIdx.x * 256;
    for (int e = tid; e < 128 * 256; e += 256) {
        int r = e >> 8, c = e & 255;
        int grow = brow + r, gcol = bcol + c;
        float acc = 0.0f;
        for (int kk = 0; kk < K; kk++) {
            float a = __bfloat162float(Ah[(size_t)grow * K + kk]) +
                      __bfloat162float(Al[(size_t)grow * K + kk]);
            float b = __bfloat162float(Bh[(size_t)gcol * K + kk]) +
                      __bfloat162float(Bl[(size_t)gcol * K + kk]);
            acc = fmaf(a, b, acc);
        }
        float v = acc + bias[gcol];
        if (RELU)   v = fmaxf(v, 0.0f);
        if (ADDRES) v += res[(size_t)grow * N + gcol];
        if (OUT == 1) {
            __nv_bfloat16 h = __float2bfloat16(v);
            Ch[(size_t)grow * N + gcol] = h;
            Cl[(size_t)grow * N + gcol] = __float2bfloat16(v - __bfloat162float(h));
        } else {
            Cf[(size_t)grow * N + gcol] = v;
        }
    }
#endif
}

// ---------------- tensor-core causal attention (batched PV+QK commit) --------
#define AQ_OFF   0
#define AK_OFF   16384
#define AV_OFF   32768
#define AP_OFF   49152
#define ALSM_OFF 81920
#define ACTRL    82944
#define ATTN_SMEM_BYTES (1024 + 82944 + 64)

__global__ __launch_bounds__(256)
void tc_attn_kernel(const __nv_bfloat16* __restrict__ qkv,
                    const __nv_bfloat16* __restrict__ vT,
                    __nv_bfloat16* __restrict__ oh,
                    __nv_bfloat16* __restrict__ ol) {
#if HAS_TCGEN05
    extern __shared__ char dsm[];
    uint32_t sbase = smem_u32(dsm);
    uint32_t tile  = (sbase + 1023u) & ~1023u;
    char* tp = dsm + (tile - sbase);
    float* lsm = (float*)(tp + ALSM_OFF);

    int qt = gridDim.x - 1 - blockIdx.x;   // longest tiles first
    int h = blockIdx.y, b = blockIdx.z;
    int tid = threadIdx.x, wid = tid >> 5, lid = tid & 31;
    int sp = wid & 3, half = wid >> 2;
    int r_local = sp * 32 + lid;
    int q_global = qt * 128 + r_local;

    const float SCALE_L2E = 0.125f * 1.4426950408889634f;
    size_t rowbase = (size_t)b * SEQ * QSTRIDE + (size_t)h * HDIM;
    const __nv_bfloat16* vTh = vT + ((size_t)(b * NHEADS + h) * HDIM) * SEQ;

    if (wid == 0) { TCGEN05_ALLOC(tile + ACTRL, 256); TCGEN05_RELINQUISH(); }
    if (tid == 0) MBARRIER_INIT(tile + ACTRL + 8, 1);
    __syncthreads();
    uint32_t tmem;
    asm volatile("ld.shared.b32 %0, [%1];" : "=r"(tmem) : "r"(tile + ACTRL));
    const uint32_t S_T = tmem;
    const uint32_t O_T = tmem + 128;
    const uint32_t MBAR = tile + ACTRL + 8;

    const uint32_t IDESC_QK = (1u << 4) | (1u << 7) | (1u << 10) | (16u << 17) | (8u << 24);
    const uint32_t IDESC_PV = (1u << 4) | (1u << 7) | (1u << 10) | (8u  << 17) | (8u << 24);
    const uint64_t dQ = make_desc_sw128(tile + AQ_OFF);
    const uint64_t dK = make_desc_sw128(tile + AK_OFF);
    const uint64_t dP = make_desc_sw128(tile + AP_OFF);
    const uint64_t dV = make_desc_sw128(tile + AV_OFF);

    uint32_t swo[4]; int rr[4], ce[4];
    uint32_t vsw[4]; size_t vgo[4];
    #pragma unroll
    for (int j = 0; j < 4; j++) {
        int cid = tid + 256 * j;
        rr[j] = cid >> 3;
        int cb = (cid & 7) << 4;
        swo[j] = sw128((uint32_t)(rr[j] * 128 + cb));
        ce[j] = cb >> 1;
        int d = cid >> 4;
        int s16 = cid & 15;
        vsw[j] = sw128((uint32_t)(((d >> 3) + ((s16 >> 3) << 3)) * 1024 +
                                  (d & 7) * 128 + (s16 & 7) * 16));
        vgo[j] = (size_t)d * SEQ + s16 * 8;
    }

    // load Q tile + stage K(0)
    {
        uint4 rk0[4];
        #pragma unroll
        for (int j = 0; j < 4; j++)
            rk0[j] = *(const uint4*)(qkv + DMODEL + rowbase +
                                     (size_t)(rr[j]) * QSTRIDE + ce[j]);
        #pragma unroll
        for (int j = 0; j < 4; j++) {
            *(uint4*)(tp + AQ_OFF + swo[j]) =
                *(const uint4*)(qkv + rowbase + (size_t)(qt * 128 + rr[j]) * QSTRIDE + ce[j]);
            *(uint4*)(tp + AK_OFF + swo[j]) = rk0[j];
        }
        __syncthreads();
        if (wid == 0) {
            FENCE_PROXY_ASYNC_SHARED_CTA();
            if (elect_one()) {
                #pragma unroll
                for (int ch = 0; ch < 4; ch++)
                    mma_f16_ss(S_T, dQ + ch * 2, dK + ch * 2, IDESC_QK, ch > 0);
                TCGEN05_COMMIT(MBAR);
            }
        }
    }

    float lsum = 0.0f;
    uint4 rv[4];
    #pragma unroll
    for (int j = 0; j < 4; j++) rv[j] = *(const uint4*)(vTh + vgo[j]);

    for (int kt = 0; kt <= qt; kt++) {
        uint4 rk[4];
        if (kt < qt) {
            #pragma unroll
            for (int j = 0; j < 4; j++)
                rk[j] = *(const uint4*)(qkv + DMODEL + rowbase +
                                        (size_t)((kt + 1) * 128 + rr[j]) * QSTRIDE + ce[j]);
        }
        MBARRIER_WAIT_PARITY(MBAR, kt & 1);
        TCGEN05_FENCE_AFTER();

        if (kt < qt) {
            // full tile: no causal masking needed
            #pragma unroll
            for (int c = 0; c < 64; c += 32) {
                uint32_t s[32];
                TCGEN05_LD_X32(s, S_T + half * 64 + c);
                TCGEN05_WAIT_LD();
                uint32_t pk[16];
                #pragma unroll
                for (int j2 = 0; j2 < 16; j2++) {
                    float p0 = fast_exp2(__uint_as_float(s[2 * j2])     * SCALE_L2E);
                    float p1 = fast_exp2(__uint_as_float(s[2 * j2 + 1]) * SCALE_L2E);
                    lsum += p0 + p1;
                    __nv_bfloat162 pr = __floats2bfloat162_rn(p0, p1);
                    pk[j2] = *(uint32_t*)&pr;
                }
                uint32_t pb = (uint32_t)(((r_local >> 3) + half * 16) * 1024 +
                                         (r_local & 7) * 128 + c * 2);
                uint4* pk4 = (uint4*)pk;
                #pragma unroll
                for (int i = 0; i < 4; i++)
                    *(uint4*)(tp + AP_OFF + sw128(pb + i * 16)) = pk4[i];
            }
        } else {
            // diagonal tile: apply causal mask
            #pragma unroll
            for (int c = 0; c < 64; c += 32) {
                uint32_t s[32];
                TCGEN05_LD_X32(s, S_T + half * 64 + c);
                TCGEN05_WAIT_LD();
                uint32_t pk[16];
                #pragma unroll
                for (int j2 = 0; j2 < 16; j2++) {
                    int col = kt * 128 + half * 64 + c + 2 * j2;
                    float p0 = fast_exp2(__uint_as_float(s[2 * j2])     * SCALE_L2E);
                    float p1 = fast_exp2(__uint_as_float(s[2 * j2 + 1]) * SCALE_L2E);
                    p0 = (col     <= q_global) ? p0 : 0.0f;
                    p1 = (col + 1 <= q_global) ? p1 : 0.0f;
                    lsum += p0 + p1;
                    __nv_bfloat162 pr = __floats2bfloat162_rn(p0, p1);
                    pk[j2] = *(uint32_t*)&pr;
                }
                uint32_t pb = (uint32_t)(((r_local >> 3) + half * 16) * 1024 +
                                         (r_local & 7) * 128 + c * 2);
                uint4* pk4 = (uint4*)pk;
                #pragma unroll
                for (int i = 0; i < 4; i++)
                    *(uint4*)(tp + AP_OFF + sw128(pb + i * 16)) = pk4[i];
            }
        }
        #pragma unroll
        for (int j = 0; j < 4; j++) *(uint4*)(tp + AV_OFF + vsw[j]) = rv[j];
        if (kt < qt) {
            #pragma unroll
            for (int j = 0; j < 4; j++) *(uint4*)(tp + AK_OFF + swo[j]) = rk[j];
        }
        __syncthreads();

        if (wid == 0) {
            FENCE_PROXY_ASYNC_SHARED_CTA();
            if (elect_one()) {
                #pragma unroll
                for (int ch = 0; ch < 8; ch++) {
                    uint64_t offP = (uint64_t)((ch & 3) * 2 + (ch >> 2) * 1024);
                    uint64_t offV = (uint64_t)((ch & 3) * 2 + (ch >> 2) * 512);
                    mma_f16_ss(O_T, dP + offP, dV + offV, IDESC_PV, !(kt == 0 && ch == 0));
                }
                if (kt < qt) {
                    #pragma unroll
                    for (int ch = 0; ch < 4; ch++)
                        mma_f16_ss(S_T, dQ + ch * 2, dK + ch * 2, IDESC_QK, ch > 0);
                }
                TCGEN05_COMMIT(MBAR);
            }
        }
        if (kt < qt) {
            #pragma unroll
            for (int j = 0; j < 4; j++)
                rv[j] = *(const uint4*)(vTh + vgo[j] + (kt + 1) * 128);
        }
    }
    MBARRIER_WAIT_PARITY(MBAR, (qt + 1) & 1);
    TCGEN05_FENCE_AFTER();

    lsm[half * 128 + r_local] = lsum;
    __syncthreads();
    float l = lsm[r_local] + lsm[128 + r_local];
    float inv_l = 1.0f / l;
    {
        uint32_t o[32];
        TCGEN05_LD_X32(o, O_T + half * 32);
        TCGEN05_WAIT_LD();
        uint4 hv[4], lv[4];
        __nv_bfloat16* hb = (__nv_bfloat16*)hv;
        __nv_bfloat16* lb = (__nv_bfloat16*)lv;
        #pragma unroll
        for (int j = 0; j < 32; j++) {
            float val = __uint_as_float(o[j]) * inv_l;
            __nv_bfloat16 h16 = __float2bfloat16(val);
            hb[j] = h16;
            lb[j] = __float2bfloat16(val - __bfloat162float(h16));
        }
        size_t gbase = (size_t)b * SEQ * DMODEL + (size_t)h * HDIM +
                       (size_t)(qt * 128 + r_local) * DMODEL + half * 32;
        uint4* oph = (uint4*)(oh + gbase);
        uint4* opl = (uint4*)(ol + gbase);
        #pragma unroll
        for (int i = 0; i < 4; i++) { oph[i] = hv[i]; opl[i] = lv[i]; }
    }
    __syncthreads();
    if (wid == 0) TCGEN05_DEALLOC(tmem, 256);
#else
    // compile-only fallback
    int qt = gridDim.x - 1 - blockIdx.x, h = blockIdx.y, b = blockIdx.z;
    int tid = threadIdx.x;
    size_t rowbase = (size_t)b * SEQ * QSTRIDE + (size_t)h * HDIM;
    size_t obase   = (size_t)b * SEQ * DMODEL + (size_t)h * HDIM;
    const __nv_bfloat16* vTh = vT + ((size_t)(b * NHEADS + h) * HDIM) * SEQ;
    for (int r = tid; r < 128; r += blockDim.x) {
        int qg = qt * 128 + r;
        float o[HDIM]; float l = 0.0f;
        for (int d = 0; d < HDIM; d++) o[d] = 0.0f;
        for (int kk = 0; kk <= qg; kk++) {
            float s = 0.0f;
            for (int d = 0; d < HDIM; d++)
                s += __bfloat162float(qkv[rowbase + (size_t)qg * QSTRIDE + d]) *
                     __bfloat162float(qkv[rowbase + (size_t)kk * QSTRIDE + DMODEL + d]);
            float p = fast_exp2(s * 0.125f * 1.4426950408889634f);
            l += p;
            for (int d = 0; d < HDIM; d++)
                o[d] += p * __bfloat162float(vTh[(size_t)d * SEQ + kk]);
        }
        for (int d = 0; d < HDIM; d++) {
            float val = o[d] / l;
            __nv_bfloat16 h16 = __float2bfloat16(val);
            oh[obase + (size_t)qg * DMODEL + d] = h16;
            ol[obase + (size_t)qg * DMODEL + d] = __float2bfloat16(val - __bfloat162float(h16));
        }
    }
#endif
}

// ---------------- launcher ----------------
extern "C" void kernel_launch(void* const* d_in, const int* in_sizes, int n_in,
                              void* d_out, int out_size) {
    (void)in_sizes; (void)n_in; (void)out_size;
    const float* x     = (const float*)d_in[0];
    const float* wq    = (const float*)d_in[1];
    const float* bq    = (const float*)d_in[2];
    const float* wk    = (const float*)d_in[3];
    const float* bk    = (const float*)d_in[4];
    const float* wv    = (const float*)d_in[5];
    const float* bv    = (const float*)d_in[6];
    const float* wo    = (const float*)d_in[7];
    const float* bo    = (const float*)d_in[8];
    const float* w1    = (const float*)d_in[9];
    const float* b1    = (const float*)d_in[10];
    const float* w2    = (const float*)d_in[11];
    const float* b2    = (const float*)d_in[12];
    const float* ln1_g = (const float*)d_in[13];
    const float* ln1_b = (const float*)d_in[14];
    const float* ln2_g = (const float*)d_in[15];
    const float* ln2_b = (const float*)d_in[16];
    float* out = (float*)d_out;

    float *x1;
    cudaGetSymbolAddress((void**)&x1, g_x1);
    __nv_bfloat16 *qkv, *vT, *wqkvth, *wscr;
    cudaGetSymbolAddress((void**)&qkv, g_qkv);
    cudaGetSymbolAddress((void**)&vT, g_vT);
    cudaGetSymbolAddress((void**)&wqkvth, g_wqkvth);
    cudaGetSymbolAddress((void**)&wscr, g_wscr);
    __nv_bfloat16 *ln1h, *ln1l, *atth, *attl, *hh, *hl, *f1h, *f1l;
    cudaGetSymbolAddress((void**)&ln1h, g_ln1h); cudaGetSymbolAddress((void**)&ln1l, g_ln1l);
    cudaGetSymbolAddress((void**)&atth, g_atth); cudaGetSymbolAddress((void**)&attl, g_attl);
    cudaGetSymbolAddress((void**)&hh,   g_hh);   cudaGetSymbolAddress((void**)&hl,   g_hl);
    cudaGetSymbolAddress((void**)&f1h,  g_f1h);  cudaGetSymbolAddress((void**)&f1l,  g_f1l);
    __nv_bfloat16 *woth, *wotl, *w1th, *w1tl, *w2th, *w2tl;
    cudaGetSymbolAddress((void**)&woth, g_woth); cudaGetSymbolAddress((void**)&wotl, g_wotl);
    cudaGetSymbolAddress((void**)&w1th, g_w1th); cudaGetSymbolAddress((void**)&w1tl, g_w1tl);
    cudaGetSymbolAddress((void**)&w2th, g_w2th); cudaGetSymbolAddress((void**)&w2tl, g_w2tl);

    cudaFuncSetAttribute(tc_gemm1_kernel,
                         cudaFuncAttributeMaxDynamicSharedMemorySize, GEMM1_SMEM_BYTES);
    cudaFuncSetAttribute(tc_gemm256_kernel<true, false, 1>,
                         cudaFuncAttributeMaxDynamicSharedMemorySize, GEMM256_SMEM_BYTES);
    cudaFuncSetAttribute(tc_gemm256_kernel<false, true, 0>,
                         cudaFuncAttributeMaxDynamicSharedMemorySize, GEMM256_SMEM_BYTES);
    cudaFuncSetAttribute(tc_attn_kernel,
                         cudaFuncAttributeMaxDynamicSharedMemorySize, ATTN_SMEM_BYTES);

    dim3 grid_qkv(QSTRIDE / 256, MROWS / 128);    // (9, 32)
    dim3 grid_o(DMODEL / 256, MROWS / 128);       // (3, 32)
    dim3 grid_ff1(DFF / 256, MROWS / 128);        // (12, 32)
    dim3 grid_ff2(DMODEL / 256, MROWS / 128);     // (3, 32)
    dim3 agrid(SEQ / 128, NHEADS, BATCH);

    layernorm_split_kernel<<<MROWS, 256>>>(x, ln1_g, ln1_b, ln1h, ln1l);
    transpose4_split_kernel<<<dim3(DMODEL / 128, DMODEL / 32, 4), 256>>>(
        wq, wk, wv, wo,
        wqkvth,                       wscr,
        wqkvth + DMODEL * DMODEL,     wscr + DMODEL * DMODEL,
        wqkvth + 2 * DMODEL * DMODEL, wscr + 2 * DMODEL * DMODEL,
        woth, wotl);
    // fused QKV projection: 128x256 tiles (halved A traffic)
    tc_gemm1_kernel<<<grid_qkv, 256, GEMM1_SMEM_BYTES>>>(
        ln1h, wqkvth, bq, bk, bv, qkv, vT, MROWS, QSTRIDE, DMODEL);
    tc_attn_kernel<<<agrid, 256, ATTN_SMEM_BYTES>>>(qkv, vT, atth, attl);
    transpose2_split_kernel<<<dim3(24, 24, 2), 256>>>(w1, w2, w1th, w1tl, w2th, w2tl);
    // O-proj: 128x256 tile, residual(x) + fp32 out
    tc_gemm256_kernel<false, true, 0><<<grid_o, 256, GEMM256_SMEM_BYTES>>>(
        atth, attl, woth, wotl, bo, x, x1, nullptr, nullptr, MROWS, DMODEL, DMODEL);
    layernorm_split_kernel<<<MROWS, 256>>>(x1, ln2_g, ln2_b, hh, hl);
    // FFN1: 128x256 tile, ReLU + bf16 hi/lo out
    tc_gemm256_kernel<true, false, 1><<<grid_ff1, 256, GEMM256_SMEM_BYTES>>>(
        hh, hl, w1th, w1tl, b1, nullptr, nullptr, f1h, f1l, MROWS, DFF, DMODEL);
    // FFN2: 128x256 tile, residual(x1) + fp32 out
    tc_gemm256_kernel<false, true, 0><<<grid_ff2, 256, GEMM256_SMEM_BYTES>>>(
        f1h, f1l, w2th, w2tl, b2, x1, out, nullptr, nullptr, MROWS, DMODEL, DFF);
}